// round 5
// baseline (speedup 1.0000x reference)
#include <cuda_runtime.h>
#include <math.h>

// Problem constants (fixed by the reference)
#define B_  2
#define T_  2048
#define C_  1024
#define NH_ 16
#define NKV_ 4
#define HD_ 64
#define VEC_ 32
#define M_  (B_ * T_)   // 4096 token rows

// ---------------------------------------------------------------------------
// Scratch (static device globals; no runtime allocation allowed)
// ---------------------------------------------------------------------------
__device__ float g_qraw[M_ * NH_ * HD_];    // [B*T, NH*HD]  raw q projection
__device__ float g_kraw[M_ * NKV_ * HD_];   // [B*T, NKV*HD]
__device__ float g_vraw[M_ * NKV_ * HD_];
__device__ float g_qn[M_ * NH_ * HD_];      // [B, NH, T, HD]  rope+rmsnorm'd
__device__ float g_kn[M_ * NKV_ * HD_];     // [B, NKV, T, HD]
__device__ float g_vn[M_ * NKV_ * HD_];     // [B, NKV, T, HD]
__device__ float g_y [M_ * NH_ * HD_];      // [B, T, NH, HD]  attn output

// ---------------------------------------------------------------------------
// Classic fp32 SGEMM: C[M,N] = A[M,K] @ B[K,N], row-major.
// 128x128 block tile, K-step 8, 256 threads, 8x8 micro-tile (4+4 split).
// Requires M%128==0, N%128==0, K%8==0 (holds for all our shapes).
// ---------------------------------------------------------------------------
__global__ __launch_bounds__(256) void sgemm128(
    const float* __restrict__ A, const float* __restrict__ Bm,
    float* __restrict__ Cm, int M, int N, int K) {
    __shared__ float As[8][128];
    __shared__ float Bs[8][128];
    const int tid = threadIdx.x;
    const int bm  = blockIdx.y * 128;
    const int bn  = blockIdx.x * 128;
    const int aRow = tid >> 1;            // 0..127
    const int aCol = (tid & 1) * 4;       // 0 or 4
    const int bRow = tid >> 5;            // 0..7
    const int bCol = (tid & 31) * 4;      // 0..124
    const int ri = (tid >> 4) * 4;        // 0..60 (and +64)
    const int ci = (tid & 15) * 4;        // 0..60 (and +64)

    float acc[8][8];
#pragma unroll
    for (int i = 0; i < 8; i++)
#pragma unroll
        for (int j = 0; j < 8; j++) acc[i][j] = 0.f;

    for (int k0 = 0; k0 < K; k0 += 8) {
        float4 av = *(const float4*)(A  + (size_t)(bm + aRow) * K + k0 + aCol);
        float4 bv = *(const float4*)(Bm + (size_t)(k0 + bRow) * N + bn + bCol);
        As[aCol + 0][aRow] = av.x;
        As[aCol + 1][aRow] = av.y;
        As[aCol + 2][aRow] = av.z;
        As[aCol + 3][aRow] = av.w;
        *(float4*)(&Bs[bRow][bCol]) = bv;
        __syncthreads();
#pragma unroll
        for (int kk = 0; kk < 8; kk++) {
            float4 a0 = *(const float4*)&As[kk][ri];
            float4 a1 = *(const float4*)&As[kk][ri + 64];
            float4 b0 = *(const float4*)&Bs[kk][ci];
            float4 b1 = *(const float4*)&Bs[kk][ci + 64];
            float ar[8] = {a0.x, a0.y, a0.z, a0.w, a1.x, a1.y, a1.z, a1.w};
            float br[8] = {b0.x, b0.y, b0.z, b0.w, b1.x, b1.y, b1.z, b1.w};
#pragma unroll
            for (int i = 0; i < 8; i++)
#pragma unroll
                for (int j = 0; j < 8; j++) acc[i][j] += ar[i] * br[j];
        }
        __syncthreads();
    }

#pragma unroll
    for (int ib = 0; ib < 2; ib++)
#pragma unroll
        for (int i = 0; i < 4; i++) {
            int row = bm + ib * 64 + ri + i;
#pragma unroll
            for (int jb = 0; jb < 2; jb++) {
                float4 v = make_float4(acc[ib * 4 + i][jb * 4 + 0],
                                       acc[ib * 4 + i][jb * 4 + 1],
                                       acc[ib * 4 + i][jb * 4 + 2],
                                       acc[ib * 4 + i][jb * 4 + 3]);
                *(float4*)(Cm + (size_t)row * N + bn + jb * 64 + ci) = v;
            }
        }
}

// ---------------------------------------------------------------------------
// Per-token post-process: gate, v += gate*ve, RoPE + RMSNorm on q/k,
// transpose into attention-friendly [B, H, T, HD] layouts.
// grid = B*T blocks, 256 threads.
// ---------------------------------------------------------------------------
__global__ __launch_bounds__(256) void postproc(
    const float* __restrict__ x, const float* __restrict__ ve,
    const float* __restrict__ cosb, const float* __restrict__ sinb,
    const float* __restrict__ Wgate) {
    const int bt = blockIdx.x;            // 0..4095
    const int b = bt / T_, t = bt % T_;
    const int tid = threadIdx.x;
    const int lane = tid & 31, w = tid >> 5;
    __shared__ float s_gate[NKV_];

    // gate[h] = 2*sigmoid( x[b,t,:32] @ Wgate[:,h] ), one warp per kv head
    if (w < NKV_) {
        float p = x[(size_t)bt * C_ + lane] * Wgate[lane * NKV_ + w];
#pragma unroll
        for (int o = 16; o; o >>= 1) p += __shfl_xor_sync(0xffffffffu, p, o);
        if (lane == 0) s_gate[w] = 2.0f / (1.0f + expf(-p));
    }
    __syncthreads();

    // RoPE + RMSNorm: 20 head rows (16 q + 4 k), one warp per row, strided.
    const float c = cosb[t * (HD_ / 2) + lane];
    const float s = sinb[t * (HD_ / 2) + lane];
    for (int row = w; row < NH_ + NKV_; row += 8) {
        const float* src;
        float* dst;
        if (row < NH_) {
            src = g_qraw + (size_t)bt * (NH_ * HD_) + row * HD_;
            dst = g_qn + ((size_t)(b * NH_ + row) * T_ + t) * HD_;
        } else {
            int kh = row - NH_;
            src = g_kraw + (size_t)bt * (NKV_ * HD_) + kh * HD_;
            dst = g_kn + ((size_t)(b * NKV_ + kh) * T_ + t) * HD_;
        }
        float x1 = src[lane], x2 = src[lane + 32];
        float o1 = x1 * c + x2 * s;
        float o2 = -x1 * s + x2 * c;
        float sq = o1 * o1 + o2 * o2;
#pragma unroll
        for (int o = 16; o; o >>= 1) sq += __shfl_xor_sync(0xffffffffu, sq, o);
        float scale = rsqrtf(sq * (1.0f / HD_) + 1.1920929e-7f);
        dst[lane] = o1 * scale;
        dst[lane + 32] = o2 * scale;
    }

    // v = vraw + gate[h] * ve  (256 values = NKV*HD, one per thread)
    {
        int h = tid >> 6, d = tid & 63;
        float val = g_vraw[(size_t)bt * (NKV_ * HD_) + tid] +
                    s_gate[h] * ve[(size_t)bt * (NKV_ * HD_) + tid];
        g_vn[((size_t)(b * NKV_ + h) * T_ + t) * HD_ + d] = val;
    }
}

// ---------------------------------------------------------------------------
// Sliding-window flash attention.
// grid = (T/128, NH, B), 256 threads.
// Each thread: 2 query rows x 16 head dims (4 threads/row -> shfl combine).
// ---------------------------------------------------------------------------
__global__ __launch_bounds__(256) void attn_kernel(const int* __restrict__ winp) {
    const int qt = blockIdx.x;            // query tile (128 queries)
    const int h  = blockIdx.y;
    const int b  = blockIdx.z;
    const int kvh = h >> 2;               // g = NH/NKV = 4
    int win = winp[0];
    if (win <= 0 || win > T_) win = 1024; // robustness vs dtype surprises

    const int q0 = qt * 128;
    const int tid = threadIdx.x;
    const int part = tid & 3;             // which 16-dim slice
    const int slot = tid >> 2;            // 0..63 -> 2 query rows
    const int dp = part * 16;
    const int r0 = q0 + slot * 2;

    __shared__ float Ks[64][64];
    __shared__ float Vs[64][64];

    const float* qptr = g_qn + ((size_t)(b * NH_ + h) * T_) * HD_;
    const float* kptr = g_kn + ((size_t)(b * NKV_ + kvh) * T_) * HD_;
    const float* vptr = g_vn + ((size_t)(b * NKV_ + kvh) * T_) * HD_;

    float qreg[2][16];
#pragma unroll
    for (int rr = 0; rr < 2; rr++)
#pragma unroll
        for (int i = 0; i < 16; i += 4)
            *(float4*)&qreg[rr][i] =
                *(const float4*)&qptr[(size_t)(r0 + rr) * HD_ + dp + i];

    float m[2] = {-1e30f, -1e30f};
    float l[2] = {0.f, 0.f};
    float o[2][16];
#pragma unroll
    for (int rr = 0; rr < 2; rr++)
#pragma unroll
        for (int i = 0; i < 16; i++) o[rr][i] = 0.f;

    int jt0 = q0 - win;
    if (jt0 < 0) jt0 = 0;
    jt0 >>= 6;
    const int jt1 = (q0 + 127) >> 6;

    for (int jt = jt0; jt <= jt1; jt++) {
        const int j0 = jt * 64;
        __syncthreads();
#pragma unroll
        for (int it = 0; it < 4; it++) {
            int f = tid + it * 256;          // float4 index 0..1023
            int j = f >> 4;
            int d4 = (f & 15) * 4;
            *(float4*)&Ks[j][d4] = *(const float4*)&kptr[(size_t)(j0 + j) * HD_ + d4];
            *(float4*)&Vs[j][d4] = *(const float4*)&vptr[(size_t)(j0 + j) * HD_ + d4];
        }
        __syncthreads();

#pragma unroll
        for (int jc = 0; jc < 4; jc++) {
            float sc[2][16];
#pragma unroll
            for (int jj = 0; jj < 16; jj++) {
                const int j = jc * 16 + jj;
                float p0 = 0.f, p1 = 0.f;
#pragma unroll
                for (int i = 0; i < 16; i++) {
                    float kv = Ks[j][dp + i];
                    p0 += qreg[0][i] * kv;
                    p1 += qreg[1][i] * kv;
                }
                // combine partial dots across the 4 'part' lanes
                p0 += __shfl_xor_sync(0xffffffffu, p0, 1);
                p0 += __shfl_xor_sync(0xffffffffu, p0, 2);
                p1 += __shfl_xor_sync(0xffffffffu, p1, 1);
                p1 += __shfl_xor_sync(0xffffffffu, p1, 2);
                const int jg = j0 + j;
                bool ok0 = (jg <= r0) && (jg >= r0 - win);
                bool ok1 = (jg <= r0 + 1) && (jg >= r0 + 1 - win);
                sc[0][jj] = ok0 ? p0 * 0.125f : -INFINITY;
                sc[1][jj] = ok1 ? p1 * 0.125f : -INFINITY;
            }
#pragma unroll
            for (int rr = 0; rr < 2; rr++) {
                float mx = m[rr];
#pragma unroll
                for (int jj = 0; jj < 16; jj++) mx = fmaxf(mx, sc[rr][jj]);
                float corr = __expf(m[rr] - mx);
                m[rr] = mx;
                float ls = 0.f;
#pragma unroll
                for (int jj = 0; jj < 16; jj++) {
                    float p = __expf(sc[rr][jj] - mx);
                    sc[rr][jj] = p;
                    ls += p;
                }
                l[rr] = l[rr] * corr + ls;
#pragma unroll
                for (int i = 0; i < 16; i++) o[rr][i] *= corr;
#pragma unroll
                for (int jj = 0; jj < 16; jj++) {
                    float p = sc[rr][jj];
#pragma unroll
                    for (int i = 0; i < 16; i++)
                        o[rr][i] += p * Vs[jc * 16 + jj][dp + i];
                }
            }
        }
    }

#pragma unroll
    for (int rr = 0; rr < 2; rr++) {
        float inv = 1.0f / l[rr];
        float* dst = g_y + ((size_t)(b * T_ + r0 + rr) * NH_ + h) * HD_ + dp;
#pragma unroll
        for (int i = 0; i < 16; i += 4) {
            float4 v = make_float4(o[rr][i] * inv, o[rr][i + 1] * inv,
                                   o[rr][i + 2] * inv, o[rr][i + 3] * inv);
            *(float4*)(dst + i) = v;
        }
    }
}

// ---------------------------------------------------------------------------
// Launch: 3 proj GEMMs -> postproc -> attention -> output GEMM
// ---------------------------------------------------------------------------
extern "C" void kernel_launch(void* const* d_in, const int* in_sizes, int n_in,
                              void* d_out, int out_size) {
    const float* x     = (const float*)d_in[0];
    const float* ve    = (const float*)d_in[1];
    const float* cosb  = (const float*)d_in[2];
    const float* sinb  = (const float*)d_in[3];
    const float* Wq    = (const float*)d_in[4];
    const float* Wk    = (const float*)d_in[5];
    const float* Wv    = (const float*)d_in[6];
    const float* Wproj = (const float*)d_in[7];
    const float* Wgate = (const float*)d_in[8];
    const int*   win   = (const int*)d_in[9];
    float* out = (float*)d_out;

    float *qraw, *kraw, *vraw, *yb;
    cudaGetSymbolAddress((void**)&qraw, g_qraw);
    cudaGetSymbolAddress((void**)&kraw, g_kraw);
    cudaGetSymbolAddress((void**)&vraw, g_vraw);
    cudaGetSymbolAddress((void**)&yb, g_y);

    dim3 blk(256);
    sgemm128<<<dim3((NH_ * HD_) / 128, M_ / 128), blk>>>(x, Wq, qraw, M_, NH_ * HD_, C_);
    sgemm128<<<dim3((NKV_ * HD_) / 128, M_ / 128), blk>>>(x, Wk, kraw, M_, NKV_ * HD_, C_);
    sgemm128<<<dim3((NKV_ * HD_) / 128, M_ / 128), blk>>>(x, Wv, vraw, M_, NKV_ * HD_, C_);
    postproc<<<M_, 256>>>(x, ve, cosb, sinb, Wgate);
    attn_kernel<<<dim3(T_ / 128, NH_, B_), 256>>>(win);
    sgemm128<<<dim3(C_ / 128, M_ / 128), blk>>>(yb, Wproj, out, M_, C_, C_);
}

// round 7
// speedup vs baseline: 1.4695x; 1.4695x over previous
#include <cuda_runtime.h>
#include <cuda_bf16.h>
#include <math.h>
#include <stdint.h>

// Problem constants (fixed by the reference)
#define B_  2
#define T_  2048
#define C_  1024
#define NH_ 16
#define NKV_ 4
#define HD_ 64
#define VEC_ 32
#define M_  (B_ * T_)      // 4096 token rows
#define NQKV_ 1536         // fused q(1024) | k(256) | v(256) columns

// tcgen05 is an arch-conditional feature: only present in the sm_103a/sm_100a
// device passes. The harness also builds a baseline compute_103 target, which
// must compile — it gets a SIMT fallback body instead.
#if defined(__CUDA_ARCH_FEAT_SM103_ALL) || defined(__CUDA_ARCH_FEAT_SM100_ALL) || \
    defined(__CUDA_ARCH_FEAT_SM101_ALL)
#define TC_OK 1
#else
#define TC_OK 0
#endif

// ---------------------------------------------------------------------------
// Scratch (static device globals; no runtime allocation allowed)
// ---------------------------------------------------------------------------
__device__ __align__(16) __nv_bfloat16 g_xs_hi[M_ * C_];
__device__ __align__(16) __nv_bfloat16 g_xs_lo[M_ * C_];
__device__ __align__(16) __nv_bfloat16 g_wqkv_hi[NQKV_ * C_];  // [N,K] transposed
__device__ __align__(16) __nv_bfloat16 g_wqkv_lo[NQKV_ * C_];
__device__ __align__(16) __nv_bfloat16 g_wproj_hi[C_ * C_];    // [N,K] transposed
__device__ __align__(16) __nv_bfloat16 g_wproj_lo[C_ * C_];
__device__ __align__(16) __nv_bfloat16 g_ys_hi[M_ * C_];
__device__ __align__(16) __nv_bfloat16 g_ys_lo[M_ * C_];
__device__ float g_qkv[M_ * NQKV_];        // fused projection output
__device__ float g_qn[M_ * NH_ * HD_];     // [B, NH, T, HD]  rope+rmsnorm'd
__device__ float g_kn[M_ * NKV_ * HD_];    // [B, NKV, T, HD]
__device__ float g_vn[M_ * NKV_ * HD_];    // [B, NKV, T, HD]
__device__ float g_y [M_ * NH_ * HD_];     // [B, T, NH, HD]  attn output

// ---------------------------------------------------------------------------
// PTX helpers (arch-conditional ones used only inside TC_OK-guarded code)
// ---------------------------------------------------------------------------
__device__ __forceinline__ uint32_t smem_u32(const void* p) {
    uint32_t a;
    asm("{ .reg .u64 t; cvta.to.shared.u64 t, %1; cvt.u32.u64 %0, t; }"
        : "=r"(a) : "l"(p));
    return a;
}
__device__ __forceinline__ uint32_t elect_one() {
    uint32_t pred;
    asm volatile("{\n\t.reg .pred p;\n\telect.sync _|p, 0xFFFFFFFF;\n\t"
                 "selp.b32 %0, 1, 0, p;\n\t}" : "=r"(pred));
    return pred;
}
#define TC_ALLOC(sm, n)   asm volatile("tcgen05.alloc.cta_group::1.sync.aligned.shared::cta.b32 [%0], %1;" :: "r"(sm), "r"((uint32_t)(n)) : "memory")
#define TC_DEALLOC(t, n)  asm volatile("tcgen05.dealloc.cta_group::1.sync.aligned.b32 %0, %1;" :: "r"(t), "r"((uint32_t)(n)))
#define TC_COMMIT(mbar)   asm volatile("tcgen05.commit.cta_group::1.mbarrier::arrive::one.shared::cluster.b64 [%0];" :: "r"(mbar) : "memory")
#define TC_FENCE_AFTER()  asm volatile("tcgen05.fence::after_thread_sync;" ::: "memory")
#define TC_WAIT_LD()      asm volatile("tcgen05.wait::ld.sync.aligned;" ::: "memory")
#define MBAR_INIT(sm, n)  asm volatile("mbarrier.init.shared.b64 [%0], %1;" :: "r"(sm), "r"((uint32_t)(n)) : "memory")
#define FENCE_ASYNC()     asm volatile("fence.proxy.async.shared::cta;" ::: "memory")

__device__ __forceinline__ void mbar_wait(uint32_t mbar, uint32_t parity) {
    asm volatile(
        "{\n\t.reg .pred P;\n\t"
        "W%=:\n\t"
        "mbarrier.try_wait.parity.acquire.cta.shared::cta.b64 P, [%0], %1, 0x989680;\n\t"
        "@P bra D%=;\n\t"
        "bra W%=;\n\t"
        "D%=:\n\t}"
        :: "r"(mbar), "r"(parity) : "memory");
}

#if TC_OK
// SS-mode bf16 MMA, cta_group::1, fp32 accum
__device__ __forceinline__ void mma_f16_ss(uint32_t d, uint64_t a, uint64_t b,
                                           uint32_t idesc, uint32_t en) {
    asm volatile(
        "{\n\t.reg .pred p;\n\t"
        "setp.ne.u32 p, %4, 0;\n\t"
        "tcgen05.mma.cta_group::1.kind::f16 [%0], %1, %2, %3, {%5, %5, %5, %5}, p;\n\t"
        "}"
        :: "r"(d), "l"(a), "l"(b), "r"(idesc), "r"(en), "r"(0u)
        : "memory");
}

#define LDTM_X32(r, addr) \
    asm volatile( \
        "tcgen05.ld.sync.aligned.32x32b.x32.b32 " \
        "{%0, %1, %2, %3, %4, %5, %6, %7, " \
        " %8, %9, %10, %11, %12, %13, %14, %15, " \
        " %16, %17, %18, %19, %20, %21, %22, %23, " \
        " %24, %25, %26, %27, %28, %29, %30, %31}, [%32];" \
        : "=r"((r)[0]),  "=r"((r)[1]),  "=r"((r)[2]),  "=r"((r)[3]), \
          "=r"((r)[4]),  "=r"((r)[5]),  "=r"((r)[6]),  "=r"((r)[7]), \
          "=r"((r)[8]),  "=r"((r)[9]),  "=r"((r)[10]), "=r"((r)[11]), \
          "=r"((r)[12]), "=r"((r)[13]), "=r"((r)[14]), "=r"((r)[15]), \
          "=r"((r)[16]), "=r"((r)[17]), "=r"((r)[18]), "=r"((r)[19]), \
          "=r"((r)[20]), "=r"((r)[21]), "=r"((r)[22]), "=r"((r)[23]), \
          "=r"((r)[24]), "=r"((r)[25]), "=r"((r)[26]), "=r"((r)[27]), \
          "=r"((r)[28]), "=r"((r)[29]), "=r"((r)[30]), "=r"((r)[31]) \
        : "r"(addr))
#endif  // TC_OK

// 64-bit SMEM descriptor: SW128, version=1 (Blackwell), LBO=1, SBO=64
static __device__ __forceinline__ uint64_t smem_desc_sw128(uint32_t addr) {
    const uint64_t base =
        (uint64_t(2)  << 61) | (uint64_t(1) << 46) |
        (uint64_t(64) << 32) | (uint64_t(1) << 16);
    return base | ((uint64_t)(addr >> 4) & 0x3FFF);
}
#define SW128(off) ((off) ^ (((off) >> 3) & 0x70))

// idesc: dtype=F32, atype=BF16, btype=BF16, N=128, M=128 (K-major both)
#define GEMM_IDESC ((1u << 4) | (1u << 7) | (1u << 10) | ((128u / 8) << 17) | ((128u / 16) << 24))

// ---------------------------------------------------------------------------
// Prep kernels: fp32 -> (hi, lo) bf16 split; transposed weight split.
// ---------------------------------------------------------------------------
__global__ __launch_bounds__(256) void split_fp32(
    const float* __restrict__ src, __nv_bfloat16* __restrict__ hi,
    __nv_bfloat16* __restrict__ lo, int n) {
    int i = blockIdx.x * 256 + threadIdx.x;
    if (i < n) {
        float v = src[i];
        __nv_bfloat16 h = __float2bfloat16(v);
        hi[i] = h;
        lo[i] = __float2bfloat16(v - __bfloat162float(h));
    }
}

// W: [K, Ncols] row-major -> out hi/lo: [Ncols, K] row-major. Block (32,8).
__global__ __launch_bounds__(256) void transpose_split(
    const float* __restrict__ W, __nv_bfloat16* __restrict__ hi,
    __nv_bfloat16* __restrict__ lo, int K, int Ncols) {
    __shared__ float t[32][33];
    const int kb = blockIdx.y * 32, nb = blockIdx.x * 32;
    const int tx = threadIdx.x, ty = threadIdx.y;
#pragma unroll
    for (int j = 0; j < 32; j += 8)
        t[ty + j][tx] = W[(size_t)(kb + ty + j) * Ncols + nb + tx];
    __syncthreads();
#pragma unroll
    for (int j = 0; j < 32; j += 8) {
        float v = t[tx][ty + j];
        __nv_bfloat16 h = __float2bfloat16(v);
        size_t o = (size_t)(nb + ty + j) * K + kb + tx;
        hi[o] = h;
        lo[o] = __float2bfloat16(v - __bfloat162float(h));
    }
}

// ---------------------------------------------------------------------------
// Split-bf16 GEMM: C[M,N] = A[M,K] . Bt[N,K]^T  (fp32-accurate)
// tcgen05 path: 128x128 tile, K-chunk 64, 3 combos (hi.hi, hi.lo, lo.hi),
// double-buffered smem with mbarrier-paced MMA overlap.
// Fallback (non-'a' baseline target): SIMT hi+lo reconstruct, same interface.
// grid = (N/128, M/128), 256 threads, dynamic smem.
// ---------------------------------------------------------------------------
#define KCHUNK   64
#define NCHUNKS  (C_ / KCHUNK)           // 16
#define BUFSZ    16384                   // 128 rows x 128 bytes
#define STAGESZ  (4 * BUFSZ)             // Ahi | Alo | Bhi | Blo
#define GEMM_SMEM (2048 + 2 * STAGESZ)   // hdr + align slack + 2 stages

__global__ __launch_bounds__(256) void gemm_split(
    const __nv_bfloat16* __restrict__ Ahi, const __nv_bfloat16* __restrict__ Alo,
    const __nv_bfloat16* __restrict__ Bhi, const __nv_bfloat16* __restrict__ Blo,
    float* __restrict__ C, int N) {
#if TC_OK
    extern __shared__ char smem[];
    const uint32_t sb = smem_u32(smem);
    const uint32_t ab = (sb + 1024 + 1023) & 0xFFFFFC00u;  // 1024-aligned stages
    char* smab = smem + (ab - sb);
    const int tid = threadIdx.x;
    const int wid = tid >> 5;
    const int lane = tid & 31;
    const int bm = blockIdx.y * 128;
    const int bn = blockIdx.x * 128;
    const int K = C_;

    if (wid == 0) TC_ALLOC(sb, 128);
    if (tid == 0) { MBAR_INIT(sb + 8, 1); MBAR_INIT(sb + 16, 1); }
    __syncthreads();
    uint32_t tmem;
    asm volatile("ld.shared.b32 %0, [%1];" : "=r"(tmem) : "r"(sb));

    // ---- chunk loader: 4 buffers x 1024 uint4, 16 vec16 per thread ----
#define LOAD_CHUNK(kc, s)                                                     \
    do {                                                                      \
        const int k0 = (kc) * KCHUNK;                                         \
        char* st = smab + (s) * STAGESZ;                                      \
        _Pragma("unroll")                                                     \
        for (int v = 0; v < 4; v++) {                                         \
            int idx = tid + v * 256;                                          \
            int r = idx >> 3, c8 = idx & 7;                                   \
            uint32_t off = SW128((uint32_t)(r * 128 + c8 * 16));              \
            size_t ga = (size_t)(bm + r) * K + k0 + c8 * 8;                   \
            size_t gb = (size_t)(bn + r) * K + k0 + c8 * 8;                   \
            *(uint4*)(st + off)              = *(const uint4*)(Ahi + ga);     \
            *(uint4*)(st + BUFSZ + off)      = *(const uint4*)(Alo + ga);     \
            *(uint4*)(st + 2 * BUFSZ + off)  = *(const uint4*)(Bhi + gb);     \
            *(uint4*)(st + 3 * BUFSZ + off)  = *(const uint4*)(Blo + gb);     \
        }                                                                     \
    } while (0)

    LOAD_CHUNK(0, 0);
    int p0 = 0, p1 = 0;

    for (int i = 0; i < NCHUNKS; i++) {
        const int s = i & 1;
        __syncthreads();                 // buf s fully written + prior waits done
        if (wid == 0) {
            FENCE_ASYNC();
            if (elect_one()) {
                uint32_t base = ab + s * STAGESZ;
                uint64_t dah = smem_desc_sw128(base);
                uint64_t dal = smem_desc_sw128(base + BUFSZ);
                uint64_t dbh = smem_desc_sw128(base + 2 * BUFSZ);
                uint64_t dbl = smem_desc_sw128(base + 3 * BUFSZ);
#pragma unroll
                for (int kk = 0; kk < 4; kk++)
                    mma_f16_ss(tmem, dah + kk * 2, dbh + kk * 2, GEMM_IDESC,
                               (i > 0) || (kk > 0));
#pragma unroll
                for (int kk = 0; kk < 4; kk++)
                    mma_f16_ss(tmem, dah + kk * 2, dbl + kk * 2, GEMM_IDESC, 1);
#pragma unroll
                for (int kk = 0; kk < 4; kk++)
                    mma_f16_ss(tmem, dal + kk * 2, dbh + kk * 2, GEMM_IDESC, 1);
                TC_COMMIT(sb + 8 + s * 8);
            }
        }
        if (i + 1 < NCHUNKS) {
            const int s2 = (i + 1) & 1;
            if (i >= 1) {                // MMAs of chunk i-1 (reading buf s2) done?
                if (s2 == 0) { mbar_wait(sb + 8,  p0 & 1); p0++; }
                else         { mbar_wait(sb + 16, p1 & 1); p1++; }
            }
            LOAD_CHUNK(i + 1, s2);
        }
    }
    // drain: last commit covers all prior MMAs (in-order completion tracking)
    {
        const int sl = (NCHUNKS - 1) & 1;
        if (sl == 0) mbar_wait(sb + 8, p0 & 1);
        else         mbar_wait(sb + 16, p1 & 1);
    }
    TC_FENCE_AFTER();

    // ---- epilogue: 8 warps; warp w reads rows (w&3)*32+lane, cols (w>>2)*64 ----
    {
        const int sp = wid & 3;
        const int colbase = (wid >> 2) * 64;
        const uint32_t wo = (uint32_t)sp << 21;
        uint32_t d0[32], d1[32];
        LDTM_X32(d0, tmem + wo + colbase);
        LDTM_X32(d1, tmem + wo + colbase + 32);
        TC_WAIT_LD();
        const int row = bm + sp * 32 + lane;
        float* dst = C + (size_t)row * N + bn + colbase;
#pragma unroll
        for (int c = 0; c < 32; c += 4) {
            *(float4*)(dst + c) = make_float4(
                __uint_as_float(d0[c]), __uint_as_float(d0[c + 1]),
                __uint_as_float(d0[c + 2]), __uint_as_float(d0[c + 3]));
            *(float4*)(dst + 32 + c) = make_float4(
                __uint_as_float(d1[c]), __uint_as_float(d1[c + 1]),
                __uint_as_float(d1[c + 2]), __uint_as_float(d1[c + 3]));
        }
    }
    __syncthreads();
    if (wid == 0) TC_DEALLOC(tmem, 128);
#undef LOAD_CHUNK

#else  // ------------- SIMT fallback (baseline compute_103 target) ----------
    __shared__ float As[8][128];
    __shared__ float Bs[8][128];
    const int tid = threadIdx.x;
    const int bm = blockIdx.y * 128;
    const int bn = blockIdx.x * 128;
    const int K = C_;
    const int ldRow = tid >> 1;           // 0..127
    const int ldK   = (tid & 1) * 4;      // 0 or 4
    const int ri = (tid >> 4) * 4;
    const int ci = (tid & 15) * 4;

    float acc[8][8];
#pragma unroll
    for (int i = 0; i < 8; i++)
#pragma unroll
        for (int j = 0; j < 8; j++) acc[i][j] = 0.f;

    for (int k0 = 0; k0 < K; k0 += 8) {
#pragma unroll
        for (int c = 0; c < 4; c++) {
            size_t ga = (size_t)(bm + ldRow) * K + k0 + ldK + c;
            size_t gb = (size_t)(bn + ldRow) * K + k0 + ldK + c;
            As[ldK + c][ldRow] = __bfloat162float(Ahi[ga]) + __bfloat162float(Alo[ga]);
            Bs[ldK + c][ldRow] = __bfloat162float(Bhi[gb]) + __bfloat162float(Blo[gb]);
        }
        __syncthreads();
#pragma unroll
        for (int kk = 0; kk < 8; kk++) {
            float ar[8], br[8];
#pragma unroll
            for (int i = 0; i < 4; i++) {
                ar[i] = As[kk][ri + i];
                ar[i + 4] = As[kk][ri + 64 + i];
                br[i] = Bs[kk][ci + i];
                br[i + 4] = Bs[kk][ci + 64 + i];
            }
#pragma unroll
            for (int i = 0; i < 8; i++)
#pragma unroll
                for (int j = 0; j < 8; j++) acc[i][j] += ar[i] * br[j];
        }
        __syncthreads();
    }
#pragma unroll
    for (int ib = 0; ib < 2; ib++)
#pragma unroll
        for (int i = 0; i < 4; i++) {
            int row = bm + ib * 64 + ri + i;
#pragma unroll
            for (int jb = 0; jb < 2; jb++)
#pragma unroll
                for (int j = 0; j < 4; j++)
                    C[(size_t)row * N + bn + jb * 64 + ci + j] =
                        acc[ib * 4 + i][jb * 4 + j];
        }
#endif
}

// ---------------------------------------------------------------------------
// Per-token post-process: gate, v += gate*ve, RoPE + RMSNorm on q/k,
// transpose into attention-friendly [B, H, T, HD] layouts.
// Reads the fused QKV projection buffer g_qkv [M, 1536].
// ---------------------------------------------------------------------------
__global__ __launch_bounds__(256) void postproc(
    const float* __restrict__ x, const float* __restrict__ ve,
    const float* __restrict__ cosb, const float* __restrict__ sinb,
    const float* __restrict__ Wgate) {
    const int bt = blockIdx.x;
    const int b = bt / T_, t = bt % T_;
    const int tid = threadIdx.x;
    const int lane = tid & 31, w = tid >> 5;
    __shared__ float s_gate[NKV_];

    if (w < NKV_) {
        float p = x[(size_t)bt * C_ + lane] * Wgate[lane * NKV_ + w];
#pragma unroll
        for (int o = 16; o; o >>= 1) p += __shfl_xor_sync(0xffffffffu, p, o);
        if (lane == 0) s_gate[w] = 2.0f / (1.0f + expf(-p));
    }
    __syncthreads();

    const float c = cosb[t * (HD_ / 2) + lane];
    const float s = sinb[t * (HD_ / 2) + lane];
    const float* qkvrow = g_qkv + (size_t)bt * NQKV_;
    for (int row = w; row < NH_ + NKV_; row += 8) {
        const float* src;
        float* dst;
        if (row < NH_) {
            src = qkvrow + row * HD_;
            dst = g_qn + ((size_t)(b * NH_ + row) * T_ + t) * HD_;
        } else {
            int kh = row - NH_;
            src = qkvrow + 1024 + kh * HD_;
            dst = g_kn + ((size_t)(b * NKV_ + kh) * T_ + t) * HD_;
        }
        float x1 = src[lane], x2 = src[lane + 32];
        float o1 = x1 * c + x2 * s;
        float o2 = -x1 * s + x2 * c;
        float sq = o1 * o1 + o2 * o2;
#pragma unroll
        for (int o = 16; o; o >>= 1) sq += __shfl_xor_sync(0xffffffffu, sq, o);
        float scale = rsqrtf(sq * (1.0f / HD_) + 1.1920929e-7f);
        dst[lane] = o1 * scale;
        dst[lane + 32] = o2 * scale;
    }

    {
        int h = tid >> 6, d = tid & 63;
        float val = qkvrow[1280 + tid] +
                    s_gate[h] * ve[(size_t)bt * (NKV_ * HD_) + tid];
        g_vn[((size_t)(b * NKV_ + h) * T_ + t) * HD_ + d] = val;
    }
}

// ---------------------------------------------------------------------------
// Sliding-window flash attention (SIMT fp32, unchanged this round).
// ---------------------------------------------------------------------------
__global__ __launch_bounds__(256) void attn_kernel(const int* __restrict__ winp) {
    const int qt = blockIdx.x;
    const int h  = blockIdx.y;
    const int b  = blockIdx.z;
    const int kvh = h >> 2;
    int win = winp[0];
    if (win <= 0 || win > T_) win = 1024;

    const int q0 = qt * 128;
    const int tid = threadIdx.x;
    const int part = tid & 3;
    const int slot = tid >> 2;
    const int dp = part * 16;
    const int r0 = q0 + slot * 2;

    __shared__ float Ks[64][64];
    __shared__ float Vs[64][64];

    const float* qptr = g_qn + ((size_t)(b * NH_ + h) * T_) * HD_;
    const float* kptr = g_kn + ((size_t)(b * NKV_ + kvh) * T_) * HD_;
    const float* vptr = g_vn + ((size_t)(b * NKV_ + kvh) * T_) * HD_;

    float qreg[2][16];
#pragma unroll
    for (int rr = 0; rr < 2; rr++)
#pragma unroll
        for (int i = 0; i < 16; i += 4)
            *(float4*)&qreg[rr][i] =
                *(const float4*)&qptr[(size_t)(r0 + rr) * HD_ + dp + i];

    float m[2] = {-1e30f, -1e30f};
    float l[2] = {0.f, 0.f};
    float o[2][16];
#pragma unroll
    for (int rr = 0; rr < 2; rr++)
#pragma unroll
        for (int i = 0; i < 16; i++) o[rr][i] = 0.f;

    int jt0 = q0 - win;
    if (jt0 < 0) jt0 = 0;
    jt0 >>= 6;
    const int jt1 = (q0 + 127) >> 6;

    for (int jt = jt0; jt <= jt1; jt++) {
        const int j0 = jt * 64;
        __syncthreads();
#pragma unroll
        for (int it = 0; it < 4; it++) {
            int f = tid + it * 256;
            int j = f >> 4;
            int d4 = (f & 15) * 4;
            *(float4*)&Ks[j][d4] = *(const float4*)&kptr[(size_t)(j0 + j) * HD_ + d4];
            *(float4*)&Vs[j][d4] = *(const float4*)&vptr[(size_t)(j0 + j) * HD_ + d4];
        }
        __syncthreads();

#pragma unroll
        for (int jc = 0; jc < 4; jc++) {
            float sc[2][16];
#pragma unroll
            for (int jj = 0; jj < 16; jj++) {
                const int j = jc * 16 + jj;
                float p0 = 0.f, p1 = 0.f;
#pragma unroll
                for (int i = 0; i < 16; i++) {
                    float kv = Ks[j][dp + i];
                    p0 += qreg[0][i] * kv;
                    p1 += qreg[1][i] * kv;
                }
                p0 += __shfl_xor_sync(0xffffffffu, p0, 1);
                p0 += __shfl_xor_sync(0xffffffffu, p0, 2);
                p1 += __shfl_xor_sync(0xffffffffu, p1, 1);
                p1 += __shfl_xor_sync(0xffffffffu, p1, 2);
                const int jg = j0 + j;
                bool ok0 = (jg <= r0) && (jg >= r0 - win);
                bool ok1 = (jg <= r0 + 1) && (jg >= r0 + 1 - win);
                sc[0][jj] = ok0 ? p0 * 0.125f : -INFINITY;
                sc[1][jj] = ok1 ? p1 * 0.125f : -INFINITY;
            }
#pragma unroll
            for (int rr = 0; rr < 2; rr++) {
                float mx = m[rr];
#pragma unroll
                for (int jj = 0; jj < 16; jj++) mx = fmaxf(mx, sc[rr][jj]);
                float corr = __expf(m[rr] - mx);
                m[rr] = mx;
                float ls = 0.f;
#pragma unroll
                for (int jj = 0; jj < 16; jj++) {
                    float p = __expf(sc[rr][jj] - mx);
                    sc[rr][jj] = p;
                    ls += p;
                }
                l[rr] = l[rr] * corr + ls;
#pragma unroll
                for (int i = 0; i < 16; i++) o[rr][i] *= corr;
#pragma unroll
                for (int jj = 0; jj < 16; jj++) {
                    float p = sc[rr][jj];
#pragma unroll
                    for (int i = 0; i < 16; i++)
                        o[rr][i] += p * Vs[jc * 16 + jj][dp + i];
                }
            }
        }
    }

#pragma unroll
    for (int rr = 0; rr < 2; rr++) {
        float inv = 1.0f / l[rr];
        float* dst = g_y + ((size_t)(b * T_ + r0 + rr) * NH_ + h) * HD_ + dp;
#pragma unroll
        for (int i = 0; i < 16; i += 4) {
            float4 v = make_float4(o[rr][i] * inv, o[rr][i + 1] * inv,
                                   o[rr][i + 2] * inv, o[rr][i + 3] * inv);
            *(float4*)(dst + i) = v;
        }
    }
}

// ---------------------------------------------------------------------------
// Launch: split x -> transpose/split weights -> QKV GEMM -> postproc ->
//         attention -> split y -> output GEMM
// ---------------------------------------------------------------------------
extern "C" void kernel_launch(void* const* d_in, const int* in_sizes, int n_in,
                              void* d_out, int out_size) {
    const float* x     = (const float*)d_in[0];
    const float* ve    = (const float*)d_in[1];
    const float* cosb  = (const float*)d_in[2];
    const float* sinb  = (const float*)d_in[3];
    const float* Wq    = (const float*)d_in[4];
    const float* Wk    = (const float*)d_in[5];
    const float* Wv    = (const float*)d_in[6];
    const float* Wproj = (const float*)d_in[7];
    const float* Wgate = (const float*)d_in[8];
    const int*   win   = (const int*)d_in[9];
    float* out = (float*)d_out;

    __nv_bfloat16 *xs_hi, *xs_lo, *wqkv_hi, *wqkv_lo, *wproj_hi, *wproj_lo,
                  *ys_hi, *ys_lo;
    float *qkv, *yb;
    cudaGetSymbolAddress((void**)&xs_hi, g_xs_hi);
    cudaGetSymbolAddress((void**)&xs_lo, g_xs_lo);
    cudaGetSymbolAddress((void**)&wqkv_hi, g_wqkv_hi);
    cudaGetSymbolAddress((void**)&wqkv_lo, g_wqkv_lo);
    cudaGetSymbolAddress((void**)&wproj_hi, g_wproj_hi);
    cudaGetSymbolAddress((void**)&wproj_lo, g_wproj_lo);
    cudaGetSymbolAddress((void**)&ys_hi, g_ys_hi);
    cudaGetSymbolAddress((void**)&ys_lo, g_ys_lo);
    cudaGetSymbolAddress((void**)&qkv, g_qkv);
    cudaGetSymbolAddress((void**)&yb, g_y);

    cudaFuncSetAttribute(gemm_split,
                         cudaFuncAttributeMaxDynamicSharedMemorySize, GEMM_SMEM);

    // 1. split x into hi/lo bf16
    split_fp32<<<(M_ * C_ + 255) / 256, 256>>>(x, xs_hi, xs_lo, M_ * C_);
    // 2. transpose + split weights into [N,K] bf16
    dim3 tb(32, 8);
    transpose_split<<<dim3(1024 / 32, C_ / 32), tb>>>(Wq, wqkv_hi, wqkv_lo, C_, 1024);
    transpose_split<<<dim3(256 / 32, C_ / 32), tb>>>(Wk, wqkv_hi + (size_t)1024 * C_,
                                                     wqkv_lo + (size_t)1024 * C_, C_, 256);
    transpose_split<<<dim3(256 / 32, C_ / 32), tb>>>(Wv, wqkv_hi + (size_t)1280 * C_,
                                                     wqkv_lo + (size_t)1280 * C_, C_, 256);
    transpose_split<<<dim3(C_ / 32, C_ / 32), tb>>>(Wproj, wproj_hi, wproj_lo, C_, C_);
    // 3. fused QKV projection on tensor cores
    gemm_split<<<dim3(NQKV_ / 128, M_ / 128), 256, GEMM_SMEM>>>(
        xs_hi, xs_lo, wqkv_hi, wqkv_lo, qkv, NQKV_);
    // 4. gate + RoPE + RMSNorm + layout
    postproc<<<M_, 256>>>(x, ve, cosb, sinb, Wgate);
    // 5. sliding-window attention
    attn_kernel<<<dim3(T_ / 128, NH_, B_), 256>>>(win);
    // 6. split attention output, 7. output projection on tensor cores
    split_fp32<<<(M_ * C_ + 255) / 256, 256>>>(yb, ys_hi, ys_lo, M_ * C_);
    gemm_split<<<dim3(C_ / 128, M_ / 128), 256, GEMM_SMEM>>>(
        ys_hi, ys_lo, wproj_hi, wproj_lo, out, C_);
}

// round 8
// speedup vs baseline: 4.7221x; 3.2134x over previous
#include <cuda_runtime.h>
#include <cuda_bf16.h>
#include <math.h>
#include <stdint.h>

// Problem constants (fixed by the reference)
#define B_  2
#define T_  2048
#define C_  1024
#define NH_ 16
#define NKV_ 4
#define HD_ 64
#define VEC_ 32
#define M_  (B_ * T_)      // 4096 token rows
#define NQKV_ 1536         // fused q(1024) | k(256) | v(256) columns

// tcgen05 is arch-conditional: only in the sm_103a/sm_100a passes. The
// baseline compute_103 target gets SIMT fallback bodies.
#if defined(__CUDA_ARCH_FEAT_SM103_ALL) || defined(__CUDA_ARCH_FEAT_SM100_ALL) || \
    defined(__CUDA_ARCH_FEAT_SM101_ALL)
#define TC_OK 1
#else
#define TC_OK 0
#endif

// ---------------------------------------------------------------------------
// Scratch (static device globals; no runtime allocation allowed)
// ---------------------------------------------------------------------------
__device__ __align__(16) __nv_bfloat16 g_xs_hi[M_ * C_];
__device__ __align__(16) __nv_bfloat16 g_xs_lo[M_ * C_];
__device__ __align__(16) __nv_bfloat16 g_wqkv_hi[NQKV_ * C_];  // [N,K] transposed
__device__ __align__(16) __nv_bfloat16 g_wqkv_lo[NQKV_ * C_];
__device__ __align__(16) __nv_bfloat16 g_wproj_hi[C_ * C_];    // [N,K] transposed
__device__ __align__(16) __nv_bfloat16 g_wproj_lo[C_ * C_];
__device__ __align__(16) __nv_bfloat16 g_ys_hi[M_ * C_];
__device__ __align__(16) __nv_bfloat16 g_ys_lo[M_ * C_];
__device__ float g_qkv[M_ * NQKV_];        // fused projection output
// attention operands, bf16 hi/lo split
__device__ __align__(16) __nv_bfloat16 g_qs_hi[M_ * NH_ * HD_];   // [B,NH,T,HD]
__device__ __align__(16) __nv_bfloat16 g_qs_lo[M_ * NH_ * HD_];
__device__ __align__(16) __nv_bfloat16 g_ks_hi[M_ * NKV_ * HD_];  // [B,NKV,T,HD]
__device__ __align__(16) __nv_bfloat16 g_ks_lo[M_ * NKV_ * HD_];
__device__ __align__(16) __nv_bfloat16 g_vts_hi[M_ * NKV_ * HD_]; // [B,NKV,HD,T]
__device__ __align__(16) __nv_bfloat16 g_vts_lo[M_ * NKV_ * HD_];

// ---------------------------------------------------------------------------
// PTX helpers
// ---------------------------------------------------------------------------
__device__ __forceinline__ uint32_t smem_u32(const void* p) {
    uint32_t a;
    asm("{ .reg .u64 t; cvta.to.shared.u64 t, %1; cvt.u32.u64 %0, t; }"
        : "=r"(a) : "l"(p));
    return a;
}
__device__ __forceinline__ uint32_t elect_one() {
    uint32_t pred;
    asm volatile("{\n\t.reg .pred p;\n\telect.sync _|p, 0xFFFFFFFF;\n\t"
                 "selp.b32 %0, 1, 0, p;\n\t}" : "=r"(pred));
    return pred;
}
#define TC_ALLOC(sm, n)   asm volatile("tcgen05.alloc.cta_group::1.sync.aligned.shared::cta.b32 [%0], %1;" :: "r"(sm), "r"((uint32_t)(n)) : "memory")
#define TC_DEALLOC(t, n)  asm volatile("tcgen05.dealloc.cta_group::1.sync.aligned.b32 %0, %1;" :: "r"(t), "r"((uint32_t)(n)))
#define TC_COMMIT(mbar)   asm volatile("tcgen05.commit.cta_group::1.mbarrier::arrive::one.shared::cluster.b64 [%0];" :: "r"(mbar) : "memory")
#define TC_FENCE_AFTER()  asm volatile("tcgen05.fence::after_thread_sync;" ::: "memory")
#define TC_WAIT_LD()      asm volatile("tcgen05.wait::ld.sync.aligned;" ::: "memory")
#define MBAR_INIT(sm, n)  asm volatile("mbarrier.init.shared.b64 [%0], %1;" :: "r"(sm), "r"((uint32_t)(n)) : "memory")
#define FENCE_ASYNC()     asm volatile("fence.proxy.async.shared::cta;" ::: "memory")

__device__ __forceinline__ void mbar_wait(uint32_t mbar, uint32_t parity) {
    asm volatile(
        "{\n\t.reg .pred P;\n\t"
        "W%=:\n\t"
        "mbarrier.try_wait.parity.acquire.cta.shared::cta.b64 P, [%0], %1, 0x989680;\n\t"
        "@P bra D%=;\n\t"
        "bra W%=;\n\t"
        "D%=:\n\t}"
        :: "r"(mbar), "r"(parity) : "memory");
}

#if TC_OK
// SS-mode bf16 MMA, cta_group::1, fp32 accum
__device__ __forceinline__ void mma_f16_ss(uint32_t d, uint64_t a, uint64_t b,
                                           uint32_t idesc, uint32_t en) {
    asm volatile(
        "{\n\t.reg .pred p;\n\t"
        "setp.ne.u32 p, %4, 0;\n\t"
        "tcgen05.mma.cta_group::1.kind::f16 [%0], %1, %2, %3, {%5, %5, %5, %5}, p;\n\t"
        "}"
        :: "r"(d), "l"(a), "l"(b), "r"(idesc), "r"(en), "r"(0u)
        : "memory");
}

#define LDTM_X32(r, addr) \
    asm volatile( \
        "tcgen05.ld.sync.aligned.32x32b.x32.b32 " \
        "{%0, %1, %2, %3, %4, %5, %6, %7, " \
        " %8, %9, %10, %11, %12, %13, %14, %15, " \
        " %16, %17, %18, %19, %20, %21, %22, %23, " \
        " %24, %25, %26, %27, %28, %29, %30, %31}, [%32];" \
        : "=r"((r)[0]),  "=r"((r)[1]),  "=r"((r)[2]),  "=r"((r)[3]), \
          "=r"((r)[4]),  "=r"((r)[5]),  "=r"((r)[6]),  "=r"((r)[7]), \
          "=r"((r)[8]),  "=r"((r)[9]),  "=r"((r)[10]), "=r"((r)[11]), \
          "=r"((r)[12]), "=r"((r)[13]), "=r"((r)[14]), "=r"((r)[15]), \
          "=r"((r)[16]), "=r"((r)[17]), "=r"((r)[18]), "=r"((r)[19]), \
          "=r"((r)[20]), "=r"((r)[21]), "=r"((r)[22]), "=r"((r)[23]), \
          "=r"((r)[24]), "=r"((r)[25]), "=r"((r)[26]), "=r"((r)[27]), \
          "=r"((r)[28]), "=r"((r)[29]), "=r"((r)[30]), "=r"((r)[31]) \
        : "r"(addr))
#endif  // TC_OK

// 64-bit SMEM descriptor: SW128, version=1 (Blackwell), LBO=1, SBO=64
static __device__ __forceinline__ uint64_t smem_desc_sw128(uint32_t addr) {
    const uint64_t base =
        (uint64_t(2)  << 61) | (uint64_t(1) << 46) |
        (uint64_t(64) << 32) | (uint64_t(1) << 16);
    return base | ((uint64_t)(addr >> 4) & 0x3FFF);
}
#define SW128(off) ((off) ^ (((off) >> 3) & 0x70))

// idesc: dtype=F32, atype=BF16, btype=BF16 (K-major both)
#define GEMM_IDESC ((1u << 4) | (1u << 7) | (1u << 10) | ((128u / 8) << 17) | ((128u / 16) << 24))
#define ATT_IDESC  ((1u << 4) | (1u << 7) | (1u << 10) | ((64u / 8) << 17) | ((128u / 16) << 24))

// ---------------------------------------------------------------------------
// Prep kernels
// ---------------------------------------------------------------------------
__global__ __launch_bounds__(256) void split_fp32(
    const float* __restrict__ src, __nv_bfloat16* __restrict__ hi,
    __nv_bfloat16* __restrict__ lo, int n) {
    int i = blockIdx.x * 256 + threadIdx.x;
    if (i < n) {
        float v = src[i];
        __nv_bfloat16 h = __float2bfloat16(v);
        hi[i] = h;
        lo[i] = __float2bfloat16(v - __bfloat162float(h));
    }
}

// W: [K, Ncols] row-major -> out hi/lo: [Ncols, K] row-major. Block (32,8).
__global__ __launch_bounds__(256) void transpose_split(
    const float* __restrict__ W, __nv_bfloat16* __restrict__ hi,
    __nv_bfloat16* __restrict__ lo, int K, int Ncols) {
    __shared__ float t[32][33];
    const int kb = blockIdx.y * 32, nb = blockIdx.x * 32;
    const int tx = threadIdx.x, ty = threadIdx.y;
#pragma unroll
    for (int j = 0; j < 32; j += 8)
        t[ty + j][tx] = W[(size_t)(kb + ty + j) * Ncols + nb + tx];
    __syncthreads();
#pragma unroll
    for (int j = 0; j < 32; j += 8) {
        float v = t[tx][ty + j];
        __nv_bfloat16 h = __float2bfloat16(v);
        size_t o = (size_t)(nb + ty + j) * K + kb + tx;
        hi[o] = h;
        lo[o] = __float2bfloat16(v - __bfloat162float(h));
    }
}

// ---------------------------------------------------------------------------
// Split-bf16 GEMM (unchanged from round 7; works): C[M,N] = A[M,K] . Bt[N,K]^T
// ---------------------------------------------------------------------------
#define KCHUNK   64
#define NCHUNKS  (C_ / KCHUNK)           // 16
#define BUFSZ    16384                   // 128 rows x 128 bytes
#define STAGESZ  (4 * BUFSZ)             // Ahi | Alo | Bhi | Blo
#define GEMM_SMEM (2048 + 2 * STAGESZ)

__global__ __launch_bounds__(256) void gemm_split(
    const __nv_bfloat16* __restrict__ Ahi, const __nv_bfloat16* __restrict__ Alo,
    const __nv_bfloat16* __restrict__ Bhi, const __nv_bfloat16* __restrict__ Blo,
    float* __restrict__ C, int N) {
#if TC_OK
    extern __shared__ char smem[];
    const uint32_t sb = smem_u32(smem);
    const uint32_t ab = (sb + 1024 + 1023) & 0xFFFFFC00u;
    char* smab = smem + (ab - sb);
    const int tid = threadIdx.x;
    const int wid = tid >> 5;
    const int lane = tid & 31;
    const int bm = blockIdx.y * 128;
    const int bn = blockIdx.x * 128;
    const int K = C_;

    if (wid == 0) TC_ALLOC(sb, 128);
    if (tid == 0) { MBAR_INIT(sb + 8, 1); MBAR_INIT(sb + 16, 1); }
    __syncthreads();
    uint32_t tmem;
    asm volatile("ld.shared.b32 %0, [%1];" : "=r"(tmem) : "r"(sb));

#define LOAD_CHUNK(kc, s)                                                     \
    do {                                                                      \
        const int k0 = (kc) * KCHUNK;                                         \
        char* st = smab + (s) * STAGESZ;                                      \
        _Pragma("unroll")                                                     \
        for (int v = 0; v < 4; v++) {                                         \
            int idx = tid + v * 256;                                          \
            int r = idx >> 3, c8 = idx & 7;                                   \
            uint32_t off = SW128((uint32_t)(r * 128 + c8 * 16));              \
            size_t ga = (size_t)(bm + r) * K + k0 + c8 * 8;                   \
            size_t gb = (size_t)(bn + r) * K + k0 + c8 * 8;                   \
            *(uint4*)(st + off)              = *(const uint4*)(Ahi + ga);     \
            *(uint4*)(st + BUFSZ + off)      = *(const uint4*)(Alo + ga);     \
            *(uint4*)(st + 2 * BUFSZ + off)  = *(const uint4*)(Bhi + gb);     \
            *(uint4*)(st + 3 * BUFSZ + off)  = *(const uint4*)(Blo + gb);     \
        }                                                                     \
    } while (0)

    LOAD_CHUNK(0, 0);
    int p0 = 0, p1 = 0;

    for (int i = 0; i < NCHUNKS; i++) {
        const int s = i & 1;
        __syncthreads();
        if (wid == 0) {
            FENCE_ASYNC();
            if (elect_one()) {
                uint32_t base = ab + s * STAGESZ;
                uint64_t dah = smem_desc_sw128(base);
                uint64_t dal = smem_desc_sw128(base + BUFSZ);
                uint64_t dbh = smem_desc_sw128(base + 2 * BUFSZ);
                uint64_t dbl = smem_desc_sw128(base + 3 * BUFSZ);
#pragma unroll
                for (int kk = 0; kk < 4; kk++)
                    mma_f16_ss(tmem, dah + kk * 2, dbh + kk * 2, GEMM_IDESC,
                               (i > 0) || (kk > 0));
#pragma unroll
                for (int kk = 0; kk < 4; kk++)
                    mma_f16_ss(tmem, dah + kk * 2, dbl + kk * 2, GEMM_IDESC, 1);
#pragma unroll
                for (int kk = 0; kk < 4; kk++)
                    mma_f16_ss(tmem, dal + kk * 2, dbh + kk * 2, GEMM_IDESC, 1);
                TC_COMMIT(sb + 8 + s * 8);
            }
        }
        if (i + 1 < NCHUNKS) {
            const int s2 = (i + 1) & 1;
            if (i >= 1) {
                if (s2 == 0) { mbar_wait(sb + 8,  p0 & 1); p0++; }
                else         { mbar_wait(sb + 16, p1 & 1); p1++; }
            }
            LOAD_CHUNK(i + 1, s2);
        }
    }
    {
        const int sl = (NCHUNKS - 1) & 1;
        if (sl == 0) mbar_wait(sb + 8, p0 & 1);
        else         mbar_wait(sb + 16, p1 & 1);
    }
    TC_FENCE_AFTER();

    {
        const int sp = wid & 3;
        const int colbase = (wid >> 2) * 64;
        const uint32_t wo = (uint32_t)sp << 21;
        uint32_t d0[32], d1[32];
        LDTM_X32(d0, tmem + wo + colbase);
        LDTM_X32(d1, tmem + wo + colbase + 32);
        TC_WAIT_LD();
        const int row = bm + sp * 32 + lane;
        float* dst = C + (size_t)row * N + bn + colbase;
#pragma unroll
        for (int c = 0; c < 32; c += 4) {
            *(float4*)(dst + c) = make_float4(
                __uint_as_float(d0[c]), __uint_as_float(d0[c + 1]),
                __uint_as_float(d0[c + 2]), __uint_as_float(d0[c + 3]));
            *(float4*)(dst + 32 + c) = make_float4(
                __uint_as_float(d1[c]), __uint_as_float(d1[c + 1]),
                __uint_as_float(d1[c + 2]), __uint_as_float(d1[c + 3]));
        }
    }
    __syncthreads();
    if (wid == 0) TC_DEALLOC(tmem, 128);
#undef LOAD_CHUNK

#else  // SIMT fallback
    __shared__ float As[8][128];
    __shared__ float Bs[8][128];
    const int tid = threadIdx.x;
    const int bm = blockIdx.y * 128;
    const int bn = blockIdx.x * 128;
    const int K = C_;
    const int ldRow = tid >> 1;
    const int ldK   = (tid & 1) * 4;
    const int ri = (tid >> 4) * 4;
    const int ci = (tid & 15) * 4;

    float acc[8][8];
#pragma unroll
    for (int i = 0; i < 8; i++)
#pragma unroll
        for (int j = 0; j < 8; j++) acc[i][j] = 0.f;

    for (int k0 = 0; k0 < K; k0 += 8) {
#pragma unroll
        for (int c = 0; c < 4; c++) {
            size_t ga = (size_t)(bm + ldRow) * K + k0 + ldK + c;
            size_t gb = (size_t)(bn + ldRow) * K + k0 + ldK + c;
            As[ldK + c][ldRow] = __bfloat162float(Ahi[ga]) + __bfloat162float(Alo[ga]);
            Bs[ldK + c][ldRow] = __bfloat162float(Bhi[gb]) + __bfloat162float(Blo[gb]);
        }
        __syncthreads();
#pragma unroll
        for (int kk = 0; kk < 8; kk++) {
            float ar[8], br[8];
#pragma unroll
            for (int i = 0; i < 4; i++) {
                ar[i] = As[kk][ri + i];
                ar[i + 4] = As[kk][ri + 64 + i];
                br[i] = Bs[kk][ci + i];
                br[i + 4] = Bs[kk][ci + 64 + i];
            }
#pragma unroll
            for (int i = 0; i < 8; i++)
#pragma unroll
                for (int j = 0; j < 8; j++) acc[i][j] += ar[i] * br[j];
        }
        __syncthreads();
    }
#pragma unroll
    for (int ib = 0; ib < 2; ib++)
#pragma unroll
        for (int i = 0; i < 4; i++) {
            int row = bm + ib * 64 + ri + i;
#pragma unroll
            for (int jb = 0; jb < 2; jb++)
#pragma unroll
                for (int j = 0; j < 4; j++)
                    C[(size_t)row * N + bn + jb * 64 + ci + j] =
                        acc[ib * 4 + i][jb * 4 + j];
        }
#endif
}

// ---------------------------------------------------------------------------
// Per-token post-process: gate, v += gate*ve, RoPE + RMSNorm on q/k.
// Outputs bf16 hi/lo: Q [B,NH,T,HD], K [B,NKV,T,HD], V^T [B,NKV,HD,T].
// ---------------------------------------------------------------------------
__global__ __launch_bounds__(256) void postproc(
    const float* __restrict__ x, const float* __restrict__ ve,
    const float* __restrict__ cosb, const float* __restrict__ sinb,
    const float* __restrict__ Wgate) {
    const int bt = blockIdx.x;
    const int b = bt / T_, t = bt % T_;
    const int tid = threadIdx.x;
    const int lane = tid & 31, w = tid >> 5;
    __shared__ float s_gate[NKV_];

    if (w < NKV_) {
        float p = x[(size_t)bt * C_ + lane] * Wgate[lane * NKV_ + w];
#pragma unroll
        for (int o = 16; o; o >>= 1) p += __shfl_xor_sync(0xffffffffu, p, o);
        if (lane == 0) s_gate[w] = 2.0f / (1.0f + expf(-p));
    }
    __syncthreads();

    const float c = cosb[t * (HD_ / 2) + lane];
    const float s = sinb[t * (HD_ / 2) + lane];
    const float* qkvrow = g_qkv + (size_t)bt * NQKV_;
    for (int row = w; row < NH_ + NKV_; row += 8) {
        const float* src;
        __nv_bfloat16 *dhi, *dlo;
        if (row < NH_) {
            src = qkvrow + row * HD_;
            size_t base = ((size_t)(b * NH_ + row) * T_ + t) * HD_;
            dhi = g_qs_hi + base;
            dlo = g_qs_lo + base;
        } else {
            int kh = row - NH_;
            src = qkvrow + 1024 + kh * HD_;
            size_t base = ((size_t)(b * NKV_ + kh) * T_ + t) * HD_;
            dhi = g_ks_hi + base;
            dlo = g_ks_lo + base;
        }
        float x1 = src[lane], x2 = src[lane + 32];
        float o1 = x1 * c + x2 * s;
        float o2 = -x1 * s + x2 * c;
        float sq = o1 * o1 + o2 * o2;
#pragma unroll
        for (int o = 16; o; o >>= 1) sq += __shfl_xor_sync(0xffffffffu, sq, o);
        float scale = rsqrtf(sq * (1.0f / HD_) + 1.1920929e-7f);
        float v1 = o1 * scale, v2 = o2 * scale;
        __nv_bfloat16 h1 = __float2bfloat16(v1);
        __nv_bfloat16 h2 = __float2bfloat16(v2);
        dhi[lane] = h1;
        dhi[lane + 32] = h2;
        dlo[lane] = __float2bfloat16(v1 - __bfloat162float(h1));
        dlo[lane + 32] = __float2bfloat16(v2 - __bfloat162float(h2));
    }

    {
        int h = tid >> 6, d = tid & 63;
        float val = qkvrow[1280 + tid] +
                    s_gate[h] * ve[(size_t)bt * (NKV_ * HD_) + tid];
        size_t o = ((size_t)(b * NKV_ + h) * HD_ + d) * T_ + t;  // transposed
        __nv_bfloat16 hh = __float2bfloat16(val);
        g_vts_hi[o] = hh;
        g_vts_lo[o] = __float2bfloat16(val - __bfloat162float(hh));
    }
}

// ---------------------------------------------------------------------------
// tcgen05 sliding-window flash attention.
// grid = (T/128, NH, B), 256 threads, 2 CTAs/SM.
// Per 64-key tile: S = Q.K^T (3 split MMAs, TMEM cols 0-63), SIMT online
// softmax (8 warps: subpartition x key-half), P split hi/lo -> SMEM,
// P.V^T (3 split MMAs, TMEM cols 64-127), O accumulated in registers.
// ---------------------------------------------------------------------------
// smem offsets relative to 1024-aligned base ab:
#define AOFF_RED 0        // redmax[256] f32 (1KB) + redsum[256] f32 (1KB)
#define AOFF_Q   2048     // Qhi 16K | Qlo 16K
#define AOFF_K   34816    // Khi 8K | Klo 8K
#define AOFF_V   51200    // Vhi 8K | Vlo 8K
#define AOFF_P   67584    // Phi 16K | Plo 16K  (end 100352)
#define ATT_SMEM 102400   // 1024 hdr + 1024 align slack + 100352

__global__ __launch_bounds__(256, 2) void attn_tc(const int* __restrict__ winp) {
#if TC_OK
    extern __shared__ char smem[];
    const uint32_t sb = smem_u32(smem);
    const uint32_t ab = (sb + 1024 + 1023) & 0xFFFFFC00u;
    char* abp = smem + (ab - sb);

    int win = winp[0];
    if (win <= 0 || win > T_) win = 1024;
    const int qt = blockIdx.x, h = blockIdx.y, b = blockIdx.z;
    const int kvh = h >> 2;
    const int q0 = qt * 128;
    const int tid = threadIdx.x, w = tid >> 5, lane = tid & 31;
    const int sp = w & 3;              // TMEM subpartition
    const int hf = w >> 2;             // key/dim half (0 or 1)
    const int kbase = hf * 32;
    const int r = sp * 32 + lane;      // q row within tile
    const int qg = q0 + r;             // global q index

    float* redmax = (float*)(abp + AOFF_RED);
    float* redsum = (float*)(abp + AOFF_RED + 1024);

    if (w == 0) TC_ALLOC(sb, 128);
    if (tid == 0) { MBAR_INIT(sb + 8, 1); MBAR_INIT(sb + 16, 1); }
    __syncthreads();
    uint32_t tmem;
    asm volatile("ld.shared.b32 %0, [%1];" : "=r"(tmem) : "r"(sb));

    // Load Q tile [128 x 64] hi/lo into SW128 smem (1024 uint4 per buffer)
    const __nv_bfloat16* qh = g_qs_hi + ((size_t)(b * NH_ + h) * T_ + q0) * HD_;
    const __nv_bfloat16* qlo = g_qs_lo + ((size_t)(b * NH_ + h) * T_ + q0) * HD_;
#pragma unroll
    for (int v = 0; v < 4; v++) {
        int idx = tid + v * 256;
        int rr = idx >> 3, c8 = idx & 7;
        uint32_t off = SW128((uint32_t)(rr * 128 + c8 * 16));
        *(uint4*)(abp + AOFF_Q + off)          = *(const uint4*)(qh  + rr * 64 + c8 * 8);
        *(uint4*)(abp + AOFF_Q + 16384 + off)  = *(const uint4*)(qlo + rr * 64 + c8 * 8);
    }

    const __nv_bfloat16* kh  = g_ks_hi  + ((size_t)(b * NKV_ + kvh) * T_) * HD_;
    const __nv_bfloat16* kl  = g_ks_lo  + ((size_t)(b * NKV_ + kvh) * T_) * HD_;
    const __nv_bfloat16* vth = g_vts_hi + ((size_t)(b * NKV_ + kvh) * HD_) * T_;
    const __nv_bfloat16* vtl = g_vts_lo + ((size_t)(b * NKV_ + kvh) * HD_) * T_;

    float m = -1e30f, l = 0.f;
    float O[32];
#pragma unroll
    for (int i = 0; i < 32; i++) O[i] = 0.f;
    int ps = 0, ppv = 0;

    int j0s = q0 - win;
    if (j0s < 0) j0s = 0;
    const int jt0 = j0s >> 6;
    const int jt1 = (q0 + 127) >> 6;

    for (int jt = jt0; jt <= jt1; jt++) {
        const int j0 = jt * 64;
        __syncthreads();   // prior tile's MMAs done (PV waited) -> K/V reuse safe
        // Load K tile [64 keys x 64 d] and V^T tile [64 d x 64 keys], hi/lo
#pragma unroll
        for (int v = 0; v < 2; v++) {
            int idx = tid + v * 256;
            int rr = idx >> 3, c8 = idx & 7;
            uint32_t off = SW128((uint32_t)(rr * 128 + c8 * 16));
            *(uint4*)(abp + AOFF_K + off)         = *(const uint4*)(kh  + (size_t)(j0 + rr) * 64 + c8 * 8);
            *(uint4*)(abp + AOFF_K + 8192 + off)  = *(const uint4*)(kl  + (size_t)(j0 + rr) * 64 + c8 * 8);
            *(uint4*)(abp + AOFF_V + off)         = *(const uint4*)(vth + (size_t)rr * T_ + j0 + c8 * 8);
            *(uint4*)(abp + AOFF_V + 8192 + off)  = *(const uint4*)(vtl + (size_t)rr * T_ + j0 + c8 * 8);
        }
        __syncthreads();
        // S = Q.K^T (3 split combos x 4 K-steps) -> TMEM cols 0-63
        if (w == 0) {
            FENCE_ASYNC();
            if (elect_one()) {
                uint64_t dQh = smem_desc_sw128(ab + AOFF_Q);
                uint64_t dQl = smem_desc_sw128(ab + AOFF_Q + 16384);
                uint64_t dKh = smem_desc_sw128(ab + AOFF_K);
                uint64_t dKl = smem_desc_sw128(ab + AOFF_K + 8192);
#pragma unroll
                for (int kk = 0; kk < 4; kk++)
                    mma_f16_ss(tmem, dQh + kk * 2, dKh + kk * 2, ATT_IDESC, kk > 0);
#pragma unroll
                for (int kk = 0; kk < 4; kk++)
                    mma_f16_ss(tmem, dQh + kk * 2, dKl + kk * 2, ATT_IDESC, 1);
#pragma unroll
                for (int kk = 0; kk < 4; kk++)
                    mma_f16_ss(tmem, dQl + kk * 2, dKh + kk * 2, ATT_IDESC, 1);
                TC_COMMIT(sb + 8);
            }
        }
        mbar_wait(sb + 8, ps & 1); ps++;
        TC_FENCE_AFTER();

        // ---- softmax: this warp handles keys [kbase, kbase+32) of row r ----
        uint32_t sr[32];
        LDTM_X32(sr, tmem + ((uint32_t)sp << 21) + kbase);
        TC_WAIT_LD();
        float sc[32];
        uint32_t okm = 0;
        float tmax = -1e30f;
#pragma unroll
        for (int i = 0; i < 32; i++) {
            int jg = j0 + kbase + i;
            bool ok = (jg <= qg) && (jg >= qg - win);
            if (ok) okm |= (1u << i);
            sc[i] = ok ? __uint_as_float(sr[i]) * 0.125f : -1e30f;
            tmax = fmaxf(tmax, sc[i]);
        }
        redmax[r * 2 + hf] = tmax;
        __syncthreads();
        float mtile = fmaxf(redmax[r * 2], redmax[r * 2 + 1]);
        float mnew = fmaxf(m, mtile);
        float corr = __expf(m - mnew);
        float p[32];
        float psum = 0.f;
#pragma unroll
        for (int i = 0; i < 32; i++) {
            float e = ((okm >> i) & 1u) ? __expf(sc[i] - mnew) : 0.f;
            p[i] = e;
            psum += e;
        }
        redsum[r * 2 + hf] = psum;
        m = mnew;
        l = l * corr;
#pragma unroll
        for (int i = 0; i < 32; i++) O[i] *= corr;
        // write P hi/lo to smem (row r, keys kbase..kbase+31)
#pragma unroll
        for (int i = 0; i < 16; i++) {
            float pa = p[2 * i], pb = p[2 * i + 1];
            __nv_bfloat162 hh = __floats2bfloat162_rn(pa, pb);
            float la = pa - __bfloat162float(hh.x);
            float lb = pb - __bfloat162float(hh.y);
            __nv_bfloat162 ll = __floats2bfloat162_rn(la, lb);
            uint32_t boff = SW128((uint32_t)(r * 128 + (kbase + 2 * i) * 2));
            *(uint32_t*)(abp + AOFF_P + boff)          = *(uint32_t*)&hh;
            *(uint32_t*)(abp + AOFF_P + 16384 + boff)  = *(uint32_t*)&ll;
        }
        __syncthreads();
        l += redsum[r * 2] + redsum[r * 2 + 1];
        // PV = P.V^T (3 split combos) -> TMEM cols 64-127 (fresh each tile)
        if (w == 0) {
            FENCE_ASYNC();
            if (elect_one()) {
                uint64_t dPh = smem_desc_sw128(ab + AOFF_P);
                uint64_t dPl = smem_desc_sw128(ab + AOFF_P + 16384);
                uint64_t dVh = smem_desc_sw128(ab + AOFF_V);
                uint64_t dVl = smem_desc_sw128(ab + AOFF_V + 8192);
#pragma unroll
                for (int kk = 0; kk < 4; kk++)
                    mma_f16_ss(tmem + 64, dPh + kk * 2, dVh + kk * 2, ATT_IDESC, kk > 0);
#pragma unroll
                for (int kk = 0; kk < 4; kk++)
                    mma_f16_ss(tmem + 64, dPh + kk * 2, dVl + kk * 2, ATT_IDESC, 1);
#pragma unroll
                for (int kk = 0; kk < 4; kk++)
                    mma_f16_ss(tmem + 64, dPl + kk * 2, dVh + kk * 2, ATT_IDESC, 1);
                TC_COMMIT(sb + 16);
            }
        }
        mbar_wait(sb + 16, ppv & 1); ppv++;
        TC_FENCE_AFTER();
        uint32_t pr[32];
        LDTM_X32(pr, tmem + ((uint32_t)sp << 21) + 64 + kbase);
        TC_WAIT_LD();
#pragma unroll
        for (int i = 0; i < 32; i++) O[i] += __uint_as_float(pr[i]);
    }

    // epilogue: out[d = kbase + i] for row qg; write ys hi/lo (bf16 split)
    {
        float inv = 1.0f / l;
        size_t orow = ((size_t)(b * T_ + qg)) * C_ + h * 64 + kbase;
#pragma unroll
        for (int i = 0; i < 32; i++) {
            float vO = O[i] * inv;
            __nv_bfloat16 hh = __float2bfloat16(vO);
            g_ys_hi[orow + i] = hh;
            g_ys_lo[orow + i] = __float2bfloat16(vO - __bfloat162float(hh));
        }
    }
    __syncthreads();
    if (w == 0) TC_DEALLOC(tmem, 128);

#else  // ---------------- SIMT fallback (baseline target, never run) --------
    const int qt = blockIdx.x, h = blockIdx.y, b = blockIdx.z;
    const int kvh = h >> 2;
    int win = winp[0];
    if (win <= 0 || win > T_) win = 1024;
    const int tid = threadIdx.x;
    if (tid < 128) {
        const int qg = qt * 128 + tid;
        const __nv_bfloat16* qh = g_qs_hi + ((size_t)(b * NH_ + h) * T_ + qg) * HD_;
        const __nv_bfloat16* qlo = g_qs_lo + ((size_t)(b * NH_ + h) * T_ + qg) * HD_;
        float q[64];
        for (int d = 0; d < 64; d++)
            q[d] = __bfloat162float(qh[d]) + __bfloat162float(qlo[d]);
        const __nv_bfloat16* kh = g_ks_hi + ((size_t)(b * NKV_ + kvh) * T_) * HD_;
        const __nv_bfloat16* kl = g_ks_lo + ((size_t)(b * NKV_ + kvh) * T_) * HD_;
        const __nv_bfloat16* vth = g_vts_hi + ((size_t)(b * NKV_ + kvh) * HD_) * T_;
        const __nv_bfloat16* vtl = g_vts_lo + ((size_t)(b * NKV_ + kvh) * HD_) * T_;
        float m = -1e30f, l = 0.f, O[64];
        for (int d = 0; d < 64; d++) O[d] = 0.f;
        int js = qg - win;
        if (js < 0) js = 0;
        for (int j = js; j <= qg; j++) {
            float s = 0.f;
            for (int d = 0; d < 64; d++)
                s += q[d] * (__bfloat162float(kh[(size_t)j * 64 + d]) +
                             __bfloat162float(kl[(size_t)j * 64 + d]));
            s *= 0.125f;
            float mn = fmaxf(m, s);
            float corr = __expf(m - mn);
            float p = __expf(s - mn);
            l = l * corr + p;
            for (int d = 0; d < 64; d++)
                O[d] = O[d] * corr + p * (__bfloat162float(vth[(size_t)d * T_ + j]) +
                                          __bfloat162float(vtl[(size_t)d * T_ + j]));
            m = mn;
        }
        float inv = 1.0f / l;
        size_t orow = ((size_t)(b * T_ + qg)) * C_ + h * 64;
        for (int d = 0; d < 64; d++) {
            float vO = O[d] * inv;
            __nv_bfloat16 hh = __float2bfloat16(vO);
            g_ys_hi[orow + d] = hh;
            g_ys_lo[orow + d] = __float2bfloat16(vO - __bfloat162float(hh));
        }
    }
#endif
}

// ---------------------------------------------------------------------------
// Launch
// ---------------------------------------------------------------------------
extern "C" void kernel_launch(void* const* d_in, const int* in_sizes, int n_in,
                              void* d_out, int out_size) {
    const float* x     = (const float*)d_in[0];
    const float* ve    = (const float*)d_in[1];
    const float* cosb  = (const float*)d_in[2];
    const float* sinb  = (const float*)d_in[3];
    const float* Wq    = (const float*)d_in[4];
    const float* Wk    = (const float*)d_in[5];
    const float* Wv    = (const float*)d_in[6];
    const float* Wproj = (const float*)d_in[7];
    const float* Wgate = (const float*)d_in[8];
    const int*   win   = (const int*)d_in[9];
    float* out = (float*)d_out;

    __nv_bfloat16 *xs_hi, *xs_lo, *wqkv_hi, *wqkv_lo, *wproj_hi, *wproj_lo,
                  *ys_hi, *ys_lo;
    float *qkv;
    cudaGetSymbolAddress((void**)&xs_hi, g_xs_hi);
    cudaGetSymbolAddress((void**)&xs_lo, g_xs_lo);
    cudaGetSymbolAddress((void**)&wqkv_hi, g_wqkv_hi);
    cudaGetSymbolAddress((void**)&wqkv_lo, g_wqkv_lo);
    cudaGetSymbolAddress((void**)&wproj_hi, g_wproj_hi);
    cudaGetSymbolAddress((void**)&wproj_lo, g_wproj_lo);
    cudaGetSymbolAddress((void**)&ys_hi, g_ys_hi);
    cudaGetSymbolAddress((void**)&ys_lo, g_ys_lo);
    cudaGetSymbolAddress((void**)&qkv, g_qkv);

    cudaFuncSetAttribute(gemm_split,
                         cudaFuncAttributeMaxDynamicSharedMemorySize, GEMM_SMEM);
    cudaFuncSetAttribute(attn_tc,
                         cudaFuncAttributeMaxDynamicSharedMemorySize, ATT_SMEM);

    // 1. split x into hi/lo bf16
    split_fp32<<<(M_ * C_ + 255) / 256, 256>>>(x, xs_hi, xs_lo, M_ * C_);
    // 2. transpose + split weights into [N,K] bf16
    dim3 tb(32, 8);
    transpose_split<<<dim3(1024 / 32, C_ / 32), tb>>>(Wq, wqkv_hi, wqkv_lo, C_, 1024);
    transpose_split<<<dim3(256 / 32, C_ / 32), tb>>>(Wk, wqkv_hi + (size_t)1024 * C_,
                                                     wqkv_lo + (size_t)1024 * C_, C_, 256);
    transpose_split<<<dim3(256 / 32, C_ / 32), tb>>>(Wv, wqkv_hi + (size_t)1280 * C_,
                                                     wqkv_lo + (size_t)1280 * C_, C_, 256);
    transpose_split<<<dim3(C_ / 32, C_ / 32), tb>>>(Wproj, wproj_hi, wproj_lo, C_, C_);
    // 3. fused QKV projection on tensor cores
    gemm_split<<<dim3(NQKV_ / 128, M_ / 128), 256, GEMM_SMEM>>>(
        xs_hi, xs_lo, wqkv_hi, wqkv_lo, qkv, NQKV_);
    // 4. gate + RoPE + RMSNorm + bf16 split + layouts
    postproc<<<M_, 256>>>(x, ve, cosb, sinb, Wgate);
    // 5. tensor-core sliding-window attention (writes ys hi/lo directly)
    attn_tc<<<dim3(T_ / 128, NH_, B_), 256, ATT_SMEM>>>(win);
    // 6. output projection on tensor cores
    gemm_split<<<dim3(C_ / 128, M_ / 128), 256, GEMM_SMEM>>>(
        ys_hi, ys_lo, wproj_hi, wproj_lo, out, C_);
}

// round 9
// speedup vs baseline: 5.1481x; 1.0902x over previous
#include <cuda_runtime.h>
#include <cuda_bf16.h>
#include <math.h>
#include <stdint.h>

// Problem constants (fixed by the reference)
#define B_  2
#define T_  2048
#define C_  1024
#define NH_ 16
#define NKV_ 4
#define HD_ 64
#define VEC_ 32
#define M_  (B_ * T_)      // 4096 token rows
#define NQKV_ 1536         // fused q(1024) | k(256) | v(256) columns

// tcgen05 is arch-conditional: only in the sm_103a/sm_100a passes. The
// baseline compute_103 target gets SIMT fallback bodies.
#if defined(__CUDA_ARCH_FEAT_SM103_ALL) || defined(__CUDA_ARCH_FEAT_SM100_ALL) || \
    defined(__CUDA_ARCH_FEAT_SM101_ALL)
#define TC_OK 1
#else
#define TC_OK 0
#endif

// ---------------------------------------------------------------------------
// Scratch (static device globals; no runtime allocation allowed)
// ---------------------------------------------------------------------------
__device__ __align__(16) __nv_bfloat16 g_wqkv_hi[NQKV_ * C_];  // [N,K] transposed
__device__ __align__(16) __nv_bfloat16 g_wqkv_lo[NQKV_ * C_];
__device__ __align__(16) __nv_bfloat16 g_wproj_hi[C_ * C_];    // [N,K] transposed
__device__ __align__(16) __nv_bfloat16 g_wproj_lo[C_ * C_];
__device__ float g_qkv[M_ * NQKV_];        // fused projection output
__device__ float g_y[M_ * C_];             // attention output [B,T,NH*HD] fp32
// attention operands, bf16 hi/lo split
__device__ __align__(16) __nv_bfloat16 g_qs_hi[M_ * NH_ * HD_];   // [B,NH,T,HD]
__device__ __align__(16) __nv_bfloat16 g_qs_lo[M_ * NH_ * HD_];
__device__ __align__(16) __nv_bfloat16 g_ks_hi[M_ * NKV_ * HD_];  // [B,NKV,T,HD]
__device__ __align__(16) __nv_bfloat16 g_ks_lo[M_ * NKV_ * HD_];
__device__ __align__(16) __nv_bfloat16 g_vts_hi[M_ * NKV_ * HD_]; // [B,NKV,HD,T]
__device__ __align__(16) __nv_bfloat16 g_vts_lo[M_ * NKV_ * HD_];

// ---------------------------------------------------------------------------
// PTX helpers
// ---------------------------------------------------------------------------
__device__ __forceinline__ uint32_t smem_u32(const void* p) {
    uint32_t a;
    asm("{ .reg .u64 t; cvta.to.shared.u64 t, %1; cvt.u32.u64 %0, t; }"
        : "=r"(a) : "l"(p));
    return a;
}
__device__ __forceinline__ uint32_t elect_one() {
    uint32_t pred;
    asm volatile("{\n\t.reg .pred p;\n\telect.sync _|p, 0xFFFFFFFF;\n\t"
                 "selp.b32 %0, 1, 0, p;\n\t}" : "=r"(pred));
    return pred;
}
#define TC_ALLOC(sm, n)   asm volatile("tcgen05.alloc.cta_group::1.sync.aligned.shared::cta.b32 [%0], %1;" :: "r"(sm), "r"((uint32_t)(n)) : "memory")
#define TC_DEALLOC(t, n)  asm volatile("tcgen05.dealloc.cta_group::1.sync.aligned.b32 %0, %1;" :: "r"(t), "r"((uint32_t)(n)))
#define TC_COMMIT(mbar)   asm volatile("tcgen05.commit.cta_group::1.mbarrier::arrive::one.shared::cluster.b64 [%0];" :: "r"(mbar) : "memory")
#define TC_FENCE_AFTER()  asm volatile("tcgen05.fence::after_thread_sync;" ::: "memory")
#define TC_WAIT_LD()      asm volatile("tcgen05.wait::ld.sync.aligned;" ::: "memory")
#define MBAR_INIT(sm, n)  asm volatile("mbarrier.init.shared.b64 [%0], %1;" :: "r"(sm), "r"((uint32_t)(n)) : "memory")
#define FENCE_ASYNC()     asm volatile("fence.proxy.async.shared::cta;" ::: "memory")

__device__ __forceinline__ void mbar_wait(uint32_t mbar, uint32_t parity) {
    asm volatile(
        "{\n\t.reg .pred P;\n\t"
        "W%=:\n\t"
        "mbarrier.try_wait.parity.acquire.cta.shared::cta.b64 P, [%0], %1, 0x989680;\n\t"
        "@P bra D%=;\n\t"
        "bra W%=;\n\t"
        "D%=:\n\t}"
        :: "r"(mbar), "r"(parity) : "memory");
}

#if TC_OK
// SS-mode bf16 MMA, cta_group::1, fp32 accum
__device__ __forceinline__ void mma_f16_ss(uint32_t d, uint64_t a, uint64_t b,
                                           uint32_t idesc, uint32_t en) {
    asm volatile(
        "{\n\t.reg .pred p;\n\t"
        "setp.ne.u32 p, %4, 0;\n\t"
        "tcgen05.mma.cta_group::1.kind::f16 [%0], %1, %2, %3, {%5, %5, %5, %5}, p;\n\t"
        "}"
        :: "r"(d), "l"(a), "l"(b), "r"(idesc), "r"(en), "r"(0u)
        : "memory");
}

#define LDTM_X32(r, addr) \
    asm volatile( \
        "tcgen05.ld.sync.aligned.32x32b.x32.b32 " \
        "{%0, %1, %2, %3, %4, %5, %6, %7, " \
        " %8, %9, %10, %11, %12, %13, %14, %15, " \
        " %16, %17, %18, %19, %20, %21, %22, %23, " \
        " %24, %25, %26, %27, %28, %29, %30, %31}, [%32];" \
        : "=r"((r)[0]),  "=r"((r)[1]),  "=r"((r)[2]),  "=r"((r)[3]), \
          "=r"((r)[4]),  "=r"((r)[5]),  "=r"((r)[6]),  "=r"((r)[7]), \
          "=r"((r)[8]),  "=r"((r)[9]),  "=r"((r)[10]), "=r"((r)[11]), \
          "=r"((r)[12]), "=r"((r)[13]), "=r"((r)[14]), "=r"((r)[15]), \
          "=r"((r)[16]), "=r"((r)[17]), "=r"((r)[18]), "=r"((r)[19]), \
          "=r"((r)[20]), "=r"((r)[21]), "=r"((r)[22]), "=r"((r)[23]), \
          "=r"((r)[24]), "=r"((r)[25]), "=r"((r)[26]), "=r"((r)[27]), \
          "=r"((r)[28]), "=r"((r)[29]), "=r"((r)[30]), "=r"((r)[31]) \
        : "r"(addr))
#endif  // TC_OK

// 64-bit SMEM descriptor: SW128, version=1 (Blackwell), LBO=1, SBO=64
static __device__ __forceinline__ uint64_t smem_desc_sw128(uint32_t addr) {
    const uint64_t base =
        (uint64_t(2)  << 61) | (uint64_t(1) << 46) |
        (uint64_t(64) << 32) | (uint64_t(1) << 16);
    return base | ((uint64_t)(addr >> 4) & 0x3FFF);
}
#define SW128(off) ((off) ^ (((off) >> 3) & 0x70))

// idesc: dtype=F32, atype=BF16, btype=BF16 (K-major both)
#define GEMM_IDESC ((1u << 4) | (1u << 7) | (1u << 10) | ((128u / 8) << 17) | ((128u / 16) << 24))
#define ATT_IDESC  ((1u << 4) | (1u << 7) | (1u << 10) | ((64u / 8) << 17) | ((128u / 16) << 24))

__device__ __forceinline__ uint32_t b2u(__nv_bfloat162 v) {
    return *(uint32_t*)&v;
}

// ---------------------------------------------------------------------------
// Combined weight transpose + hi/lo split.
// grid (80, 32): blockIdx.x selects col-tile across {Wq:32, Wk:8, Wv:8, Wproj:32}
// ---------------------------------------------------------------------------
__global__ __launch_bounds__(256) void transpose_split_all(
    const float* __restrict__ Wq, const float* __restrict__ Wk,
    const float* __restrict__ Wv, const float* __restrict__ Wp) {
    __shared__ float t[32][33];
    const int ct = blockIdx.x;
    const float* W;
    __nv_bfloat16 *hi, *lo;
    int Ncols, nb;
    if (ct < 32)      { W = Wq; hi = g_wqkv_hi;                     lo = g_wqkv_lo;                     Ncols = 1024; nb = ct * 32; }
    else if (ct < 40) { W = Wk; hi = g_wqkv_hi + (size_t)1024 * C_; lo = g_wqkv_lo + (size_t)1024 * C_; Ncols = 256;  nb = (ct - 32) * 32; }
    else if (ct < 48) { W = Wv; hi = g_wqkv_hi + (size_t)1280 * C_; lo = g_wqkv_lo + (size_t)1280 * C_; Ncols = 256;  nb = (ct - 40) * 32; }
    else              { W = Wp; hi = g_wproj_hi;                    lo = g_wproj_lo;                    Ncols = 1024; nb = (ct - 48) * 32; }
    const int kb = blockIdx.y * 32;
    const int tx = threadIdx.x, ty = threadIdx.y;
#pragma unroll
    for (int j = 0; j < 32; j += 8)
        t[ty + j][tx] = W[(size_t)(kb + ty + j) * Ncols + nb + tx];
    __syncthreads();
#pragma unroll
    for (int j = 0; j < 32; j += 8) {
        float v = t[tx][ty + j];
        __nv_bfloat16 h = __float2bfloat16(v);
        size_t o = (size_t)(nb + ty + j) * C_ + kb + tx;
        hi[o] = h;
        lo[o] = __float2bfloat16(v - __bfloat162float(h));
    }
}

// ---------------------------------------------------------------------------
// Split-bf16 GEMM: C[M,N] = A[M,K] . Bt[N,K]^T  (fp32-accurate)
// A is fp32 and converted to hi/lo bf16 in-register during the smem fill
// (no separate split pass). B pre-split. 128x128 tile, K-chunk 64, 3 combos,
// double-buffered, mbarrier-paced. grid = (N/128, M/128), 256 threads.
// ---------------------------------------------------------------------------
#define KCHUNK   64
#define NCHUNKS  (C_ / KCHUNK)           // 16
#define BUFSZ    16384                   // 128 rows x 128 bytes
#define STAGESZ  (4 * BUFSZ)             // Ahi | Alo | Bhi | Blo
#define GEMM_SMEM (2048 + 2 * STAGESZ)

__global__ __launch_bounds__(256) void gemm_split(
    const float* __restrict__ A,
    const __nv_bfloat16* __restrict__ Bhi, const __nv_bfloat16* __restrict__ Blo,
    float* __restrict__ C, int N) {
#if TC_OK
    extern __shared__ char smem[];
    const uint32_t sb = smem_u32(smem);
    const uint32_t ab = (sb + 1024 + 1023) & 0xFFFFFC00u;
    char* smab = smem + (ab - sb);
    const int tid = threadIdx.x;
    const int wid = tid >> 5;
    const int lane = tid & 31;
    const int bm = blockIdx.y * 128;
    const int bn = blockIdx.x * 128;
    const int K = C_;

    if (wid == 0) TC_ALLOC(sb, 128);
    if (tid == 0) { MBAR_INIT(sb + 8, 1); MBAR_INIT(sb + 16, 1); }
    __syncthreads();
    uint32_t tmem;
    asm volatile("ld.shared.b32 %0, [%1];" : "=r"(tmem) : "r"(sb));

#define LOAD_CHUNK(kc, s)                                                     \
    do {                                                                      \
        const int k0 = (kc) * KCHUNK;                                         \
        char* st = smab + (s) * STAGESZ;                                      \
        _Pragma("unroll")                                                     \
        for (int v = 0; v < 4; v++) {                                         \
            int idx = tid + v * 256;                                          \
            int r = idx >> 3, c8 = idx & 7;                                   \
            uint32_t off = SW128((uint32_t)(r * 128 + c8 * 16));              \
            const float* ap = A + (size_t)(bm + r) * K + k0 + c8 * 8;         \
            float4 a0 = *(const float4*)ap;                                   \
            float4 a1 = *(const float4*)(ap + 4);                             \
            __nv_bfloat162 h0 = __floats2bfloat162_rn(a0.x, a0.y);            \
            __nv_bfloat162 h1 = __floats2bfloat162_rn(a0.z, a0.w);            \
            __nv_bfloat162 h2 = __floats2bfloat162_rn(a1.x, a1.y);            \
            __nv_bfloat162 h3 = __floats2bfloat162_rn(a1.z, a1.w);            \
            __nv_bfloat162 l0 = __floats2bfloat162_rn(                        \
                a0.x - __bfloat162float(h0.x), a0.y - __bfloat162float(h0.y));\
            __nv_bfloat162 l1 = __floats2bfloat162_rn(                        \
                a0.z - __bfloat162float(h1.x), a0.w - __bfloat162float(h1.y));\
            __nv_bfloat162 l2 = __floats2bfloat162_rn(                        \
                a1.x - __bfloat162float(h2.x), a1.y - __bfloat162float(h2.y));\
            __nv_bfloat162 l3 = __floats2bfloat162_rn(                        \
                a1.z - __bfloat162float(h3.x), a1.w - __bfloat162float(h3.y));\
            uint4 hv = make_uint4(b2u(h0), b2u(h1), b2u(h2), b2u(h3));        \
            uint4 lv = make_uint4(b2u(l0), b2u(l1), b2u(l2), b2u(l3));        \
            *(uint4*)(st + off)         = hv;                                 \
            *(uint4*)(st + BUFSZ + off) = lv;                                 \
            size_t gb = (size_t)(bn + r) * K + k0 + c8 * 8;                   \
            *(uint4*)(st + 2 * BUFSZ + off) = *(const uint4*)(Bhi + gb);      \
            *(uint4*)(st + 3 * BUFSZ + off) = *(const uint4*)(Blo + gb);      \
        }                                                                     \
    } while (0)

    LOAD_CHUNK(0, 0);
    int p0 = 0, p1 = 0;

    for (int i = 0; i < NCHUNKS; i++) {
        const int s = i & 1;
        __syncthreads();
        if (wid == 0) {
            FENCE_ASYNC();
            if (elect_one()) {
                uint32_t base = ab + s * STAGESZ;
                uint64_t dah = smem_desc_sw128(base);
                uint64_t dal = smem_desc_sw128(base + BUFSZ);
                uint64_t dbh = smem_desc_sw128(base + 2 * BUFSZ);
                uint64_t dbl = smem_desc_sw128(base + 3 * BUFSZ);
#pragma unroll
                for (int kk = 0; kk < 4; kk++)
                    mma_f16_ss(tmem, dah + kk * 2, dbh + kk * 2, GEMM_IDESC,
                               (i > 0) || (kk > 0));
#pragma unroll
                for (int kk = 0; kk < 4; kk++)
                    mma_f16_ss(tmem, dah + kk * 2, dbl + kk * 2, GEMM_IDESC, 1);
#pragma unroll
                for (int kk = 0; kk < 4; kk++)
                    mma_f16_ss(tmem, dal + kk * 2, dbh + kk * 2, GEMM_IDESC, 1);
                TC_COMMIT(sb + 8 + s * 8);
            }
        }
        if (i + 1 < NCHUNKS) {
            const int s2 = (i + 1) & 1;
            if (i >= 1) {
                if (s2 == 0) { mbar_wait(sb + 8,  p0 & 1); p0++; }
                else         { mbar_wait(sb + 16, p1 & 1); p1++; }
            }
            LOAD_CHUNK(i + 1, s2);
        }
    }
    {
        const int sl = (NCHUNKS - 1) & 1;
        if (sl == 0) mbar_wait(sb + 8, p0 & 1);
        else         mbar_wait(sb + 16, p1 & 1);
    }
    TC_FENCE_AFTER();

    {
        const int sp = wid & 3;
        const int colbase = (wid >> 2) * 64;
        const uint32_t wo = (uint32_t)sp << 21;
        uint32_t d0[32], d1[32];
        LDTM_X32(d0, tmem + wo + colbase);
        LDTM_X32(d1, tmem + wo + colbase + 32);
        TC_WAIT_LD();
        const int row = bm + sp * 32 + lane;
        float* dst = C + (size_t)row * N + bn + colbase;
#pragma unroll
        for (int c = 0; c < 32; c += 4) {
            *(float4*)(dst + c) = make_float4(
                __uint_as_float(d0[c]), __uint_as_float(d0[c + 1]),
                __uint_as_float(d0[c + 2]), __uint_as_float(d0[c + 3]));
            *(float4*)(dst + 32 + c) = make_float4(
                __uint_as_float(d1[c]), __uint_as_float(d1[c + 1]),
                __uint_as_float(d1[c + 2]), __uint_as_float(d1[c + 3]));
        }
    }
    __syncthreads();
    if (wid == 0) TC_DEALLOC(tmem, 128);
#undef LOAD_CHUNK

#else  // SIMT fallback
    __shared__ float As[8][128];
    __shared__ float Bs[8][128];
    const int tid = threadIdx.x;
    const int bm = blockIdx.y * 128;
    const int bn = blockIdx.x * 128;
    const int K = C_;
    const int ldRow = tid >> 1;
    const int ldK   = (tid & 1) * 4;
    const int ri = (tid >> 4) * 4;
    const int ci = (tid & 15) * 4;

    float acc[8][8];
#pragma unroll
    for (int i = 0; i < 8; i++)
#pragma unroll
        for (int j = 0; j < 8; j++) acc[i][j] = 0.f;

    for (int k0 = 0; k0 < K; k0 += 8) {
#pragma unroll
        for (int c = 0; c < 4; c++) {
            size_t ga = (size_t)(bm + ldRow) * K + k0 + ldK + c;
            size_t gb = (size_t)(bn + ldRow) * K + k0 + ldK + c;
            As[ldK + c][ldRow] = A[ga];
            Bs[ldK + c][ldRow] = __bfloat162float(Bhi[gb]) + __bfloat162float(Blo[gb]);
        }
        __syncthreads();
#pragma unroll
        for (int kk = 0; kk < 8; kk++) {
            float ar[8], br[8];
#pragma unroll
            for (int i = 0; i < 4; i++) {
                ar[i] = As[kk][ri + i];
                ar[i + 4] = As[kk][ri + 64 + i];
                br[i] = Bs[kk][ci + i];
                br[i + 4] = Bs[kk][ci + 64 + i];
            }
#pragma unroll
            for (int i = 0; i < 8; i++)
#pragma unroll
                for (int j = 0; j < 8; j++) acc[i][j] += ar[i] * br[j];
        }
        __syncthreads();
    }
#pragma unroll
    for (int ib = 0; ib < 2; ib++)
#pragma unroll
        for (int i = 0; i < 4; i++) {
            int row = bm + ib * 64 + ri + i;
#pragma unroll
            for (int jb = 0; jb < 2; jb++)
#pragma unroll
                for (int j = 0; j < 4; j++)
                    C[(size_t)row * N + bn + jb * 64 + ci + j] =
                        acc[ib * 4 + i][jb * 4 + j];
        }
#endif
}

// ---------------------------------------------------------------------------
// Per-token post-process: gate, v += gate*ve, RoPE + RMSNorm on q/k.
// Outputs bf16 hi/lo: Q [B,NH,T,HD], K [B,NKV,T,HD], V^T [B,NKV,HD,T].
// ---------------------------------------------------------------------------
__global__ __launch_bounds__(256) void postproc(
    const float* __restrict__ x, const float* __restrict__ ve,
    const float* __restrict__ cosb, const float* __restrict__ sinb,
    const float* __restrict__ Wgate) {
    const int bt = blockIdx.x;
    const int b = bt / T_, t = bt % T_;
    const int tid = threadIdx.x;
    const int lane = tid & 31, w = tid >> 5;
    __shared__ float s_gate[NKV_];

    if (w < NKV_) {
        float p = x[(size_t)bt * C_ + lane] * Wgate[lane * NKV_ + w];
#pragma unroll
        for (int o = 16; o; o >>= 1) p += __shfl_xor_sync(0xffffffffu, p, o);
        if (lane == 0) s_gate[w] = 2.0f / (1.0f + expf(-p));
    }
    __syncthreads();

    const float c = cosb[t * (HD_ / 2) + lane];
    const float s = sinb[t * (HD_ / 2) + lane];
    const float* qkvrow = g_qkv + (size_t)bt * NQKV_;
    for (int row = w; row < NH_ + NKV_; row += 8) {
        const float* src;
        __nv_bfloat16 *dhi, *dlo;
        if (row < NH_) {
            src = qkvrow + row * HD_;
            size_t base = ((size_t)(b * NH_ + row) * T_ + t) * HD_;
            dhi = g_qs_hi + base;
            dlo = g_qs_lo + base;
        } else {
            int kh = row - NH_;
            src = qkvrow + 1024 + kh * HD_;
            size_t base = ((size_t)(b * NKV_ + kh) * T_ + t) * HD_;
            dhi = g_ks_hi + base;
            dlo = g_ks_lo + base;
        }
        float x1 = src[lane], x2 = src[lane + 32];
        float o1 = x1 * c + x2 * s;
        float o2 = -x1 * s + x2 * c;
        float sq = o1 * o1 + o2 * o2;
#pragma unroll
        for (int o = 16; o; o >>= 1) sq += __shfl_xor_sync(0xffffffffu, sq, o);
        float scale = rsqrtf(sq * (1.0f / HD_) + 1.1920929e-7f);
        float v1 = o1 * scale, v2 = o2 * scale;
        __nv_bfloat16 h1 = __float2bfloat16(v1);
        __nv_bfloat16 h2 = __float2bfloat16(v2);
        dhi[lane] = h1;
        dhi[lane + 32] = h2;
        dlo[lane] = __float2bfloat16(v1 - __bfloat162float(h1));
        dlo[lane + 32] = __float2bfloat16(v2 - __bfloat162float(h2));
    }

    {
        int h = tid >> 6, d = tid & 63;
        float val = qkvrow[1280 + tid] +
                    s_gate[h] * ve[(size_t)bt * (NKV_ * HD_) + tid];
        size_t o = ((size_t)(b * NKV_ + h) * HD_ + d) * T_ + t;  // transposed
        __nv_bfloat16 hh = __float2bfloat16(val);
        g_vts_hi[o] = hh;
        g_vts_lo[o] = __float2bfloat16(val - __bfloat162float(hh));
    }
}

// ---------------------------------------------------------------------------
// tcgen05 sliding-window flash attention, STATIC-MAX softmax.
// After RMSNorm |q|=|k|=8, so scores s/8 in [-8, 8]. Use fixed max 8:
//   p = exp(s/8 - 8), common factor cancels in O/l. No online max, no
//   O-correction; PV accumulates in TMEM across key tiles (enable_d).
// grid = (T/128, NH, B), 256 threads, 2 CTAs/SM.
// ---------------------------------------------------------------------------
#define AOFF_RED 0        // redsum[256] f32 (1KB)
#define AOFF_Q   2048     // Qhi 16K | Qlo 16K
#define AOFF_K   34816    // Khi 8K | Klo 8K
#define AOFF_V   51200    // Vhi 8K | Vlo 8K
#define AOFF_P   67584    // Phi 16K | Plo 16K  (end 100352)
#define ATT_SMEM 102400

__global__ __launch_bounds__(256, 2) void attn_tc(const int* __restrict__ winp) {
#if TC_OK
    extern __shared__ char smem[];
    const uint32_t sb = smem_u32(smem);
    const uint32_t ab = (sb + 1024 + 1023) & 0xFFFFFC00u;
    char* abp = smem + (ab - sb);

    int win = winp[0];
    if (win <= 0 || win > T_) win = 1024;
    const int qt = blockIdx.x, h = blockIdx.y, b = blockIdx.z;
    const int kvh = h >> 2;
    const int q0 = qt * 128;
    const int tid = threadIdx.x, w = tid >> 5, lane = tid & 31;
    const int sp = w & 3;              // TMEM subpartition
    const int hf = w >> 2;             // key/dim half (0 or 1)
    const int kbase = hf * 32;
    const int r = sp * 32 + lane;      // q row within tile
    const int qg = q0 + r;             // global q index

    float* redsum = (float*)(abp + AOFF_RED);

    if (w == 0) TC_ALLOC(sb, 128);
    if (tid == 0) { MBAR_INIT(sb + 8, 1); MBAR_INIT(sb + 16, 1); }
    __syncthreads();
    uint32_t tmem;
    asm volatile("ld.shared.b32 %0, [%1];" : "=r"(tmem) : "r"(sb));

    // Load Q tile [128 x 64] hi/lo into SW128 smem
    const __nv_bfloat16* qh  = g_qs_hi + ((size_t)(b * NH_ + h) * T_ + q0) * HD_;
    const __nv_bfloat16* qlo = g_qs_lo + ((size_t)(b * NH_ + h) * T_ + q0) * HD_;
#pragma unroll
    for (int v = 0; v < 4; v++) {
        int idx = tid + v * 256;
        int rr = idx >> 3, c8 = idx & 7;
        uint32_t off = SW128((uint32_t)(rr * 128 + c8 * 16));
        *(uint4*)(abp + AOFF_Q + off)         = *(const uint4*)(qh  + rr * 64 + c8 * 8);
        *(uint4*)(abp + AOFF_Q + 16384 + off) = *(const uint4*)(qlo + rr * 64 + c8 * 8);
    }

    const __nv_bfloat16* kh  = g_ks_hi  + ((size_t)(b * NKV_ + kvh) * T_) * HD_;
    const __nv_bfloat16* kl  = g_ks_lo  + ((size_t)(b * NKV_ + kvh) * T_) * HD_;
    const __nv_bfloat16* vth = g_vts_hi + ((size_t)(b * NKV_ + kvh) * HD_) * T_;
    const __nv_bfloat16* vtl = g_vts_lo + ((size_t)(b * NKV_ + kvh) * HD_) * T_;

    float l_loc = 0.f;
    int ps = 0, ppv = 0;

    int j0s = q0 - win;
    if (j0s < 0) j0s = 0;
    const int jt0 = j0s >> 6;
    const int jt1 = (q0 + 127) >> 6;

    for (int jt = jt0; jt <= jt1; jt++) {
        const int j0 = jt * 64;
        // PV(jt-1) must be done before we overwrite V (and P later)
        if (jt > jt0) { mbar_wait(sb + 16, ppv & 1); ppv++; }
        __syncthreads();
        // Load K tile [64 keys x 64 d] and V^T tile [64 d x 64 keys], hi/lo
#pragma unroll
        for (int v = 0; v < 2; v++) {
            int idx = tid + v * 256;
            int rr = idx >> 3, c8 = idx & 7;
            uint32_t off = SW128((uint32_t)(rr * 128 + c8 * 16));
            *(uint4*)(abp + AOFF_K + off)        = *(const uint4*)(kh  + (size_t)(j0 + rr) * 64 + c8 * 8);
            *(uint4*)(abp + AOFF_K + 8192 + off) = *(const uint4*)(kl  + (size_t)(j0 + rr) * 64 + c8 * 8);
            *(uint4*)(abp + AOFF_V + off)        = *(const uint4*)(vth + (size_t)rr * T_ + j0 + c8 * 8);
            *(uint4*)(abp + AOFF_V + 8192 + off) = *(const uint4*)(vtl + (size_t)rr * T_ + j0 + c8 * 8);
        }
        __syncthreads();
        // S = Q.K^T (3 split combos x 4 K-steps) -> TMEM cols 0-63 (fresh)
        if (w == 0) {
            FENCE_ASYNC();
            if (elect_one()) {
                uint64_t dQh = smem_desc_sw128(ab + AOFF_Q);
                uint64_t dQl = smem_desc_sw128(ab + AOFF_Q + 16384);
                uint64_t dKh = smem_desc_sw128(ab + AOFF_K);
                uint64_t dKl = smem_desc_sw128(ab + AOFF_K + 8192);
#pragma unroll
                for (int kk = 0; kk < 4; kk++)
                    mma_f16_ss(tmem, dQh + kk * 2, dKh + kk * 2, ATT_IDESC, kk > 0);
#pragma unroll
                for (int kk = 0; kk < 4; kk++)
                    mma_f16_ss(tmem, dQh + kk * 2, dKl + kk * 2, ATT_IDESC, 1);
#pragma unroll
                for (int kk = 0; kk < 4; kk++)
                    mma_f16_ss(tmem, dQl + kk * 2, dKh + kk * 2, ATT_IDESC, 1);
                TC_COMMIT(sb + 8);
            }
        }
        mbar_wait(sb + 8, ps & 1); ps++;
        TC_FENCE_AFTER();

        // ---- static-max softmax: p = exp(s/8 - 8), masked -> 0 ----
        uint32_t sr[32];
        LDTM_X32(sr, tmem + ((uint32_t)sp << 21) + kbase);
        TC_WAIT_LD();
        float p[32];
#pragma unroll
        for (int i = 0; i < 32; i++) {
            int jg = j0 + kbase + i;
            bool ok = (jg <= qg) && (jg >= qg - win);
            float e = __expf(__uint_as_float(sr[i]) * 0.125f - 8.0f);
            p[i] = ok ? e : 0.f;
            l_loc += p[i];
        }
        // write P hi/lo to smem (row r, keys kbase..kbase+31)
#pragma unroll
        for (int i = 0; i < 16; i++) {
            float pa = p[2 * i], pb = p[2 * i + 1];
            __nv_bfloat162 hh = __floats2bfloat162_rn(pa, pb);
            float la = pa - __bfloat162float(hh.x);
            float lb = pb - __bfloat162float(hh.y);
            __nv_bfloat162 ll = __floats2bfloat162_rn(la, lb);
            uint32_t boff = SW128((uint32_t)(r * 128 + (kbase + 2 * i) * 2));
            *(uint32_t*)(abp + AOFF_P + boff)         = b2u(hh);
            *(uint32_t*)(abp + AOFF_P + 16384 + boff) = b2u(ll);
        }
        __syncthreads();
        // PV = P.V^T (3 split combos) -> TMEM cols 64-127, ACCUMULATED
        if (w == 0) {
            FENCE_ASYNC();
            if (elect_one()) {
                uint64_t dPh = smem_desc_sw128(ab + AOFF_P);
                uint64_t dPl = smem_desc_sw128(ab + AOFF_P + 16384);
                uint64_t dVh = smem_desc_sw128(ab + AOFF_V);
                uint64_t dVl = smem_desc_sw128(ab + AOFF_V + 8192);
#pragma unroll
                for (int kk = 0; kk < 4; kk++)
                    mma_f16_ss(tmem + 64, dPh + kk * 2, dVh + kk * 2, ATT_IDESC,
                               (jt > jt0) || (kk > 0));
#pragma unroll
                for (int kk = 0; kk < 4; kk++)
                    mma_f16_ss(tmem + 64, dPh + kk * 2, dVl + kk * 2, ATT_IDESC, 1);
#pragma unroll
                for (int kk = 0; kk < 4; kk++)
                    mma_f16_ss(tmem + 64, dPl + kk * 2, dVh + kk * 2, ATT_IDESC, 1);
                TC_COMMIT(sb + 16);
            }
        }
    }
    // drain final PV, combine l over the two key halves, write O
    mbar_wait(sb + 16, ppv & 1);
    TC_FENCE_AFTER();
    redsum[r * 2 + hf] = l_loc;
    __syncthreads();
    const float l = redsum[r * 2] + redsum[r * 2 + 1];
    uint32_t pr[32];
    LDTM_X32(pr, tmem + ((uint32_t)sp << 21) + 64 + kbase);
    TC_WAIT_LD();
    {
        const float inv = 1.0f / l;
        float* dst = g_y + ((size_t)(b * T_ + qg)) * C_ + h * 64 + kbase;
#pragma unroll
        for (int i = 0; i < 32; i += 4)
            *(float4*)(dst + i) = make_float4(
                __uint_as_float(pr[i]) * inv, __uint_as_float(pr[i + 1]) * inv,
                __uint_as_float(pr[i + 2]) * inv, __uint_as_float(pr[i + 3]) * inv);
    }
    __syncthreads();
    if (w == 0) TC_DEALLOC(tmem, 128);

#else  // ---------------- SIMT fallback (baseline target, never run) --------
    const int qt = blockIdx.x, h = blockIdx.y, b = blockIdx.z;
    const int kvh = h >> 2;
    int win = winp[0];
    if (win <= 0 || win > T_) win = 1024;
    const int tid = threadIdx.x;
    if (tid < 128) {
        const int qg = qt * 128 + tid;
        const __nv_bfloat16* qh  = g_qs_hi + ((size_t)(b * NH_ + h) * T_ + qg) * HD_;
        const __nv_bfloat16* qlo = g_qs_lo + ((size_t)(b * NH_ + h) * T_ + qg) * HD_;
        float q[64];
        for (int d = 0; d < 64; d++)
            q[d] = __bfloat162float(qh[d]) + __bfloat162float(qlo[d]);
        const __nv_bfloat16* kh  = g_ks_hi  + ((size_t)(b * NKV_ + kvh) * T_) * HD_;
        const __nv_bfloat16* kl  = g_ks_lo  + ((size_t)(b * NKV_ + kvh) * T_) * HD_;
        const __nv_bfloat16* vth = g_vts_hi + ((size_t)(b * NKV_ + kvh) * HD_) * T_;
        const __nv_bfloat16* vtl = g_vts_lo + ((size_t)(b * NKV_ + kvh) * HD_) * T_;
        float l = 0.f, O[64];
        for (int d = 0; d < 64; d++) O[d] = 0.f;
        int js = qg - win;
        if (js < 0) js = 0;
        for (int j = js; j <= qg; j++) {
            float s = 0.f;
            for (int d = 0; d < 64; d++)
                s += q[d] * (__bfloat162float(kh[(size_t)j * 64 + d]) +
                             __bfloat162float(kl[(size_t)j * 64 + d]));
            float p = __expf(s * 0.125f - 8.0f);
            l += p;
            for (int d = 0; d < 64; d++)
                O[d] += p * (__bfloat162float(vth[(size_t)d * T_ + j]) +
                             __bfloat162float(vtl[(size_t)d * T_ + j]));
        }
        float inv = 1.0f / l;
        float* dst = g_y + ((size_t)(b * T_ + qg)) * C_ + h * 64;
        for (int d = 0; d < 64; d++) dst[d] = O[d] * inv;
    }
#endif
}

// ---------------------------------------------------------------------------
// Launch: weights prep -> QKV GEMM (fp32 A fused split) -> postproc ->
//         attention (fp32 y out) -> output GEMM (fp32 A fused split)
// ---------------------------------------------------------------------------
extern "C" void kernel_launch(void* const* d_in, const int* in_sizes, int n_in,
                              void* d_out, int out_size) {
    const float* x     = (const float*)d_in[0];
    const float* ve    = (const float*)d_in[1];
    const float* cosb  = (const float*)d_in[2];
    const float* sinb  = (const float*)d_in[3];
    const float* Wq    = (const float*)d_in[4];
    const float* Wk    = (const float*)d_in[5];
    const float* Wv    = (const float*)d_in[6];
    const float* Wproj = (const float*)d_in[7];
    const float* Wgate = (const float*)d_in[8];
    const int*   win   = (const int*)d_in[9];
    float* out = (float*)d_out;

    __nv_bfloat16 *wqkv_hi, *wqkv_lo, *wproj_hi, *wproj_lo;
    float *qkv, *yb;
    cudaGetSymbolAddress((void**)&wqkv_hi, g_wqkv_hi);
    cudaGetSymbolAddress((void**)&wqkv_lo, g_wqkv_lo);
    cudaGetSymbolAddress((void**)&wproj_hi, g_wproj_hi);
    cudaGetSymbolAddress((void**)&wproj_lo, g_wproj_lo);
    cudaGetSymbolAddress((void**)&qkv, g_qkv);
    cudaGetSymbolAddress((void**)&yb, g_y);

    cudaFuncSetAttribute(gemm_split,
                         cudaFuncAttributeMaxDynamicSharedMemorySize, GEMM_SMEM);
    cudaFuncSetAttribute(attn_tc,
                         cudaFuncAttributeMaxDynamicSharedMemorySize, ATT_SMEM);

    // 1. transpose + split all weights (one launch)
    transpose_split_all<<<dim3(80, C_ / 32), dim3(32, 8)>>>(Wq, Wk, Wv, Wproj);
    // 2. fused QKV projection (A = x fp32, split in-kernel)
    gemm_split<<<dim3(NQKV_ / 128, M_ / 128), 256, GEMM_SMEM>>>(
        x, wqkv_hi, wqkv_lo, qkv, NQKV_);
    // 3. gate + RoPE + RMSNorm + bf16 split + layouts
    postproc<<<M_, 256>>>(x, ve, cosb, sinb, Wgate);
    // 4. tensor-core attention, static-max softmax, fp32 y out
    attn_tc<<<dim3(T_ / 128, NH_, B_), 256, ATT_SMEM>>>(win);
    // 5. output projection (A = y fp32, split in-kernel)
    gemm_split<<<dim3(C_ / 128, M_ / 128), 256, GEMM_SMEM>>>(
        yb, wproj_hi, wproj_lo, out, C_);
}

// round 11
// speedup vs baseline: 5.4089x; 1.0507x over previous
#include <cuda_runtime.h>
#include <cuda_bf16.h>
#include <math.h>
#include <stdint.h>

// Problem constants (fixed by the reference)
#define B_  2
#define T_  2048
#define C_  1024
#define NH_ 16
#define NKV_ 4
#define HD_ 64
#define VEC_ 32
#define M_  (B_ * T_)      // 4096 token rows
#define NQKV_ 1536         // fused q(1024) | k(256) | v(256) columns

// tcgen05 is arch-conditional: only in the sm_103a/sm_100a passes. The
// baseline compute_103 target gets SIMT fallback bodies.
#if defined(__CUDA_ARCH_FEAT_SM103_ALL) || defined(__CUDA_ARCH_FEAT_SM100_ALL) || \
    defined(__CUDA_ARCH_FEAT_SM101_ALL)
#define TC_OK 1
#else
#define TC_OK 0
#endif

// ---------------------------------------------------------------------------
// Scratch (static device globals; no runtime allocation allowed)
// ---------------------------------------------------------------------------
__device__ __align__(16) __nv_bfloat16 g_wqkv_hi[NQKV_ * C_];  // [N,K] transposed
__device__ __align__(16) __nv_bfloat16 g_wqkv_lo[NQKV_ * C_];
__device__ __align__(16) __nv_bfloat16 g_wproj_hi[C_ * C_];    // [N,K] transposed
__device__ __align__(16) __nv_bfloat16 g_wproj_lo[C_ * C_];
__device__ float g_qkv[M_ * NQKV_];        // fused projection output
__device__ float g_y[M_ * C_];             // attention output [B,T,NH*HD] fp32
// attention operands, bf16 hi/lo split
__device__ __align__(16) __nv_bfloat16 g_qs_hi[M_ * NH_ * HD_];   // [B,NH,T,HD]
__device__ __align__(16) __nv_bfloat16 g_qs_lo[M_ * NH_ * HD_];
__device__ __align__(16) __nv_bfloat16 g_ks_hi[M_ * NKV_ * HD_];  // [B,NKV,T,HD]
__device__ __align__(16) __nv_bfloat16 g_ks_lo[M_ * NKV_ * HD_];
__device__ __align__(16) __nv_bfloat16 g_vts_hi[M_ * NKV_ * HD_]; // [B,NKV,HD,T]
__device__ __align__(16) __nv_bfloat16 g_vts_lo[M_ * NKV_ * HD_];

// ---------------------------------------------------------------------------
// PTX helpers
// ---------------------------------------------------------------------------
__device__ __forceinline__ uint32_t smem_u32(const void* p) {
    uint32_t a;
    asm("{ .reg .u64 t; cvta.to.shared.u64 t, %1; cvt.u32.u64 %0, t; }"
        : "=r"(a) : "l"(p));
    return a;
}
__device__ __forceinline__ uint32_t elect_one() {
    uint32_t pred;
    asm volatile("{\n\t.reg .pred p;\n\telect.sync _|p, 0xFFFFFFFF;\n\t"
                 "selp.b32 %0, 1, 0, p;\n\t}" : "=r"(pred));
    return pred;
}
#define TC_ALLOC(sm, n)   asm volatile("tcgen05.alloc.cta_group::1.sync.aligned.shared::cta.b32 [%0], %1;" :: "r"(sm), "r"((uint32_t)(n)) : "memory")
#define TC_DEALLOC(t, n)  asm volatile("tcgen05.dealloc.cta_group::1.sync.aligned.b32 %0, %1;" :: "r"(t), "r"((uint32_t)(n)))
#define TC_COMMIT(mbar)   asm volatile("tcgen05.commit.cta_group::1.mbarrier::arrive::one.shared::cluster.b64 [%0];" :: "r"(mbar) : "memory")
#define TC_FENCE_AFTER()  asm volatile("tcgen05.fence::after_thread_sync;" ::: "memory")
#define TC_WAIT_LD()      asm volatile("tcgen05.wait::ld.sync.aligned;" ::: "memory")
#define MBAR_INIT(sm, n)  asm volatile("mbarrier.init.shared.b64 [%0], %1;" :: "r"(sm), "r"((uint32_t)(n)) : "memory")
#define FENCE_ASYNC()     asm volatile("fence.proxy.async.shared::cta;" ::: "memory")
#define CP_ASYNC16(dst, src) asm volatile("cp.async.cg.shared.global [%0], [%1], 16;" :: "r"(dst), "l"(src) : "memory")
#define CP_COMMIT()       asm volatile("cp.async.commit_group;" ::: "memory")
#define CP_WAIT0()        asm volatile("cp.async.wait_group 0;" ::: "memory")

__device__ __forceinline__ void mbar_wait(uint32_t mbar, uint32_t parity) {
    asm volatile(
        "{\n\t.reg .pred P;\n\t"
        "W%=:\n\t"
        "mbarrier.try_wait.parity.acquire.cta.shared::cta.b64 P, [%0], %1, 0x989680;\n\t"
        "@P bra D%=;\n\t"
        "bra W%=;\n\t"
        "D%=:\n\t}"
        :: "r"(mbar), "r"(parity) : "memory");
}

#if TC_OK
// SS-mode bf16 MMA, cta_group::1, fp32 accum
__device__ __forceinline__ void mma_f16_ss(uint32_t d, uint64_t a, uint64_t b,
                                           uint32_t idesc, uint32_t en) {
    asm volatile(
        "{\n\t.reg .pred p;\n\t"
        "setp.ne.u32 p, %4, 0;\n\t"
        "tcgen05.mma.cta_group::1.kind::f16 [%0], %1, %2, %3, {%5, %5, %5, %5}, p;\n\t"
        "}"
        :: "r"(d), "l"(a), "l"(b), "r"(idesc), "r"(en), "r"(0u)
        : "memory");
}

#define LDTM_X32(r, addr) \
    asm volatile( \
        "tcgen05.ld.sync.aligned.32x32b.x32.b32 " \
        "{%0, %1, %2, %3, %4, %5, %6, %7, " \
        " %8, %9, %10, %11, %12, %13, %14, %15, " \
        " %16, %17, %18, %19, %20, %21, %22, %23, " \
        " %24, %25, %26, %27, %28, %29, %30, %31}, [%32];" \
        : "=r"((r)[0]),  "=r"((r)[1]),  "=r"((r)[2]),  "=r"((r)[3]), \
          "=r"((r)[4]),  "=r"((r)[5]),  "=r"((r)[6]),  "=r"((r)[7]), \
          "=r"((r)[8]),  "=r"((r)[9]),  "=r"((r)[10]), "=r"((r)[11]), \
          "=r"((r)[12]), "=r"((r)[13]), "=r"((r)[14]), "=r"((r)[15]), \
          "=r"((r)[16]), "=r"((r)[17]), "=r"((r)[18]), "=r"((r)[19]), \
          "=r"((r)[20]), "=r"((r)[21]), "=r"((r)[22]), "=r"((r)[23]), \
          "=r"((r)[24]), "=r"((r)[25]), "=r"((r)[26]), "=r"((r)[27]), \
          "=r"((r)[28]), "=r"((r)[29]), "=r"((r)[30]), "=r"((r)[31]) \
        : "r"(addr))
#endif  // TC_OK

// 64-bit SMEM descriptor: SW128, version=1 (Blackwell), LBO=1, SBO=64
static __device__ __forceinline__ uint64_t smem_desc_sw128(uint32_t addr) {
    const uint64_t base =
        (uint64_t(2)  << 61) | (uint64_t(1) << 46) |
        (uint64_t(64) << 32) | (uint64_t(1) << 16);
    return base | ((uint64_t)(addr >> 4) & 0x3FFF);
}
#define SW128(off) ((off) ^ (((off) >> 3) & 0x70))

// idesc: dtype=F32, atype=BF16, btype=BF16 (K-major both)
#define GEMM_IDESC ((1u << 4) | (1u << 7) | (1u << 10) | ((128u / 8) << 17) | ((128u / 16) << 24))
#define ATT_IDESC  ((1u << 4) | (1u << 7) | (1u << 10) | ((64u / 8) << 17) | ((128u / 16) << 24))

__device__ __forceinline__ uint32_t b2u(__nv_bfloat162 v) {
    return *(uint32_t*)&v;
}

// ---------------------------------------------------------------------------
// Combined weight transpose + hi/lo split.
// grid (80, 32): blockIdx.x selects col-tile across {Wq:32, Wk:8, Wv:8, Wproj:32}
// ---------------------------------------------------------------------------
__global__ __launch_bounds__(256) void transpose_split_all(
    const float* __restrict__ Wq, const float* __restrict__ Wk,
    const float* __restrict__ Wv, const float* __restrict__ Wp) {
    __shared__ float t[32][33];
    const int ct = blockIdx.x;
    const float* W;
    __nv_bfloat16 *hi, *lo;
    int Ncols, nb;
    if (ct < 32)      { W = Wq; hi = g_wqkv_hi;                     lo = g_wqkv_lo;                     Ncols = 1024; nb = ct * 32; }
    else if (ct < 40) { W = Wk; hi = g_wqkv_hi + (size_t)1024 * C_; lo = g_wqkv_lo + (size_t)1024 * C_; Ncols = 256;  nb = (ct - 32) * 32; }
    else if (ct < 48) { W = Wv; hi = g_wqkv_hi + (size_t)1280 * C_; lo = g_wqkv_lo + (size_t)1280 * C_; Ncols = 256;  nb = (ct - 40) * 32; }
    else              { W = Wp; hi = g_wproj_hi;                    lo = g_wproj_lo;                    Ncols = 1024; nb = (ct - 48) * 32; }
    const int kb = blockIdx.y * 32;
    const int tx = threadIdx.x, ty = threadIdx.y;
#pragma unroll
    for (int j = 0; j < 32; j += 8)
        t[ty + j][tx] = W[(size_t)(kb + ty + j) * Ncols + nb + tx];
    __syncthreads();
#pragma unroll
    for (int j = 0; j < 32; j += 8) {
        float v = t[tx][ty + j];
        __nv_bfloat16 h = __float2bfloat16(v);
        size_t o = (size_t)(nb + ty + j) * C_ + kb + tx;
        hi[o] = h;
        lo[o] = __float2bfloat16(v - __bfloat162float(h));
    }
}

// ---------------------------------------------------------------------------
// Split-bf16 GEMM: C[M,N] = A[M,K] . Bt[N,K]^T  (fp32-accurate)
// A fp32, split in-register during smem fill. Unchanged (passed rounds 7-9).
// ---------------------------------------------------------------------------
#define KCHUNK   64
#define NCHUNKS  (C_ / KCHUNK)           // 16
#define BUFSZ    16384                   // 128 rows x 128 bytes
#define STAGESZ  (4 * BUFSZ)             // Ahi | Alo | Bhi | Blo
#define GEMM_SMEM (2048 + 2 * STAGESZ)

__global__ __launch_bounds__(256) void gemm_split(
    const float* __restrict__ A,
    const __nv_bfloat16* __restrict__ Bhi, const __nv_bfloat16* __restrict__ Blo,
    float* __restrict__ C, int N) {
#if TC_OK
    extern __shared__ char smem[];
    const uint32_t sb = smem_u32(smem);
    const uint32_t ab = (sb + 1024 + 1023) & 0xFFFFFC00u;
    char* smab = smem + (ab - sb);
    const int tid = threadIdx.x;
    const int wid = tid >> 5;
    const int lane = tid & 31;
    const int bm = blockIdx.y * 128;
    const int bn = blockIdx.x * 128;
    const int K = C_;

    if (wid == 0) TC_ALLOC(sb, 128);
    if (tid == 0) { MBAR_INIT(sb + 8, 1); MBAR_INIT(sb + 16, 1); }
    __syncthreads();
    uint32_t tmem;
    asm volatile("ld.shared.b32 %0, [%1];" : "=r"(tmem) : "r"(sb));

#define LOAD_CHUNK(kc, s)                                                     \
    do {                                                                      \
        const int k0 = (kc) * KCHUNK;                                         \
        char* st = smab + (s) * STAGESZ;                                      \
        _Pragma("unroll")                                                     \
        for (int v = 0; v < 4; v++) {                                         \
            int idx = tid + v * 256;                                          \
            int r = idx >> 3, c8 = idx & 7;                                   \
            uint32_t off = SW128((uint32_t)(r * 128 + c8 * 16));              \
            const float* ap = A + (size_t)(bm + r) * K + k0 + c8 * 8;         \
            float4 a0 = *(const float4*)ap;                                   \
            float4 a1 = *(const float4*)(ap + 4);                             \
            __nv_bfloat162 h0 = __floats2bfloat162_rn(a0.x, a0.y);            \
            __nv_bfloat162 h1 = __floats2bfloat162_rn(a0.z, a0.w);            \
            __nv_bfloat162 h2 = __floats2bfloat162_rn(a1.x, a1.y);            \
            __nv_bfloat162 h3 = __floats2bfloat162_rn(a1.z, a1.w);            \
            __nv_bfloat162 l0 = __floats2bfloat162_rn(                        \
                a0.x - __bfloat162float(h0.x), a0.y - __bfloat162float(h0.y));\
            __nv_bfloat162 l1 = __floats2bfloat162_rn(                        \
                a0.z - __bfloat162float(h1.x), a0.w - __bfloat162float(h1.y));\
            __nv_bfloat162 l2 = __floats2bfloat162_rn(                        \
                a1.x - __bfloat162float(h2.x), a1.y - __bfloat162float(h2.y));\
            __nv_bfloat162 l3 = __floats2bfloat162_rn(                        \
                a1.z - __bfloat162float(h3.x), a1.w - __bfloat162float(h3.y));\
            uint4 hv = make_uint4(b2u(h0), b2u(h1), b2u(h2), b2u(h3));        \
            uint4 lv = make_uint4(b2u(l0), b2u(l1), b2u(l2), b2u(l3));        \
            *(uint4*)(st + off)         = hv;                                 \
            *(uint4*)(st + BUFSZ + off) = lv;                                 \
            size_t gb = (size_t)(bn + r) * K + k0 + c8 * 8;                   \
            *(uint4*)(st + 2 * BUFSZ + off) = *(const uint4*)(Bhi + gb);      \
            *(uint4*)(st + 3 * BUFSZ + off) = *(const uint4*)(Blo + gb);      \
        }                                                                     \
    } while (0)

    LOAD_CHUNK(0, 0);
    int p0 = 0, p1 = 0;

    for (int i = 0; i < NCHUNKS; i++) {
        const int s = i & 1;
        __syncthreads();
        if (wid == 0) {
            FENCE_ASYNC();
            if (elect_one()) {
                uint32_t base = ab + s * STAGESZ;
                uint64_t dah = smem_desc_sw128(base);
                uint64_t dal = smem_desc_sw128(base + BUFSZ);
                uint64_t dbh = smem_desc_sw128(base + 2 * BUFSZ);
                uint64_t dbl = smem_desc_sw128(base + 3 * BUFSZ);
#pragma unroll
                for (int kk = 0; kk < 4; kk++)
                    mma_f16_ss(tmem, dah + kk * 2, dbh + kk * 2, GEMM_IDESC,
                               (i > 0) || (kk > 0));
#pragma unroll
                for (int kk = 0; kk < 4; kk++)
                    mma_f16_ss(tmem, dah + kk * 2, dbl + kk * 2, GEMM_IDESC, 1);
#pragma unroll
                for (int kk = 0; kk < 4; kk++)
                    mma_f16_ss(tmem, dal + kk * 2, dbh + kk * 2, GEMM_IDESC, 1);
                TC_COMMIT(sb + 8 + s * 8);
            }
        }
        if (i + 1 < NCHUNKS) {
            const int s2 = (i + 1) & 1;
            if (i >= 1) {
                if (s2 == 0) { mbar_wait(sb + 8,  p0 & 1); p0++; }
                else         { mbar_wait(sb + 16, p1 & 1); p1++; }
            }
            LOAD_CHUNK(i + 1, s2);
        }
    }
    {
        const int sl = (NCHUNKS - 1) & 1;
        if (sl == 0) mbar_wait(sb + 8, p0 & 1);
        else         mbar_wait(sb + 16, p1 & 1);
    }
    TC_FENCE_AFTER();

    {
        const int sp = wid & 3;
        const int colbase = (wid >> 2) * 64;
        const uint32_t wo = (uint32_t)sp << 21;
        uint32_t d0[32], d1[32];
        LDTM_X32(d0, tmem + wo + colbase);
        LDTM_X32(d1, tmem + wo + colbase + 32);
        TC_WAIT_LD();
        const int row = bm + sp * 32 + lane;
        float* dst = C + (size_t)row * N + bn + colbase;
#pragma unroll
        for (int c = 0; c < 32; c += 4) {
            *(float4*)(dst + c) = make_float4(
                __uint_as_float(d0[c]), __uint_as_float(d0[c + 1]),
                __uint_as_float(d0[c + 2]), __uint_as_float(d0[c + 3]));
            *(float4*)(dst + 32 + c) = make_float4(
                __uint_as_float(d1[c]), __uint_as_float(d1[c + 1]),
                __uint_as_float(d1[c + 2]), __uint_as_float(d1[c + 3]));
        }
    }
    __syncthreads();
    if (wid == 0) TC_DEALLOC(tmem, 128);
#undef LOAD_CHUNK

#else  // SIMT fallback
    __shared__ float As[8][128];
    __shared__ float Bs[8][128];
    const int tid = threadIdx.x;
    const int bm = blockIdx.y * 128;
    const int bn = blockIdx.x * 128;
    const int K = C_;
    const int ldRow = tid >> 1;
    const int ldK   = (tid & 1) * 4;
    const int ri = (tid >> 4) * 4;
    const int ci = (tid & 15) * 4;

    float acc[8][8];
#pragma unroll
    for (int i = 0; i < 8; i++)
#pragma unroll
        for (int j = 0; j < 8; j++) acc[i][j] = 0.f;

    for (int k0 = 0; k0 < K; k0 += 8) {
#pragma unroll
        for (int c = 0; c < 4; c++) {
            size_t ga = (size_t)(bm + ldRow) * K + k0 + ldK + c;
            size_t gb = (size_t)(bn + ldRow) * K + k0 + ldK + c;
            As[ldK + c][ldRow] = A[ga];
            Bs[ldK + c][ldRow] = __bfloat162float(Bhi[gb]) + __bfloat162float(Blo[gb]);
        }
        __syncthreads();
#pragma unroll
        for (int kk = 0; kk < 8; kk++) {
            float ar[8], br[8];
#pragma unroll
            for (int i = 0; i < 4; i++) {
                ar[i] = As[kk][ri + i];
                ar[i + 4] = As[kk][ri + 64 + i];
                br[i] = Bs[kk][ci + i];
                br[i + 4] = Bs[kk][ci + 64 + i];
            }
#pragma unroll
            for (int i = 0; i < 8; i++)
#pragma unroll
                for (int j = 0; j < 8; j++) acc[i][j] += ar[i] * br[j];
        }
        __syncthreads();
    }
#pragma unroll
    for (int ib = 0; ib < 2; ib++)
#pragma unroll
        for (int i = 0; i < 4; i++) {
            int row = bm + ib * 64 + ri + i;
#pragma unroll
            for (int jb = 0; jb < 2; jb++)
#pragma unroll
                for (int j = 0; j < 4; j++)
                    C[(size_t)row * N + bn + jb * 64 + ci + j] =
                        acc[ib * 4 + i][jb * 4 + j];
        }
#endif
}

// ---------------------------------------------------------------------------
// Per-token post-process (unchanged).
// ---------------------------------------------------------------------------
__global__ __launch_bounds__(256) void postproc(
    const float* __restrict__ x, const float* __restrict__ ve,
    const float* __restrict__ cosb, const float* __restrict__ sinb,
    const float* __restrict__ Wgate) {
    const int bt = blockIdx.x;
    const int b = bt / T_, t = bt % T_;
    const int tid = threadIdx.x;
    const int lane = tid & 31, w = tid >> 5;
    __shared__ float s_gate[NKV_];

    if (w < NKV_) {
        float p = x[(size_t)bt * C_ + lane] * Wgate[lane * NKV_ + w];
#pragma unroll
        for (int o = 16; o; o >>= 1) p += __shfl_xor_sync(0xffffffffu, p, o);
        if (lane == 0) s_gate[w] = 2.0f / (1.0f + expf(-p));
    }
    __syncthreads();

    const float c = cosb[t * (HD_ / 2) + lane];
    const float s = sinb[t * (HD_ / 2) + lane];
    const float* qkvrow = g_qkv + (size_t)bt * NQKV_;
    for (int row = w; row < NH_ + NKV_; row += 8) {
        const float* src;
        __nv_bfloat16 *dhi, *dlo;
        if (row < NH_) {
            src = qkvrow + row * HD_;
            size_t base = ((size_t)(b * NH_ + row) * T_ + t) * HD_;
            dhi = g_qs_hi + base;
            dlo = g_qs_lo + base;
        } else {
            int kh = row - NH_;
            src = qkvrow + 1024 + kh * HD_;
            size_t base = ((size_t)(b * NKV_ + kh) * T_ + t) * HD_;
            dhi = g_ks_hi + base;
            dlo = g_ks_lo + base;
        }
        float x1 = src[lane], x2 = src[lane + 32];
        float o1 = x1 * c + x2 * s;
        float o2 = -x1 * s + x2 * c;
        float sq = o1 * o1 + o2 * o2;
#pragma unroll
        for (int o = 16; o; o >>= 1) sq += __shfl_xor_sync(0xffffffffu, sq, o);
        float scale = rsqrtf(sq * (1.0f / HD_) + 1.1920929e-7f);
        float v1 = o1 * scale, v2 = o2 * scale;
        __nv_bfloat16 h1 = __float2bfloat16(v1);
        __nv_bfloat16 h2 = __float2bfloat16(v2);
        dhi[lane] = h1;
        dhi[lane + 32] = h2;
        dlo[lane] = __float2bfloat16(v1 - __bfloat162float(h1));
        dlo[lane + 32] = __float2bfloat16(v2 - __bfloat162float(h2));
    }

    {
        int h = tid >> 6, d = tid & 63;
        float val = qkvrow[1280 + tid] +
                    s_gate[h] * ve[(size_t)bt * (NKV_ * HD_) + tid];
        size_t o = ((size_t)(b * NKV_ + h) * HD_ + d) * T_ + t;  // transposed
        __nv_bfloat16 hh = __float2bfloat16(val);
        g_vts_hi[o] = hh;
        g_vts_lo[o] = __float2bfloat16(val - __bfloat162float(hh));
    }
}

// ---------------------------------------------------------------------------
// tcgen05 sliding-window flash attention, static-max softmax, SOFTWARE
// PIPELINED: double-buffered S in TMEM (cols 0-63 / 64-127), PV accumulator
// at cols 128-191; double-buffered K/V/P in smem with cp.async prefetch.
// Issue order per tile jt: [softmax jt] -> PV(jt) -> S(jt+1) -> commit.
// In-order tcgen05 completion: waiting S(jt) implies PV(jt-1) done, so the
// buffer reuse (distance 2) and P overwrite are all guarded by ONE wait.
// grid = (T/128, NH, B), 256 threads, 1 CTA/SM (smem ~167KB).
// ---------------------------------------------------------------------------
#define AOFF_RED 0         // redsum[256] f32 (1KB)
#define AOFF_Q   2048      // Qhi 16K | Qlo 16K                 (end 34816)
#define AOFF_K   34816     // buf s: {Khi 8K | Klo 8K} x2       (end 67584)
#define AOFF_V   67584     // buf s: {Vhi 8K | Vlo 8K} x2       (end 100352)
#define AOFF_P   100352    // buf s: {Phi 16K | Plo 16K} x2     (end 165888)
#define KBUF(s)  (AOFF_K + (s) * 16384)
#define VBUF(s)  (AOFF_V + (s) * 16384)
#define PBUF(s)  (AOFF_P + (s) * 32768)
#define ATT_SMEM 168960    // 1024 hdr + align slack + 165888

__global__ __launch_bounds__(256, 1) void attn_tc(const int* __restrict__ winp) {
#if TC_OK
    extern __shared__ char smem[];
    const uint32_t sb = smem_u32(smem);
    const uint32_t ab = (sb + 1024 + 1023) & 0xFFFFFC00u;
    char* abp = smem + (ab - sb);

    int win = winp[0];
    if (win <= 0 || win > T_) win = 1024;
    const int qt = blockIdx.x, h = blockIdx.y, b = blockIdx.z;
    const int kvh = h >> 2;
    const int q0 = qt * 128;
    const int tid = threadIdx.x, w = tid >> 5, lane = tid & 31;
    const int sp = w & 3;              // TMEM subpartition
    const int hf = w >> 2;             // key half (0 or 1)
    const int kbase = hf * 32;
    const int r = sp * 32 + lane;      // q row within tile
    const int qg = q0 + r;             // global q index

    float* redsum = (float*)(abp + AOFF_RED);

    if (w == 0) TC_ALLOC(sb, 256);
    if (tid == 0) MBAR_INIT(sb + 8, 1);
    __syncthreads();
    uint32_t tmem;
    asm volatile("ld.shared.b32 %0, [%1];" : "=r"(tmem) : "r"(sb));

    const __nv_bfloat16* qh  = g_qs_hi  + ((size_t)(b * NH_ + h) * T_ + q0) * HD_;
    const __nv_bfloat16* qlo = g_qs_lo  + ((size_t)(b * NH_ + h) * T_ + q0) * HD_;
    const __nv_bfloat16* kh  = g_ks_hi  + ((size_t)(b * NKV_ + kvh) * T_) * HD_;
    const __nv_bfloat16* kl  = g_ks_lo  + ((size_t)(b * NKV_ + kvh) * T_) * HD_;
    const __nv_bfloat16* vth = g_vts_hi + ((size_t)(b * NKV_ + kvh) * HD_) * T_;
    const __nv_bfloat16* vtl = g_vts_lo + ((size_t)(b * NKV_ + kvh) * HD_) * T_;

    int j0s = q0 - win;
    if (j0s < 0) j0s = 0;
    const int jt0 = j0s >> 6;
    const int jt1 = (q0 + 127) >> 6;

    // per-thread K/V load coordinates: 512 x 16B per component, 2 per thread
    const int krr0 = tid >> 3, kc8 = (tid & 7) * 8;          // rows 0..31
    const uint32_t koff0 = SW128((uint32_t)(krr0 * 128 + kc8 * 2));
    const uint32_t koff1 = SW128((uint32_t)((krr0 + 32) * 128 + kc8 * 2));

#define LOAD_KV(jt, s)                                                        \
    do {                                                                      \
        const int j0_ = (jt) * 64;                                            \
        const __nv_bfloat16* k0p = kh  + (size_t)(j0_ + krr0) * 64 + kc8;     \
        const __nv_bfloat16* k1p = kh  + (size_t)(j0_ + krr0 + 32) * 64 + kc8;\
        const __nv_bfloat16* l0p = kl  + (size_t)(j0_ + krr0) * 64 + kc8;     \
        const __nv_bfloat16* l1p = kl  + (size_t)(j0_ + krr0 + 32) * 64 + kc8;\
        const __nv_bfloat16* v0p = vth + (size_t)krr0 * T_ + j0_ + kc8;       \
        const __nv_bfloat16* v1p = vth + (size_t)(krr0 + 32) * T_ + j0_ + kc8;\
        const __nv_bfloat16* w0p = vtl + (size_t)krr0 * T_ + j0_ + kc8;       \
        const __nv_bfloat16* w1p = vtl + (size_t)(krr0 + 32) * T_ + j0_ + kc8;\
        uint32_t kb_ = ab + KBUF(s), vb_ = ab + VBUF(s);                      \
        CP_ASYNC16(kb_ + koff0, k0p);                                         \
        CP_ASYNC16(kb_ + koff1, k1p);                                         \
        CP_ASYNC16(kb_ + 8192 + koff0, l0p);                                  \
        CP_ASYNC16(kb_ + 8192 + koff1, l1p);                                  \
        CP_ASYNC16(vb_ + koff0, v0p);                                         \
        CP_ASYNC16(vb_ + koff1, v1p);                                         \
        CP_ASYNC16(vb_ + 8192 + koff0, w0p);                                  \
        CP_ASYNC16(vb_ + 8192 + koff1, w1p);                                  \
        CP_COMMIT();                                                          \
    } while (0)

    // ---- prologue: Q plain loads; K/V(jt0) via cp.async; issue S(jt0) ----
#pragma unroll
    for (int v = 0; v < 4; v++) {
        int idx = tid + v * 256;
        int rr = idx >> 3, c8 = idx & 7;
        uint32_t off = SW128((uint32_t)(rr * 128 + c8 * 16));
        *(uint4*)(abp + AOFF_Q + off)         = *(const uint4*)(qh  + rr * 64 + c8 * 8);
        *(uint4*)(abp + AOFF_Q + 16384 + off) = *(const uint4*)(qlo + rr * 64 + c8 * 8);
    }
    LOAD_KV(jt0, jt0 & 1);
    CP_WAIT0();
    __syncthreads();
    const uint64_t dQh = smem_desc_sw128(ab + AOFF_Q);
    const uint64_t dQl = smem_desc_sw128(ab + AOFF_Q + 16384);
    if (w == 0) {
        FENCE_ASYNC();
        if (elect_one()) {
            uint64_t dKh = smem_desc_sw128(ab + KBUF(jt0 & 1));
            uint64_t dKl = smem_desc_sw128(ab + KBUF(jt0 & 1) + 8192);
            uint32_t sdst = tmem + (jt0 & 1) * 64;
#pragma unroll
            for (int kk = 0; kk < 4; kk++)
                mma_f16_ss(sdst, dQh + kk * 2, dKh + kk * 2, ATT_IDESC, kk > 0);
#pragma unroll
            for (int kk = 0; kk < 4; kk++)
                mma_f16_ss(sdst, dQh + kk * 2, dKl + kk * 2, ATT_IDESC, 1);
#pragma unroll
            for (int kk = 0; kk < 4; kk++)
                mma_f16_ss(sdst, dQl + kk * 2, dKh + kk * 2, ATT_IDESC, 1);
            TC_COMMIT(sb + 8);
        }
    }

    float l_loc = 0.f;
    int ps = 0;

    for (int jt = jt0; jt <= jt1; jt++) {
        const int sbuf = jt & 1;
        const int j0 = jt * 64;
        // S(jt) done -> PV(jt-1) and all older MMAs done (in-order commits)
        mbar_wait(sb + 8, ps & 1); ps++;
        TC_FENCE_AFTER();
        // prefetch K/V(jt+1) into the now-free buffers (readers finished)
        if (jt < jt1) LOAD_KV(jt + 1, sbuf ^ 1);
        // ---- static-max softmax on S(jt): p = exp(s/8 - 8), masked -> 0 ----
        uint32_t sr[32];
        LDTM_X32(sr, tmem + ((uint32_t)sp << 21) + sbuf * 64 + kbase);
        TC_WAIT_LD();
        float p[32];
#pragma unroll
        for (int i = 0; i < 32; i++) {
            int jg = j0 + kbase + i;
            bool ok = (jg <= qg) && (jg >= qg - win);
            float e = __expf(__uint_as_float(sr[i]) * 0.125f - 8.0f);
            p[i] = ok ? e : 0.f;
            l_loc += p[i];
        }
        // write P(jt) hi/lo into P buffer sbuf (prev user PV(jt-2) done)
#pragma unroll
        for (int i = 0; i < 16; i++) {
            float pa = p[2 * i], pb = p[2 * i + 1];
            __nv_bfloat162 hh = __floats2bfloat162_rn(pa, pb);
            float la = pa - __bfloat162float(hh.x);
            float lb = pb - __bfloat162float(hh.y);
            __nv_bfloat162 ll = __floats2bfloat162_rn(la, lb);
            uint32_t boff = SW128((uint32_t)(r * 128 + (kbase + 2 * i) * 2));
            *(uint32_t*)(abp + PBUF(sbuf) + boff)         = b2u(hh);
            *(uint32_t*)(abp + PBUF(sbuf) + 16384 + boff) = b2u(ll);
        }
        CP_WAIT0();          // K/V(jt+1) landed
        __syncthreads();     // P(jt) + K/V(jt+1) visible block-wide
        // issue PV(jt) [accum] then S(jt+1); one commit covers both
        if (w == 0) {
            FENCE_ASYNC();
            if (elect_one()) {
                uint64_t dPh = smem_desc_sw128(ab + PBUF(sbuf));
                uint64_t dPl = smem_desc_sw128(ab + PBUF(sbuf) + 16384);
                uint64_t dVh = smem_desc_sw128(ab + VBUF(sbuf));
                uint64_t dVl = smem_desc_sw128(ab + VBUF(sbuf) + 8192);
#pragma unroll
                for (int kk = 0; kk < 4; kk++)
                    mma_f16_ss(tmem + 128, dPh + kk * 2, dVh + kk * 2, ATT_IDESC,
                               (jt > jt0) || (kk > 0));
#pragma unroll
                for (int kk = 0; kk < 4; kk++)
                    mma_f16_ss(tmem + 128, dPh + kk * 2, dVl + kk * 2, ATT_IDESC, 1);
#pragma unroll
                for (int kk = 0; kk < 4; kk++)
                    mma_f16_ss(tmem + 128, dPl + kk * 2, dVh + kk * 2, ATT_IDESC, 1);
                if (jt < jt1) {
                    uint64_t dKh = smem_desc_sw128(ab + KBUF(sbuf ^ 1));
                    uint64_t dKl = smem_desc_sw128(ab + KBUF(sbuf ^ 1) + 8192);
                    uint32_t sdst = tmem + (sbuf ^ 1) * 64;
#pragma unroll
                    for (int kk = 0; kk < 4; kk++)
                        mma_f16_ss(sdst, dQh + kk * 2, dKh + kk * 2, ATT_IDESC, kk > 0);
#pragma unroll
                    for (int kk = 0; kk < 4; kk++)
                        mma_f16_ss(sdst, dQh + kk * 2, dKl + kk * 2, ATT_IDESC, 1);
#pragma unroll
                    for (int kk = 0; kk < 4; kk++)
                        mma_f16_ss(sdst, dQl + kk * 2, dKh + kk * 2, ATT_IDESC, 1);
                }
                TC_COMMIT(sb + 8);
            }
        }
    }
    // drain final commit (covers PV(jt1)), combine l halves, write O
    mbar_wait(sb + 8, ps & 1);
    TC_FENCE_AFTER();
    redsum[r * 2 + hf] = l_loc;
    __syncthreads();
    const float l = redsum[r * 2] + redsum[r * 2 + 1];
    uint32_t pr[32];
    LDTM_X32(pr, tmem + ((uint32_t)sp << 21) + 128 + kbase);
    TC_WAIT_LD();
    {
        const float inv = 1.0f / l;
        float* dst = g_y + ((size_t)(b * T_ + qg)) * C_ + h * 64 + kbase;
#pragma unroll
        for (int i = 0; i < 32; i += 4)
            *(float4*)(dst + i) = make_float4(
                __uint_as_float(pr[i]) * inv, __uint_as_float(pr[i + 1]) * inv,
                __uint_as_float(pr[i + 2]) * inv, __uint_as_float(pr[i + 3]) * inv);
    }
    __syncthreads();
    if (w == 0) TC_DEALLOC(tmem, 256);
#undef LOAD_KV

#else  // ---------------- SIMT fallback (baseline target, never run) --------
    const int qt = blockIdx.x, h = blockIdx.y, b = blockIdx.z;
    const int kvh = h >> 2;
    int win = winp[0];
    if (win <= 0 || win > T_) win = 1024;
    const int tid = threadIdx.x;
    if (tid < 128) {
        const int qg = qt * 128 + tid;
        const __nv_bfloat16* qh  = g_qs_hi + ((size_t)(b * NH_ + h) * T_ + qg) * HD_;
        const __nv_bfloat16* qlo = g_qs_lo + ((size_t)(b * NH_ + h) * T_ + qg) * HD_;
        float q[64];
        for (int d = 0; d < 64; d++)
            q[d] = __bfloat162float(qh[d]) + __bfloat162float(qlo[d]);
        const __nv_bfloat16* kh  = g_ks_hi  + ((size_t)(b * NKV_ + kvh) * T_) * HD_;
        const __nv_bfloat16* kl  = g_ks_lo  + ((size_t)(b * NKV_ + kvh) * T_) * HD_;
        const __nv_bfloat16* vth = g_vts_hi + ((size_t)(b * NKV_ + kvh) * HD_) * T_;
        const __nv_bfloat16* vtl = g_vts_lo + ((size_t)(b * NKV_ + kvh) * HD_) * T_;
        float l = 0.f, O[64];
        for (int d = 0; d < 64; d++) O[d] = 0.f;
        int js = qg - win;
        if (js < 0) js = 0;
        for (int j = js; j <= qg; j++) {
            float s = 0.f;
            for (int d = 0; d < 64; d++)
                s += q[d] * (__bfloat162float(kh[(size_t)j * 64 + d]) +
                             __bfloat162float(kl[(size_t)j * 64 + d]));
            float p = __expf(s * 0.125f - 8.0f);
            l += p;
            for (int d = 0; d < 64; d++)
                O[d] += p * (__bfloat162float(vth[(size_t)d * T_ + j]) +
                             __bfloat162float(vtl[(size_t)d * T_ + j]));
        }
        float inv = 1.0f / l;
        float* dst = g_y + ((size_t)(b * T_ + qg)) * C_ + h * 64;
        for (int d = 0; d < 64; d++) dst[d] = O[d] * inv;
    }
#endif
}

// ---------------------------------------------------------------------------
// Launch
// ---------------------------------------------------------------------------
extern "C" void kernel_launch(void* const* d_in, const int* in_sizes, int n_in,
                              void* d_out, int out_size) {
    const float* x     = (const float*)d_in[0];
    const float* ve    = (const float*)d_in[1];
    const float* cosb  = (const float*)d_in[2];
    const float* sinb  = (const float*)d_in[3];
    const float* Wq    = (const float*)d_in[4];
    const float* Wk    = (const float*)d_in[5];
    const float* Wv    = (const float*)d_in[6];
    const float* Wproj = (const float*)d_in[7];
    const float* Wgate = (const float*)d_in[8];
    const int*   win   = (const int*)d_in[9];
    float* out = (float*)d_out;

    __nv_bfloat16 *wqkv_hi, *wqkv_lo, *wproj_hi, *wproj_lo;
    float *qkv, *yb;
    cudaGetSymbolAddress((void**)&wqkv_hi, g_wqkv_hi);
    cudaGetSymbolAddress((void**)&wqkv_lo, g_wqkv_lo);
    cudaGetSymbolAddress((void**)&wproj_hi, g_wproj_hi);
    cudaGetSymbolAddress((void**)&wproj_lo, g_wproj_lo);
    cudaGetSymbolAddress((void**)&qkv, g_qkv);
    cudaGetSymbolAddress((void**)&yb, g_y);

    cudaFuncSetAttribute(gemm_split,
                         cudaFuncAttributeMaxDynamicSharedMemorySize, GEMM_SMEM);
    cudaFuncSetAttribute(attn_tc,
                         cudaFuncAttributeMaxDynamicSharedMemorySize, ATT_SMEM);

    // 1. transpose + split all weights (one launch)
    transpose_split_all<<<dim3(80, C_ / 32), dim3(32, 8)>>>(Wq, Wk, Wv, Wproj);
    // 2. fused QKV projection (A = x fp32, split in-kernel)
    gemm_split<<<dim3(NQKV_ / 128, M_ / 128), 256, GEMM_SMEM>>>(
        x, wqkv_hi, wqkv_lo, qkv, NQKV_);
    // 3. gate + RoPE + RMSNorm + bf16 split + layouts
    postproc<<<M_, 256>>>(x, ve, cosb, sinb, Wgate);
    // 4. pipelined tensor-core attention, static-max softmax, fp32 y out
    attn_tc<<<dim3(T_ / 128, NH_, B_), 256, ATT_SMEM>>>(win);
    // 5. output projection (A = y fp32, split in-kernel)
    gemm_split<<<dim3(C_ / 128, M_ / 128), 256, GEMM_SMEM>>>(
        yb, wproj_hi, wproj_lo, out, C_);
}

// round 12
// speedup vs baseline: 5.7875x; 1.0700x over previous
#include <cuda_runtime.h>
#include <cuda_bf16.h>
#include <math.h>
#include <stdint.h>

// Problem constants (fixed by the reference)
#define B_  2
#define T_  2048
#define C_  1024
#define NH_ 16
#define NKV_ 4
#define HD_ 64
#define VEC_ 32
#define M_  (B_ * T_)      // 4096 token rows
#define NQKV_ 1536         // fused q(1024) | k(256) | v(256) columns

// tcgen05 is arch-conditional: only in the sm_103a/sm_100a passes. The
// baseline compute_103 target gets SIMT fallback bodies.
#if defined(__CUDA_ARCH_FEAT_SM103_ALL) || defined(__CUDA_ARCH_FEAT_SM100_ALL) || \
    defined(__CUDA_ARCH_FEAT_SM101_ALL)
#define TC_OK 1
#else
#define TC_OK 0
#endif

// ---------------------------------------------------------------------------
// Scratch (static device globals; no runtime allocation allowed)
// ---------------------------------------------------------------------------
__device__ __align__(16) __nv_bfloat16 g_wqkv_hi[NQKV_ * C_];  // [N,K] transposed
__device__ __align__(16) __nv_bfloat16 g_wqkv_lo[NQKV_ * C_];
__device__ __align__(16) __nv_bfloat16 g_wproj_hi[C_ * C_];    // [N,K] transposed
__device__ __align__(16) __nv_bfloat16 g_wproj_lo[C_ * C_];
__device__ float g_qkv[M_ * NQKV_];        // fused projection output
__device__ float g_y[M_ * C_];             // attention output [B,T,NH*HD] fp32
// attention operands, bf16 hi/lo split
__device__ __align__(16) __nv_bfloat16 g_qs_hi[M_ * NH_ * HD_];   // [B,NH,T,HD]
__device__ __align__(16) __nv_bfloat16 g_qs_lo[M_ * NH_ * HD_];
__device__ __align__(16) __nv_bfloat16 g_ks_hi[M_ * NKV_ * HD_];  // [B,NKV,T,HD]
__device__ __align__(16) __nv_bfloat16 g_ks_lo[M_ * NKV_ * HD_];
__device__ __align__(16) __nv_bfloat16 g_vts_hi[M_ * NKV_ * HD_]; // [B,NKV,HD,T]
__device__ __align__(16) __nv_bfloat16 g_vts_lo[M_ * NKV_ * HD_];

// ---------------------------------------------------------------------------
// PTX helpers
// ---------------------------------------------------------------------------
__device__ __forceinline__ uint32_t smem_u32(const void* p) {
    uint32_t a;
    asm("{ .reg .u64 t; cvta.to.shared.u64 t, %1; cvt.u32.u64 %0, t; }"
        : "=r"(a) : "l"(p));
    return a;
}
__device__ __forceinline__ uint32_t elect_one() {
    uint32_t pred;
    asm volatile("{\n\t.reg .pred p;\n\telect.sync _|p, 0xFFFFFFFF;\n\t"
                 "selp.b32 %0, 1, 0, p;\n\t}" : "=r"(pred));
    return pred;
}
#define TC_ALLOC(sm, n)   asm volatile("tcgen05.alloc.cta_group::1.sync.aligned.shared::cta.b32 [%0], %1;" :: "r"(sm), "r"((uint32_t)(n)) : "memory")
#define TC_DEALLOC(t, n)  asm volatile("tcgen05.dealloc.cta_group::1.sync.aligned.b32 %0, %1;" :: "r"(t), "r"((uint32_t)(n)))
#define TC_COMMIT(mbar)   asm volatile("tcgen05.commit.cta_group::1.mbarrier::arrive::one.shared::cluster.b64 [%0];" :: "r"(mbar) : "memory")
#define TC_FENCE_AFTER()  asm volatile("tcgen05.fence::after_thread_sync;" ::: "memory")
#define TC_WAIT_LD()      asm volatile("tcgen05.wait::ld.sync.aligned;" ::: "memory")
#define MBAR_INIT(sm, n)  asm volatile("mbarrier.init.shared.b64 [%0], %1;" :: "r"(sm), "r"((uint32_t)(n)) : "memory")
#define FENCE_ASYNC()     asm volatile("fence.proxy.async.shared::cta;" ::: "memory")
#define CP_ASYNC16(dst, src) asm volatile("cp.async.cg.shared.global [%0], [%1], 16;" :: "r"(dst), "l"(src) : "memory")
#define CP_COMMIT()       asm volatile("cp.async.commit_group;" ::: "memory")
#define CP_WAIT0()        asm volatile("cp.async.wait_group 0;" ::: "memory")
#define CP_WAIT1()        asm volatile("cp.async.wait_group 1;" ::: "memory")

__device__ __forceinline__ void mbar_wait(uint32_t mbar, uint32_t parity) {
    asm volatile(
        "{\n\t.reg .pred P;\n\t"
        "W%=:\n\t"
        "mbarrier.try_wait.parity.acquire.cta.shared::cta.b64 P, [%0], %1, 0x989680;\n\t"
        "@P bra D%=;\n\t"
        "bra W%=;\n\t"
        "D%=:\n\t}"
        :: "r"(mbar), "r"(parity) : "memory");
}

#if TC_OK
// SS-mode bf16 MMA, cta_group::1, fp32 accum
__device__ __forceinline__ void mma_f16_ss(uint32_t d, uint64_t a, uint64_t b,
                                           uint32_t idesc, uint32_t en) {
    asm volatile(
        "{\n\t.reg .pred p;\n\t"
        "setp.ne.u32 p, %4, 0;\n\t"
        "tcgen05.mma.cta_group::1.kind::f16 [%0], %1, %2, %3, {%5, %5, %5, %5}, p;\n\t"
        "}"
        :: "r"(d), "l"(a), "l"(b), "r"(idesc), "r"(en), "r"(0u)
        : "memory");
}

#define LDTM_X32(r, addr) \
    asm volatile( \
        "tcgen05.ld.sync.aligned.32x32b.x32.b32 " \
        "{%0, %1, %2, %3, %4, %5, %6, %7, " \
        " %8, %9, %10, %11, %12, %13, %14, %15, " \
        " %16, %17, %18, %19, %20, %21, %22, %23, " \
        " %24, %25, %26, %27, %28, %29, %30, %31}, [%32];" \
        : "=r"((r)[0]),  "=r"((r)[1]),  "=r"((r)[2]),  "=r"((r)[3]), \
          "=r"((r)[4]),  "=r"((r)[5]),  "=r"((r)[6]),  "=r"((r)[7]), \
          "=r"((r)[8]),  "=r"((r)[9]),  "=r"((r)[10]), "=r"((r)[11]), \
          "=r"((r)[12]), "=r"((r)[13]), "=r"((r)[14]), "=r"((r)[15]), \
          "=r"((r)[16]), "=r"((r)[17]), "=r"((r)[18]), "=r"((r)[19]), \
          "=r"((r)[20]), "=r"((r)[21]), "=r"((r)[22]), "=r"((r)[23]), \
          "=r"((r)[24]), "=r"((r)[25]), "=r"((r)[26]), "=r"((r)[27]), \
          "=r"((r)[28]), "=r"((r)[29]), "=r"((r)[30]), "=r"((r)[31]) \
        : "r"(addr))
#endif  // TC_OK

// 64-bit SMEM descriptor: SW128, version=1 (Blackwell), LBO=1, SBO=64
static __device__ __forceinline__ uint64_t smem_desc_sw128(uint32_t addr) {
    const uint64_t base =
        (uint64_t(2)  << 61) | (uint64_t(1) << 46) |
        (uint64_t(64) << 32) | (uint64_t(1) << 16);
    return base | ((uint64_t)(addr >> 4) & 0x3FFF);
}
#define SW128(off) ((off) ^ (((off) >> 3) & 0x70))

// idesc: dtype=F32, atype=BF16, btype=BF16 (K-major both)
#define GEMM_IDESC ((1u << 4) | (1u << 7) | (1u << 10) | ((128u / 8) << 17) | ((128u / 16) << 24))
#define ATT_IDESC  ((1u << 4) | (1u << 7) | (1u << 10) | ((64u / 8) << 17) | ((128u / 16) << 24))

__device__ __forceinline__ uint32_t b2u(__nv_bfloat162 v) {
    return *(uint32_t*)&v;
}

// ---------------------------------------------------------------------------
// Combined weight transpose + hi/lo split.
// grid (80, 32): blockIdx.x selects col-tile across {Wq:32, Wk:8, Wv:8, Wproj:32}
// ---------------------------------------------------------------------------
__global__ __launch_bounds__(256) void transpose_split_all(
    const float* __restrict__ Wq, const float* __restrict__ Wk,
    const float* __restrict__ Wv, const float* __restrict__ Wp) {
    __shared__ float t[32][33];
    const int ct = blockIdx.x;
    const float* W;
    __nv_bfloat16 *hi, *lo;
    int Ncols, nb;
    if (ct < 32)      { W = Wq; hi = g_wqkv_hi;                     lo = g_wqkv_lo;                     Ncols = 1024; nb = ct * 32; }
    else if (ct < 40) { W = Wk; hi = g_wqkv_hi + (size_t)1024 * C_; lo = g_wqkv_lo + (size_t)1024 * C_; Ncols = 256;  nb = (ct - 32) * 32; }
    else if (ct < 48) { W = Wv; hi = g_wqkv_hi + (size_t)1280 * C_; lo = g_wqkv_lo + (size_t)1280 * C_; Ncols = 256;  nb = (ct - 40) * 32; }
    else              { W = Wp; hi = g_wproj_hi;                    lo = g_wproj_lo;                    Ncols = 1024; nb = (ct - 48) * 32; }
    const int kb = blockIdx.y * 32;
    const int tx = threadIdx.x, ty = threadIdx.y;
#pragma unroll
    for (int j = 0; j < 32; j += 8)
        t[ty + j][tx] = W[(size_t)(kb + ty + j) * Ncols + nb + tx];
    __syncthreads();
#pragma unroll
    for (int j = 0; j < 32; j += 8) {
        float v = t[tx][ty + j];
        __nv_bfloat16 h = __float2bfloat16(v);
        size_t o = (size_t)(nb + ty + j) * C_ + kb + tx;
        hi[o] = h;
        lo[o] = __float2bfloat16(v - __bfloat162float(h));
    }
}

// ---------------------------------------------------------------------------
// Split-bf16 GEMM: C[M,N] = A[M,K] . Bt[N,K]^T  (fp32-accurate)
// A fp32, split in-register during smem fill. Unchanged (passing since r7).
// ---------------------------------------------------------------------------
#define KCHUNK   64
#define NCHUNKS  (C_ / KCHUNK)           // 16
#define BUFSZ    16384                   // 128 rows x 128 bytes
#define STAGESZ  (4 * BUFSZ)             // Ahi | Alo | Bhi | Blo
#define GEMM_SMEM (2048 + 2 * STAGESZ)

__global__ __launch_bounds__(256) void gemm_split(
    const float* __restrict__ A,
    const __nv_bfloat16* __restrict__ Bhi, const __nv_bfloat16* __restrict__ Blo,
    float* __restrict__ C, int N) {
#if TC_OK
    extern __shared__ char smem[];
    const uint32_t sb = smem_u32(smem);
    const uint32_t ab = (sb + 1024 + 1023) & 0xFFFFFC00u;
    char* smab = smem + (ab - sb);
    const int tid = threadIdx.x;
    const int wid = tid >> 5;
    const int lane = tid & 31;
    const int bm = blockIdx.y * 128;
    const int bn = blockIdx.x * 128;
    const int K = C_;

    if (wid == 0) TC_ALLOC(sb, 128);
    if (tid == 0) { MBAR_INIT(sb + 8, 1); MBAR_INIT(sb + 16, 1); }
    __syncthreads();
    uint32_t tmem;
    asm volatile("ld.shared.b32 %0, [%1];" : "=r"(tmem) : "r"(sb));

#define LOAD_CHUNK(kc, s)                                                     \
    do {                                                                      \
        const int k0 = (kc) * KCHUNK;                                         \
        char* st = smab + (s) * STAGESZ;                                      \
        _Pragma("unroll")                                                     \
        for (int v = 0; v < 4; v++) {                                         \
            int idx = tid + v * 256;                                          \
            int r = idx >> 3, c8 = idx & 7;                                   \
            uint32_t off = SW128((uint32_t)(r * 128 + c8 * 16));              \
            const float* ap = A + (size_t)(bm + r) * K + k0 + c8 * 8;         \
            float4 a0 = *(const float4*)ap;                                   \
            float4 a1 = *(const float4*)(ap + 4);                             \
            __nv_bfloat162 h0 = __floats2bfloat162_rn(a0.x, a0.y);            \
            __nv_bfloat162 h1 = __floats2bfloat162_rn(a0.z, a0.w);            \
            __nv_bfloat162 h2 = __floats2bfloat162_rn(a1.x, a1.y);            \
            __nv_bfloat162 h3 = __floats2bfloat162_rn(a1.z, a1.w);            \
            __nv_bfloat162 l0 = __floats2bfloat162_rn(                        \
                a0.x - __bfloat162float(h0.x), a0.y - __bfloat162float(h0.y));\
            __nv_bfloat162 l1 = __floats2bfloat162_rn(                        \
                a0.z - __bfloat162float(h1.x), a0.w - __bfloat162float(h1.y));\
            __nv_bfloat162 l2 = __floats2bfloat162_rn(                        \
                a1.x - __bfloat162float(h2.x), a1.y - __bfloat162float(h2.y));\
            __nv_bfloat162 l3 = __floats2bfloat162_rn(                        \
                a1.z - __bfloat162float(h3.x), a1.w - __bfloat162float(h3.y));\
            uint4 hv = make_uint4(b2u(h0), b2u(h1), b2u(h2), b2u(h3));        \
            uint4 lv = make_uint4(b2u(l0), b2u(l1), b2u(l2), b2u(l3));        \
            *(uint4*)(st + off)         = hv;                                 \
            *(uint4*)(st + BUFSZ + off) = lv;                                 \
            size_t gb = (size_t)(bn + r) * K + k0 + c8 * 8;                   \
            *(uint4*)(st + 2 * BUFSZ + off) = *(const uint4*)(Bhi + gb);      \
            *(uint4*)(st + 3 * BUFSZ + off) = *(const uint4*)(Blo + gb);      \
        }                                                                     \
    } while (0)

    LOAD_CHUNK(0, 0);
    int p0 = 0, p1 = 0;

    for (int i = 0; i < NCHUNKS; i++) {
        const int s = i & 1;
        __syncthreads();
        if (wid == 0) {
            FENCE_ASYNC();
            if (elect_one()) {
                uint32_t base = ab + s * STAGESZ;
                uint64_t dah = smem_desc_sw128(base);
                uint64_t dal = smem_desc_sw128(base + BUFSZ);
                uint64_t dbh = smem_desc_sw128(base + 2 * BUFSZ);
                uint64_t dbl = smem_desc_sw128(base + 3 * BUFSZ);
#pragma unroll
                for (int kk = 0; kk < 4; kk++)
                    mma_f16_ss(tmem, dah + kk * 2, dbh + kk * 2, GEMM_IDESC,
                               (i > 0) || (kk > 0));
#pragma unroll
                for (int kk = 0; kk < 4; kk++)
                    mma_f16_ss(tmem, dah + kk * 2, dbl + kk * 2, GEMM_IDESC, 1);
#pragma unroll
                for (int kk = 0; kk < 4; kk++)
                    mma_f16_ss(tmem, dal + kk * 2, dbh + kk * 2, GEMM_IDESC, 1);
                TC_COMMIT(sb + 8 + s * 8);
            }
        }
        if (i + 1 < NCHUNKS) {
            const int s2 = (i + 1) & 1;
            if (i >= 1) {
                if (s2 == 0) { mbar_wait(sb + 8,  p0 & 1); p0++; }
                else         { mbar_wait(sb + 16, p1 & 1); p1++; }
            }
            LOAD_CHUNK(i + 1, s2);
        }
    }
    {
        const int sl = (NCHUNKS - 1) & 1;
        if (sl == 0) mbar_wait(sb + 8, p0 & 1);
        else         mbar_wait(sb + 16, p1 & 1);
    }
    TC_FENCE_AFTER();

    {
        const int sp = wid & 3;
        const int colbase = (wid >> 2) * 64;
        const uint32_t wo = (uint32_t)sp << 21;
        uint32_t d0[32], d1[32];
        LDTM_X32(d0, tmem + wo + colbase);
        LDTM_X32(d1, tmem + wo + colbase + 32);
        TC_WAIT_LD();
        const int row = bm + sp * 32 + lane;
        float* dst = C + (size_t)row * N + bn + colbase;
#pragma unroll
        for (int c = 0; c < 32; c += 4) {
            *(float4*)(dst + c) = make_float4(
                __uint_as_float(d0[c]), __uint_as_float(d0[c + 1]),
                __uint_as_float(d0[c + 2]), __uint_as_float(d0[c + 3]));
            *(float4*)(dst + 32 + c) = make_float4(
                __uint_as_float(d1[c]), __uint_as_float(d1[c + 1]),
                __uint_as_float(d1[c + 2]), __uint_as_float(d1[c + 3]));
        }
    }
    __syncthreads();
    if (wid == 0) TC_DEALLOC(tmem, 128);
#undef LOAD_CHUNK

#else  // SIMT fallback
    __shared__ float As[8][128];
    __shared__ float Bs[8][128];
    const int tid = threadIdx.x;
    const int bm = blockIdx.y * 128;
    const int bn = blockIdx.x * 128;
    const int K = C_;
    const int ldRow = tid >> 1;
    const int ldK   = (tid & 1) * 4;
    const int ri = (tid >> 4) * 4;
    const int ci = (tid & 15) * 4;

    float acc[8][8];
#pragma unroll
    for (int i = 0; i < 8; i++)
#pragma unroll
        for (int j = 0; j < 8; j++) acc[i][j] = 0.f;

    for (int k0 = 0; k0 < K; k0 += 8) {
#pragma unroll
        for (int c = 0; c < 4; c++) {
            size_t ga = (size_t)(bm + ldRow) * K + k0 + ldK + c;
            size_t gb = (size_t)(bn + ldRow) * K + k0 + ldK + c;
            As[ldK + c][ldRow] = A[ga];
            Bs[ldK + c][ldRow] = __bfloat162float(Bhi[gb]) + __bfloat162float(Blo[gb]);
        }
        __syncthreads();
#pragma unroll
        for (int kk = 0; kk < 8; kk++) {
            float ar[8], br[8];
#pragma unroll
            for (int i = 0; i < 4; i++) {
                ar[i] = As[kk][ri + i];
                ar[i + 4] = As[kk][ri + 64 + i];
                br[i] = Bs[kk][ci + i];
                br[i + 4] = Bs[kk][ci + 64 + i];
            }
#pragma unroll
            for (int i = 0; i < 8; i++)
#pragma unroll
                for (int j = 0; j < 8; j++) acc[i][j] += ar[i] * br[j];
        }
        __syncthreads();
    }
#pragma unroll
    for (int ib = 0; ib < 2; ib++)
#pragma unroll
        for (int i = 0; i < 4; i++) {
            int row = bm + ib * 64 + ri + i;
#pragma unroll
            for (int jb = 0; jb < 2; jb++)
#pragma unroll
                for (int j = 0; j < 4; j++)
                    C[(size_t)row * N + bn + jb * 64 + ci + j] =
                        acc[ib * 4 + i][jb * 4 + j];
        }
#endif
}

// ---------------------------------------------------------------------------
// Per-token post-process (unchanged).
// ---------------------------------------------------------------------------
__global__ __launch_bounds__(256) void postproc(
    const float* __restrict__ x, const float* __restrict__ ve,
    const float* __restrict__ cosb, const float* __restrict__ sinb,
    const float* __restrict__ Wgate) {
    const int bt = blockIdx.x;
    const int b = bt / T_, t = bt % T_;
    const int tid = threadIdx.x;
    const int lane = tid & 31, w = tid >> 5;
    __shared__ float s_gate[NKV_];

    if (w < NKV_) {
        float p = x[(size_t)bt * C_ + lane] * Wgate[lane * NKV_ + w];
#pragma unroll
        for (int o = 16; o; o >>= 1) p += __shfl_xor_sync(0xffffffffu, p, o);
        if (lane == 0) s_gate[w] = 2.0f / (1.0f + expf(-p));
    }
    __syncthreads();

    const float c = cosb[t * (HD_ / 2) + lane];
    const float s = sinb[t * (HD_ / 2) + lane];
    const float* qkvrow = g_qkv + (size_t)bt * NQKV_;
    for (int row = w; row < NH_ + NKV_; row += 8) {
        const float* src;
        __nv_bfloat16 *dhi, *dlo;
        if (row < NH_) {
            src = qkvrow + row * HD_;
            size_t base = ((size_t)(b * NH_ + row) * T_ + t) * HD_;
            dhi = g_qs_hi + base;
            dlo = g_qs_lo + base;
        } else {
            int kh = row - NH_;
            src = qkvrow + 1024 + kh * HD_;
            size_t base = ((size_t)(b * NKV_ + kh) * T_ + t) * HD_;
            dhi = g_ks_hi + base;
            dlo = g_ks_lo + base;
        }
        float x1 = src[lane], x2 = src[lane + 32];
        float o1 = x1 * c + x2 * s;
        float o2 = -x1 * s + x2 * c;
        float sq = o1 * o1 + o2 * o2;
#pragma unroll
        for (int o = 16; o; o >>= 1) sq += __shfl_xor_sync(0xffffffffu, sq, o);
        float scale = rsqrtf(sq * (1.0f / HD_) + 1.1920929e-7f);
        float v1 = o1 * scale, v2 = o2 * scale;
        __nv_bfloat16 h1 = __float2bfloat16(v1);
        __nv_bfloat16 h2 = __float2bfloat16(v2);
        dhi[lane] = h1;
        dhi[lane + 32] = h2;
        dlo[lane] = __float2bfloat16(v1 - __bfloat162float(h1));
        dlo[lane + 32] = __float2bfloat16(v2 - __bfloat162float(h2));
    }

    {
        int h = tid >> 6, d = tid & 63;
        float val = qkvrow[1280 + tid] +
                    s_gate[h] * ve[(size_t)bt * (NKV_ * HD_) + tid];
        size_t o = ((size_t)(b * NKV_ + h) * HD_ + d) * T_ + t;  // transposed
        __nv_bfloat16 hh = __float2bfloat16(val);
        g_vts_hi[o] = hh;
        g_vts_lo[o] = __float2bfloat16(val - __bfloat162float(hh));
    }
}

// ---------------------------------------------------------------------------
// tcgen05 sliding-window flash attention, static-max softmax, DEEP pipeline:
// S(jt+1) is issued BEFORE softmax(jt), so the tensor queue
// (... S(jt), PV(jt-1), S(jt+1), PV(jt) ...) stays busy while SIMT does
// softmax. K prefetched distance-2, V distance-1 (clamped indices keep
// cp.async group counts uniform so wait_group 1 always retires the needed
// group). mbar0 = S commits (waited at iter top); mbar1 = PV commits
// (waited just before the V-buffer overwrite; near-zero cost).
// grid = (T/128, NH, B), 256 threads, 1 CTA/SM (smem ~167KB).
// ---------------------------------------------------------------------------
#define AOFF_RED 0         // redsum[256] f32 (1KB)
#define AOFF_Q   2048      // Qhi 16K | Qlo 16K                 (end 34816)
#define AOFF_K   34816     // buf s: {Khi 8K | Klo 8K} x2       (end 67584)
#define AOFF_V   67584     // buf s: {Vhi 8K | Vlo 8K} x2       (end 100352)
#define AOFF_P   100352    // buf s: {Phi 16K | Plo 16K} x2     (end 165888)
#define KBUF(s)  (AOFF_K + (s) * 16384)
#define VBUF(s)  (AOFF_V + (s) * 16384)
#define PBUF(s)  (AOFF_P + (s) * 32768)
#define ATT_SMEM 168960    // 1024 hdr + align slack + 165888

__global__ __launch_bounds__(256, 1) void attn_tc(const int* __restrict__ winp) {
#if TC_OK
    extern __shared__ char smem[];
    const uint32_t sb = smem_u32(smem);
    const uint32_t ab = (sb + 1024 + 1023) & 0xFFFFFC00u;
    char* abp = smem + (ab - sb);

    int win = winp[0];
    if (win <= 0 || win > T_) win = 1024;
    const int qt = blockIdx.x, h = blockIdx.y, b = blockIdx.z;
    const int kvh = h >> 2;
    const int q0 = qt * 128;
    const int tid = threadIdx.x, w = tid >> 5, lane = tid & 31;
    const int sp = w & 3;              // TMEM subpartition
    const int hf = w >> 2;             // key half (0 or 1)
    const int kbase = hf * 32;
    const int r = sp * 32 + lane;      // q row within tile
    const int qg = q0 + r;             // global q index

    float* redsum = (float*)(abp + AOFF_RED);

    if (w == 0) TC_ALLOC(sb, 256);
    if (tid == 0) { MBAR_INIT(sb + 8, 1); MBAR_INIT(sb + 16, 1); }
    __syncthreads();
    uint32_t tmem;
    asm volatile("ld.shared.b32 %0, [%1];" : "=r"(tmem) : "r"(sb));

    const __nv_bfloat16* qh  = g_qs_hi  + ((size_t)(b * NH_ + h) * T_ + q0) * HD_;
    const __nv_bfloat16* qlo = g_qs_lo  + ((size_t)(b * NH_ + h) * T_ + q0) * HD_;
    const __nv_bfloat16* kh  = g_ks_hi  + ((size_t)(b * NKV_ + kvh) * T_) * HD_;
    const __nv_bfloat16* kl  = g_ks_lo  + ((size_t)(b * NKV_ + kvh) * T_) * HD_;
    const __nv_bfloat16* vth = g_vts_hi + ((size_t)(b * NKV_ + kvh) * HD_) * T_;
    const __nv_bfloat16* vtl = g_vts_lo + ((size_t)(b * NKV_ + kvh) * HD_) * T_;

    int j0s = q0 - win;
    if (j0s < 0) j0s = 0;
    const int jt0 = j0s >> 6;
    const int jt1 = (q0 + 127) >> 6;   // always >= jt0 + 1

    // per-thread K/V load coordinates: 2 x 16B per component per thread
    const int krr0 = tid >> 3, kc8 = (tid & 7) * 8;          // rows 0..31
    const uint32_t koff0 = SW128((uint32_t)(krr0 * 128 + kc8 * 2));
    const uint32_t koff1 = SW128((uint32_t)((krr0 + 32) * 128 + kc8 * 2));

#define LOAD_K(jt, s)                                                         \
    do {                                                                      \
        const int j0_ = (jt) * 64;                                            \
        uint32_t kb_ = ab + KBUF(s);                                          \
        CP_ASYNC16(kb_ + koff0,        kh + (size_t)(j0_ + krr0) * 64 + kc8); \
        CP_ASYNC16(kb_ + koff1,        kh + (size_t)(j0_ + krr0 + 32) * 64 + kc8); \
        CP_ASYNC16(kb_ + 8192 + koff0, kl + (size_t)(j0_ + krr0) * 64 + kc8); \
        CP_ASYNC16(kb_ + 8192 + koff1, kl + (size_t)(j0_ + krr0 + 32) * 64 + kc8); \
    } while (0)

#define LOAD_V(jt, s)                                                         \
    do {                                                                      \
        const int j0_ = (jt) * 64;                                            \
        uint32_t vb_ = ab + VBUF(s);                                          \
        CP_ASYNC16(vb_ + koff0,        vth + (size_t)krr0 * T_ + j0_ + kc8);  \
        CP_ASYNC16(vb_ + koff1,        vth + (size_t)(krr0 + 32) * T_ + j0_ + kc8); \
        CP_ASYNC16(vb_ + 8192 + koff0, vtl + (size_t)krr0 * T_ + j0_ + kc8);  \
        CP_ASYNC16(vb_ + 8192 + koff1, vtl + (size_t)(krr0 + 32) * T_ + j0_ + kc8); \
    } while (0)

#define ISSUE_S(kbuf_s, tm_s)                                                 \
    do {                                                                      \
        uint64_t dKh = smem_desc_sw128(ab + KBUF(kbuf_s));                    \
        uint64_t dKl = smem_desc_sw128(ab + KBUF(kbuf_s) + 8192);             \
        uint32_t sdst = tmem + (tm_s) * 64;                                   \
        _Pragma("unroll")                                                     \
        for (int kk = 0; kk < 4; kk++)                                        \
            mma_f16_ss(sdst, dQh + kk * 2, dKh + kk * 2, ATT_IDESC, kk > 0);  \
        _Pragma("unroll")                                                     \
        for (int kk = 0; kk < 4; kk++)                                        \
            mma_f16_ss(sdst, dQh + kk * 2, dKl + kk * 2, ATT_IDESC, 1);       \
        _Pragma("unroll")                                                     \
        for (int kk = 0; kk < 4; kk++)                                        \
            mma_f16_ss(sdst, dQl + kk * 2, dKh + kk * 2, ATT_IDESC, 1);       \
    } while (0)

    // ---- prologue ----
#pragma unroll
    for (int v = 0; v < 4; v++) {
        int idx = tid + v * 256;
        int rr = idx >> 3, c8 = idx & 7;
        uint32_t off = SW128((uint32_t)(rr * 128 + c8 * 16));
        *(uint4*)(abp + AOFF_Q + off)         = *(const uint4*)(qh  + rr * 64 + c8 * 8);
        *(uint4*)(abp + AOFF_Q + 16384 + off) = *(const uint4*)(qlo + rr * 64 + c8 * 8);
    }
    LOAD_K(jt0, jt0 & 1);
    LOAD_V(jt0, jt0 & 1);
    CP_COMMIT();
    LOAD_K(jt0 + 1, (jt0 + 1) & 1);    // jt0+1 <= jt1 always
    CP_COMMIT();
    CP_WAIT0();
    __syncthreads();
    const uint64_t dQh = smem_desc_sw128(ab + AOFF_Q);
    const uint64_t dQl = smem_desc_sw128(ab + AOFF_Q + 16384);
    if (w == 0) {
        FENCE_ASYNC();
        if (elect_one()) {
            ISSUE_S(jt0 & 1, jt0 & 1);
            TC_COMMIT(sb + 8);
        }
    }

    float l_loc = 0.f;
    int ps = 0, ppv = 0;

    for (int jt = jt0; jt <= jt1; jt++) {
        const int sbuf = jt & 1;
        const int j0 = jt * 64;
        // 1. S(jt) done (also implies PV(jt-2) and older)
        mbar_wait(sb + 8, ps & 1); ps++;
        // 2. own K(jt+1) cp.async copies retired (oldest group)
        CP_WAIT1();
        // 3. everyone's K(jt+1) visible; all LDTMs of prior iter done
        __syncthreads();
        TC_FENCE_AFTER();
        // 4. issue S(jt+1) NOW (runs behind PV(jt-1) while we do softmax)
        if (jt < jt1 && w == 0) {
            FENCE_ASYNC();
            if (elect_one()) {
                ISSUE_S(sbuf ^ 1, sbuf ^ 1);
                TC_COMMIT(sb + 8);
            }
        }
        // 5. prefetch K(jt+2) into kbuf[sbuf] (K(jt) reader S(jt) done)
        {
            int kidx = jt + 2 <= jt1 ? jt + 2 : jt1;
            LOAD_K(kidx, sbuf);
            CP_COMMIT();
        }
        // 6. softmax(jt): p = exp(s/8 - 8), masked -> 0
        uint32_t sr[32];
        LDTM_X32(sr, tmem + ((uint32_t)sp << 21) + sbuf * 64 + kbase);
        TC_WAIT_LD();
        float p[32];
#pragma unroll
        for (int i = 0; i < 32; i++) {
            int jg = j0 + kbase + i;
            bool ok = (jg <= qg) && (jg >= qg - win);
            float e = __expf(__uint_as_float(sr[i]) * 0.125f - 8.0f);
            p[i] = ok ? e : 0.f;
            l_loc += p[i];
        }
        // 7. store P(jt) into pbuf[sbuf] (reader PV(jt-2) done via step 1)
#pragma unroll
        for (int i = 0; i < 16; i++) {
            float pa = p[2 * i], pb = p[2 * i + 1];
            __nv_bfloat162 hh = __floats2bfloat162_rn(pa, pb);
            float la = pa - __bfloat162float(hh.x);
            float lb = pb - __bfloat162float(hh.y);
            __nv_bfloat162 ll = __floats2bfloat162_rn(la, lb);
            uint32_t boff = SW128((uint32_t)(r * 128 + (kbase + 2 * i) * 2));
            *(uint32_t*)(abp + PBUF(sbuf) + boff)         = b2u(hh);
            *(uint32_t*)(abp + PBUF(sbuf) + 16384 + boff) = b2u(ll);
        }
        // 8. PV(jt-1) done -> V(jt-1) buffer free (finished during softmax)
        if (jt > jt0) { mbar_wait(sb + 16, ppv & 1); ppv++; }
        // 9. own V(jt) copies retired (oldest group now), prefetch V(jt+1)
        CP_WAIT1();
        {
            int vidx = jt + 1 <= jt1 ? jt + 1 : jt1;
            LOAD_V(vidx, sbuf ^ 1);
            CP_COMMIT();
        }
        // 10. P(jt) + everyone's V(jt) visible block-wide
        __syncthreads();
        // 11. issue PV(jt), accumulate into TMEM cols 128-191
        if (w == 0) {
            FENCE_ASYNC();
            if (elect_one()) {
                uint64_t dPh = smem_desc_sw128(ab + PBUF(sbuf));
                uint64_t dPl = smem_desc_sw128(ab + PBUF(sbuf) + 16384);
                uint64_t dVh = smem_desc_sw128(ab + VBUF(sbuf));
                uint64_t dVl = smem_desc_sw128(ab + VBUF(sbuf) + 8192);
#pragma unroll
                for (int kk = 0; kk < 4; kk++)
                    mma_f16_ss(tmem + 128, dPh + kk * 2, dVh + kk * 2, ATT_IDESC,
                               (jt > jt0) || (kk > 0));
#pragma unroll
                for (int kk = 0; kk < 4; kk++)
                    mma_f16_ss(tmem + 128, dPh + kk * 2, dVl + kk * 2, ATT_IDESC, 1);
#pragma unroll
                for (int kk = 0; kk < 4; kk++)
                    mma_f16_ss(tmem + 128, dPl + kk * 2, dVh + kk * 2, ATT_IDESC, 1);
                TC_COMMIT(sb + 16);
            }
        }
    }
    // drain final PV, combine l halves, write O
    mbar_wait(sb + 16, ppv & 1);
    TC_FENCE_AFTER();
    redsum[r * 2 + hf] = l_loc;
    __syncthreads();
    const float l = redsum[r * 2] + redsum[r * 2 + 1];
    uint32_t pr[32];
    LDTM_X32(pr, tmem + ((uint32_t)sp << 21) + 128 + kbase);
    TC_WAIT_LD();
    {
        const float inv = 1.0f / l;
        float* dst = g_y + ((size_t)(b * T_ + qg)) * C_ + h * 64 + kbase;
#pragma unroll
        for (int i = 0; i < 32; i += 4)
            *(float4*)(dst + i) = make_float4(
                __uint_as_float(pr[i]) * inv, __uint_as_float(pr[i + 1]) * inv,
                __uint_as_float(pr[i + 2]) * inv, __uint_as_float(pr[i + 3]) * inv);
    }
    __syncthreads();
    if (w == 0) TC_DEALLOC(tmem, 256);
#undef LOAD_K
#undef LOAD_V
#undef ISSUE_S

#else  // ---------------- SIMT fallback (baseline target, never run) --------
    const int qt = blockIdx.x, h = blockIdx.y, b = blockIdx.z;
    const int kvh = h >> 2;
    int win = winp[0];
    if (win <= 0 || win > T_) win = 1024;
    const int tid = threadIdx.x;
    if (tid < 128) {
        const int qg = qt * 128 + tid;
        const __nv_bfloat16* qh  = g_qs_hi + ((size_t)(b * NH_ + h) * T_ + qg) * HD_;
        const __nv_bfloat16* qlo = g_qs_lo + ((size_t)(b * NH_ + h) * T_ + qg) * HD_;
        float q[64];
        for (int d = 0; d < 64; d++)
            q[d] = __bfloat162float(qh[d]) + __bfloat162float(qlo[d]);
        const __nv_bfloat16* kh  = g_ks_hi  + ((size_t)(b * NKV_ + kvh) * T_) * HD_;
        const __nv_bfloat16* kl  = g_ks_lo  + ((size_t)(b * NKV_ + kvh) * T_) * HD_;
        const __nv_bfloat16* vth = g_vts_hi + ((size_t)(b * NKV_ + kvh) * HD_) * T_;
        const __nv_bfloat16* vtl = g_vts_lo + ((size_t)(b * NKV_ + kvh) * HD_) * T_;
        float l = 0.f, O[64];
        for (int d = 0; d < 64; d++) O[d] = 0.f;
        int js = qg - win;
        if (js < 0) js = 0;
        for (int j = js; j <= qg; j++) {
            float s = 0.f;
            for (int d = 0; d < 64; d++)
                s += q[d] * (__bfloat162float(kh[(size_t)j * 64 + d]) +
                             __bfloat162float(kl[(size_t)j * 64 + d]));
            float p = __expf(s * 0.125f - 8.0f);
            l += p;
            for (int d = 0; d < 64; d++)
                O[d] += p * (__bfloat162float(vth[(size_t)d * T_ + j]) +
                             __bfloat162float(vtl[(size_t)d * T_ + j]));
        }
        float inv = 1.0f / l;
        float* dst = g_y + ((size_t)(b * T_ + qg)) * C_ + h * 64;
        for (int d = 0; d < 64; d++) dst[d] = O[d] * inv;
    }
#endif
}

// ---------------------------------------------------------------------------
// Launch
// ---------------------------------------------------------------------------
extern "C" void kernel_launch(void* const* d_in, const int* in_sizes, int n_in,
                              void* d_out, int out_size) {
    const float* x     = (const float*)d_in[0];
    const float* ve    = (const float*)d_in[1];
    const float* cosb  = (const float*)d_in[2];
    const float* sinb  = (const float*)d_in[3];
    const float* Wq    = (const float*)d_in[4];
    const float* Wk    = (const float*)d_in[5];
    const float* Wv    = (const float*)d_in[6];
    const float* Wproj = (const float*)d_in[7];
    const float* Wgate = (const float*)d_in[8];
    const int*   win   = (const int*)d_in[9];
    float* out = (float*)d_out;

    __nv_bfloat16 *wqkv_hi, *wqkv_lo, *wproj_hi, *wproj_lo;
    float *qkv, *yb;
    cudaGetSymbolAddress((void**)&wqkv_hi, g_wqkv_hi);
    cudaGetSymbolAddress((void**)&wqkv_lo, g_wqkv_lo);
    cudaGetSymbolAddress((void**)&wproj_hi, g_wproj_hi);
    cudaGetSymbolAddress((void**)&wproj_lo, g_wproj_lo);
    cudaGetSymbolAddress((void**)&qkv, g_qkv);
    cudaGetSymbolAddress((void**)&yb, g_y);

    cudaFuncSetAttribute(gemm_split,
                         cudaFuncAttributeMaxDynamicSharedMemorySize, GEMM_SMEM);
    cudaFuncSetAttribute(attn_tc,
                         cudaFuncAttributeMaxDynamicSharedMemorySize, ATT_SMEM);

    // 1. transpose + split all weights (one launch)
    transpose_split_all<<<dim3(80, C_ / 32), dim3(32, 8)>>>(Wq, Wk, Wv, Wproj);
    // 2. fused QKV projection (A = x fp32, split in-kernel)
    gemm_split<<<dim3(NQKV_ / 128, M_ / 128), 256, GEMM_SMEM>>>(
        x, wqkv_hi, wqkv_lo, qkv, NQKV_);
    // 3. gate + RoPE + RMSNorm + bf16 split + layouts
    postproc<<<M_, 256>>>(x, ve, cosb, sinb, Wgate);
    // 4. deep-pipelined tensor-core attention, static-max softmax
    attn_tc<<<dim3(T_ / 128, NH_, B_), 256, ATT_SMEM>>>(win);
    // 5. output projection (A = y fp32, split in-kernel)
    gemm_split<<<dim3(C_ / 128, M_ / 128), 256, GEMM_SMEM>>>(
        yb, wproj_hi, wproj_lo, out, C_);
}

// round 13
// speedup vs baseline: 6.5493x; 1.1316x over previous
#include <cuda_runtime.h>
#include <cuda_bf16.h>
#include <math.h>
#include <stdint.h>

// Problem constants (fixed by the reference)
#define B_  2
#define T_  2048
#define C_  1024
#define NH_ 16
#define NKV_ 4
#define HD_ 64
#define VEC_ 32
#define M_  (B_ * T_)      // 4096 token rows
#define NQKV_ 1536         // fused q(1024) | k(256) | v(256) columns

// tcgen05 is arch-conditional: only in the sm_103a/sm_100a passes. The
// baseline compute_103 target gets SIMT fallback bodies.
#if defined(__CUDA_ARCH_FEAT_SM103_ALL) || defined(__CUDA_ARCH_FEAT_SM100_ALL) || \
    defined(__CUDA_ARCH_FEAT_SM101_ALL)
#define TC_OK 1
#else
#define TC_OK 0
#endif

// ---------------------------------------------------------------------------
// Scratch (static device globals; no runtime allocation allowed)
// ---------------------------------------------------------------------------
__device__ __align__(16) __nv_bfloat16 g_wqkv_hi[NQKV_ * C_];  // [N,K] transposed
__device__ __align__(16) __nv_bfloat16 g_wqkv_lo[NQKV_ * C_];
__device__ __align__(16) __nv_bfloat16 g_wproj_hi[C_ * C_];    // [N,K] transposed
__device__ __align__(16) __nv_bfloat16 g_wproj_lo[C_ * C_];
__device__ float g_qkv[M_ * NQKV_];        // fused projection output
__device__ float g_y[M_ * C_];             // attention output [B,T,NH*HD] fp32
// attention operands, bf16 hi/lo split
__device__ __align__(16) __nv_bfloat16 g_qs_hi[M_ * NH_ * HD_];   // [B,NH,T,HD]
__device__ __align__(16) __nv_bfloat16 g_qs_lo[M_ * NH_ * HD_];
__device__ __align__(16) __nv_bfloat16 g_ks_hi[M_ * NKV_ * HD_];  // [B,NKV,T,HD]
__device__ __align__(16) __nv_bfloat16 g_ks_lo[M_ * NKV_ * HD_];
__device__ __align__(16) __nv_bfloat16 g_vts_hi[M_ * NKV_ * HD_]; // [B,NKV,HD,T]
__device__ __align__(16) __nv_bfloat16 g_vts_lo[M_ * NKV_ * HD_];

// ---------------------------------------------------------------------------
// PTX helpers
// ---------------------------------------------------------------------------
__device__ __forceinline__ uint32_t smem_u32(const void* p) {
    uint32_t a;
    asm("{ .reg .u64 t; cvta.to.shared.u64 t, %1; cvt.u32.u64 %0, t; }"
        : "=r"(a) : "l"(p));
    return a;
}
__device__ __forceinline__ uint32_t elect_one() {
    uint32_t pred;
    asm volatile("{\n\t.reg .pred p;\n\telect.sync _|p, 0xFFFFFFFF;\n\t"
                 "selp.b32 %0, 1, 0, p;\n\t}" : "=r"(pred));
    return pred;
}
#define TC_ALLOC(sm, n)   asm volatile("tcgen05.alloc.cta_group::1.sync.aligned.shared::cta.b32 [%0], %1;" :: "r"(sm), "r"((uint32_t)(n)) : "memory")
#define TC_DEALLOC(t, n)  asm volatile("tcgen05.dealloc.cta_group::1.sync.aligned.b32 %0, %1;" :: "r"(t), "r"((uint32_t)(n)))
#define TC_RELINQ()       asm volatile("tcgen05.relinquish_alloc_permit.cta_group::1.sync.aligned;")
#define TC_COMMIT(mbar)   asm volatile("tcgen05.commit.cta_group::1.mbarrier::arrive::one.shared::cluster.b64 [%0];" :: "r"(mbar) : "memory")
#define TC_FENCE_AFTER()  asm volatile("tcgen05.fence::after_thread_sync;" ::: "memory")
#define TC_FENCE_BEFORE() asm volatile("tcgen05.fence::before_thread_sync;" ::: "memory")
#define TC_WAIT_LD()      asm volatile("tcgen05.wait::ld.sync.aligned;" ::: "memory")
#define TC_WAIT_ST()      asm volatile("tcgen05.wait::st.sync.aligned;" ::: "memory")
#define MBAR_INIT(sm, n)  asm volatile("mbarrier.init.shared.b64 [%0], %1;" :: "r"(sm), "r"((uint32_t)(n)) : "memory")
#define FENCE_ASYNC()     asm volatile("fence.proxy.async.shared::cta;" ::: "memory")
#define CP_ASYNC16(dst, src) asm volatile("cp.async.cg.shared.global [%0], [%1], 16;" :: "r"(dst), "l"(src) : "memory")
#define CP_COMMIT()       asm volatile("cp.async.commit_group;" ::: "memory")
#define CP_WAIT0()        asm volatile("cp.async.wait_group 0;" ::: "memory")
#define CP_WAIT1()        asm volatile("cp.async.wait_group 1;" ::: "memory")

__device__ __forceinline__ void mbar_wait(uint32_t mbar, uint32_t parity) {
    asm volatile(
        "{\n\t.reg .pred P;\n\t"
        "W%=:\n\t"
        "mbarrier.try_wait.parity.acquire.cta.shared::cta.b64 P, [%0], %1, 0x989680;\n\t"
        "@P bra D%=;\n\t"
        "bra W%=;\n\t"
        "D%=:\n\t}"
        :: "r"(mbar), "r"(parity) : "memory");
}
__device__ __forceinline__ float ex2_approx(float x) {
    float r;
    asm("ex2.approx.ftz.f32 %0, %1;" : "=f"(r) : "f"(x));
    return r;
}

#if TC_OK
// SS-mode bf16 MMA, cta_group::1, fp32 accum
__device__ __forceinline__ void mma_f16_ss(uint32_t d, uint64_t a, uint64_t b,
                                           uint32_t idesc, uint32_t en) {
    asm volatile(
        "{\n\t.reg .pred p;\n\t"
        "setp.ne.u32 p, %4, 0;\n\t"
        "tcgen05.mma.cta_group::1.kind::f16 [%0], %1, %2, %3, {%5, %5, %5, %5}, p;\n\t"
        "}"
        :: "r"(d), "l"(a), "l"(b), "r"(idesc), "r"(en), "r"(0u)
        : "memory");
}
// TS-mode bf16 MMA: A in TMEM, B in SMEM
__device__ __forceinline__ void mma_f16_ts(uint32_t d, uint32_t a, uint64_t b,
                                           uint32_t idesc, uint32_t en) {
    asm volatile(
        "{\n\t.reg .pred p;\n\t"
        "setp.ne.u32 p, %4, 0;\n\t"
        "tcgen05.mma.cta_group::1.kind::f16 [%0], [%1], %2, %3, {%5, %5, %5, %5}, p;\n\t"
        "}"
        :: "r"(d), "r"(a), "l"(b), "r"(idesc), "r"(en), "r"(0u)
        : "memory");
}

#define LDTM_X32(r, addr) \
    asm volatile( \
        "tcgen05.ld.sync.aligned.32x32b.x32.b32 " \
        "{%0, %1, %2, %3, %4, %5, %6, %7, " \
        " %8, %9, %10, %11, %12, %13, %14, %15, " \
        " %16, %17, %18, %19, %20, %21, %22, %23, " \
        " %24, %25, %26, %27, %28, %29, %30, %31}, [%32];" \
        : "=r"((r)[0]),  "=r"((r)[1]),  "=r"((r)[2]),  "=r"((r)[3]), \
          "=r"((r)[4]),  "=r"((r)[5]),  "=r"((r)[6]),  "=r"((r)[7]), \
          "=r"((r)[8]),  "=r"((r)[9]),  "=r"((r)[10]), "=r"((r)[11]), \
          "=r"((r)[12]), "=r"((r)[13]), "=r"((r)[14]), "=r"((r)[15]), \
          "=r"((r)[16]), "=r"((r)[17]), "=r"((r)[18]), "=r"((r)[19]), \
          "=r"((r)[20]), "=r"((r)[21]), "=r"((r)[22]), "=r"((r)[23]), \
          "=r"((r)[24]), "=r"((r)[25]), "=r"((r)[26]), "=r"((r)[27]), \
          "=r"((r)[28]), "=r"((r)[29]), "=r"((r)[30]), "=r"((r)[31]) \
        : "r"(addr))

#define STTM_X16(addr, r) \
    asm volatile( \
        "tcgen05.st.sync.aligned.32x32b.x16.b32 [%0], " \
        "{%1, %2, %3, %4, %5, %6, %7, %8, " \
        " %9, %10, %11, %12, %13, %14, %15, %16};" \
        :: "r"(addr), \
           "r"((r)[0]),  "r"((r)[1]),  "r"((r)[2]),  "r"((r)[3]), \
           "r"((r)[4]),  "r"((r)[5]),  "r"((r)[6]),  "r"((r)[7]), \
           "r"((r)[8]),  "r"((r)[9]),  "r"((r)[10]), "r"((r)[11]), \
           "r"((r)[12]), "r"((r)[13]), "r"((r)[14]), "r"((r)[15]) \
        : "memory")
#endif  // TC_OK

// 64-bit SMEM descriptor: SW128, version=1 (Blackwell), LBO=1, SBO=64
static __device__ __forceinline__ uint64_t smem_desc_sw128(uint32_t addr) {
    const uint64_t base =
        (uint64_t(2)  << 61) | (uint64_t(1) << 46) |
        (uint64_t(64) << 32) | (uint64_t(1) << 16);
    return base | ((uint64_t)(addr >> 4) & 0x3FFF);
}
#define SW128(off) ((off) ^ (((off) >> 3) & 0x70))

// idesc: dtype=F32, atype=BF16, btype=BF16 (K-major both)
#define GEMM_IDESC ((1u << 4) | (1u << 7) | (1u << 10) | ((128u / 8) << 17) | ((128u / 16) << 24))
#define ATT_IDESC  ((1u << 4) | (1u << 7) | (1u << 10) | ((64u / 8) << 17) | ((128u / 16) << 24))

__device__ __forceinline__ uint32_t b2u(__nv_bfloat162 v) {
    return *(uint32_t*)&v;
}

// ---------------------------------------------------------------------------
// Combined weight transpose + hi/lo split.
// ---------------------------------------------------------------------------
__global__ __launch_bounds__(256) void transpose_split_all(
    const float* __restrict__ Wq, const float* __restrict__ Wk,
    const float* __restrict__ Wv, const float* __restrict__ Wp) {
    __shared__ float t[32][33];
    const int ct = blockIdx.x;
    const float* W;
    __nv_bfloat16 *hi, *lo;
    int Ncols, nb;
    if (ct < 32)      { W = Wq; hi = g_wqkv_hi;                     lo = g_wqkv_lo;                     Ncols = 1024; nb = ct * 32; }
    else if (ct < 40) { W = Wk; hi = g_wqkv_hi + (size_t)1024 * C_; lo = g_wqkv_lo + (size_t)1024 * C_; Ncols = 256;  nb = (ct - 32) * 32; }
    else if (ct < 48) { W = Wv; hi = g_wqkv_hi + (size_t)1280 * C_; lo = g_wqkv_lo + (size_t)1280 * C_; Ncols = 256;  nb = (ct - 40) * 32; }
    else              { W = Wp; hi = g_wproj_hi;                    lo = g_wproj_lo;                    Ncols = 1024; nb = (ct - 48) * 32; }
    const int kb = blockIdx.y * 32;
    const int tx = threadIdx.x, ty = threadIdx.y;
#pragma unroll
    for (int j = 0; j < 32; j += 8)
        t[ty + j][tx] = W[(size_t)(kb + ty + j) * Ncols + nb + tx];
    __syncthreads();
#pragma unroll
    for (int j = 0; j < 32; j += 8) {
        float v = t[tx][ty + j];
        __nv_bfloat16 h = __float2bfloat16(v);
        size_t o = (size_t)(nb + ty + j) * C_ + kb + tx;
        hi[o] = h;
        lo[o] = __float2bfloat16(v - __bfloat162float(h));
    }
}

// ---------------------------------------------------------------------------
// Split-bf16 GEMM: C[M,N] = A[M,K] . Bt[N,K]^T  (fp32-accurate)
// A fp32, split in-register during smem fill. Unchanged (passing since r7).
// ---------------------------------------------------------------------------
#define KCHUNK   64
#define NCHUNKS  (C_ / KCHUNK)           // 16
#define BUFSZ    16384                   // 128 rows x 128 bytes
#define STAGESZ  (4 * BUFSZ)             // Ahi | Alo | Bhi | Blo
#define GEMM_SMEM (2048 + 2 * STAGESZ)

__global__ __launch_bounds__(256) void gemm_split(
    const float* __restrict__ A,
    const __nv_bfloat16* __restrict__ Bhi, const __nv_bfloat16* __restrict__ Blo,
    float* __restrict__ C, int N) {
#if TC_OK
    extern __shared__ char smem[];
    const uint32_t sb = smem_u32(smem);
    const uint32_t ab = (sb + 1024 + 1023) & 0xFFFFFC00u;
    char* smab = smem + (ab - sb);
    const int tid = threadIdx.x;
    const int wid = tid >> 5;
    const int lane = tid & 31;
    const int bm = blockIdx.y * 128;
    const int bn = blockIdx.x * 128;
    const int K = C_;

    if (wid == 0) TC_ALLOC(sb, 128);
    if (tid == 0) { MBAR_INIT(sb + 8, 1); MBAR_INIT(sb + 16, 1); }
    __syncthreads();
    uint32_t tmem;
    asm volatile("ld.shared.b32 %0, [%1];" : "=r"(tmem) : "r"(sb));

#define LOAD_CHUNK(kc, s)                                                     \
    do {                                                                      \
        const int k0 = (kc) * KCHUNK;                                         \
        char* st = smab + (s) * STAGESZ;                                      \
        _Pragma("unroll")                                                     \
        for (int v = 0; v < 4; v++) {                                         \
            int idx = tid + v * 256;                                          \
            int r = idx >> 3, c8 = idx & 7;                                   \
            uint32_t off = SW128((uint32_t)(r * 128 + c8 * 16));              \
            const float* ap = A + (size_t)(bm + r) * K + k0 + c8 * 8;         \
            float4 a0 = *(const float4*)ap;                                   \
            float4 a1 = *(const float4*)(ap + 4);                             \
            __nv_bfloat162 h0 = __floats2bfloat162_rn(a0.x, a0.y);            \
            __nv_bfloat162 h1 = __floats2bfloat162_rn(a0.z, a0.w);            \
            __nv_bfloat162 h2 = __floats2bfloat162_rn(a1.x, a1.y);            \
            __nv_bfloat162 h3 = __floats2bfloat162_rn(a1.z, a1.w);            \
            __nv_bfloat162 l0 = __floats2bfloat162_rn(                        \
                a0.x - __bfloat162float(h0.x), a0.y - __bfloat162float(h0.y));\
            __nv_bfloat162 l1 = __floats2bfloat162_rn(                        \
                a0.z - __bfloat162float(h1.x), a0.w - __bfloat162float(h1.y));\
            __nv_bfloat162 l2 = __floats2bfloat162_rn(                        \
                a1.x - __bfloat162float(h2.x), a1.y - __bfloat162float(h2.y));\
            __nv_bfloat162 l3 = __floats2bfloat162_rn(                        \
                a1.z - __bfloat162float(h3.x), a1.w - __bfloat162float(h3.y));\
            uint4 hv = make_uint4(b2u(h0), b2u(h1), b2u(h2), b2u(h3));        \
            uint4 lv = make_uint4(b2u(l0), b2u(l1), b2u(l2), b2u(l3));        \
            *(uint4*)(st + off)         = hv;                                 \
            *(uint4*)(st + BUFSZ + off) = lv;                                 \
            size_t gb = (size_t)(bn + r) * K + k0 + c8 * 8;                   \
            *(uint4*)(st + 2 * BUFSZ + off) = *(const uint4*)(Bhi + gb);      \
            *(uint4*)(st + 3 * BUFSZ + off) = *(const uint4*)(Blo + gb);      \
        }                                                                     \
    } while (0)

    LOAD_CHUNK(0, 0);
    int p0 = 0, p1 = 0;

    for (int i = 0; i < NCHUNKS; i++) {
        const int s = i & 1;
        __syncthreads();
        if (wid == 0) {
            FENCE_ASYNC();
            if (elect_one()) {
                uint32_t base = ab + s * STAGESZ;
                uint64_t dah = smem_desc_sw128(base);
                uint64_t dal = smem_desc_sw128(base + BUFSZ);
                uint64_t dbh = smem_desc_sw128(base + 2 * BUFSZ);
                uint64_t dbl = smem_desc_sw128(base + 3 * BUFSZ);
#pragma unroll
                for (int kk = 0; kk < 4; kk++)
                    mma_f16_ss(tmem, dah + kk * 2, dbh + kk * 2, GEMM_IDESC,
                               (i > 0) || (kk > 0));
#pragma unroll
                for (int kk = 0; kk < 4; kk++)
                    mma_f16_ss(tmem, dah + kk * 2, dbl + kk * 2, GEMM_IDESC, 1);
#pragma unroll
                for (int kk = 0; kk < 4; kk++)
                    mma_f16_ss(tmem, dal + kk * 2, dbh + kk * 2, GEMM_IDESC, 1);
                TC_COMMIT(sb + 8 + s * 8);
            }
        }
        if (i + 1 < NCHUNKS) {
            const int s2 = (i + 1) & 1;
            if (i >= 1) {
                if (s2 == 0) { mbar_wait(sb + 8,  p0 & 1); p0++; }
                else         { mbar_wait(sb + 16, p1 & 1); p1++; }
            }
            LOAD_CHUNK(i + 1, s2);
        }
    }
    {
        const int sl = (NCHUNKS - 1) & 1;
        if (sl == 0) mbar_wait(sb + 8, p0 & 1);
        else         mbar_wait(sb + 16, p1 & 1);
    }
    TC_FENCE_AFTER();

    {
        const int sp = wid & 3;
        const int colbase = (wid >> 2) * 64;
        const uint32_t wo = (uint32_t)sp << 21;
        uint32_t d0[32], d1[32];
        LDTM_X32(d0, tmem + wo + colbase);
        LDTM_X32(d1, tmem + wo + colbase + 32);
        TC_WAIT_LD();
        const int row = bm + sp * 32 + lane;
        float* dst = C + (size_t)row * N + bn + colbase;
#pragma unroll
        for (int c = 0; c < 32; c += 4) {
            *(float4*)(dst + c) = make_float4(
                __uint_as_float(d0[c]), __uint_as_float(d0[c + 1]),
                __uint_as_float(d0[c + 2]), __uint_as_float(d0[c + 3]));
            *(float4*)(dst + 32 + c) = make_float4(
                __uint_as_float(d1[c]), __uint_as_float(d1[c + 1]),
                __uint_as_float(d1[c + 2]), __uint_as_float(d1[c + 3]));
        }
    }
    __syncthreads();
    if (wid == 0) TC_DEALLOC(tmem, 128);
#undef LOAD_CHUNK

#else  // SIMT fallback
    __shared__ float As[8][128];
    __shared__ float Bs[8][128];
    const int tid = threadIdx.x;
    const int bm = blockIdx.y * 128;
    const int bn = blockIdx.x * 128;
    const int K = C_;
    const int ldRow = tid >> 1;
    const int ldK   = (tid & 1) * 4;
    const int ri = (tid >> 4) * 4;
    const int ci = (tid & 15) * 4;

    float acc[8][8];
#pragma unroll
    for (int i = 0; i < 8; i++)
#pragma unroll
        for (int j = 0; j < 8; j++) acc[i][j] = 0.f;

    for (int k0 = 0; k0 < K; k0 += 8) {
#pragma unroll
        for (int c = 0; c < 4; c++) {
            size_t ga = (size_t)(bm + ldRow) * K + k0 + ldK + c;
            size_t gb = (size_t)(bn + ldRow) * K + k0 + ldK + c;
            As[ldK + c][ldRow] = A[ga];
            Bs[ldK + c][ldRow] = __bfloat162float(Bhi[gb]) + __bfloat162float(Blo[gb]);
        }
        __syncthreads();
#pragma unroll
        for (int kk = 0; kk < 8; kk++) {
            float ar[8], br[8];
#pragma unroll
            for (int i = 0; i < 4; i++) {
                ar[i] = As[kk][ri + i];
                ar[i + 4] = As[kk][ri + 64 + i];
                br[i] = Bs[kk][ci + i];
                br[i + 4] = Bs[kk][ci + 64 + i];
            }
#pragma unroll
            for (int i = 0; i < 8; i++)
#pragma unroll
                for (int j = 0; j < 8; j++) acc[i][j] += ar[i] * br[j];
        }
        __syncthreads();
    }
#pragma unroll
    for (int ib = 0; ib < 2; ib++)
#pragma unroll
        for (int i = 0; i < 4; i++) {
            int row = bm + ib * 64 + ri + i;
#pragma unroll
            for (int jb = 0; jb < 2; jb++)
#pragma unroll
                for (int j = 0; j < 4; j++)
                    C[(size_t)row * N + bn + jb * 64 + ci + j] =
                        acc[ib * 4 + i][jb * 4 + j];
        }
#endif
}

// ---------------------------------------------------------------------------
// Per-token post-process (unchanged).
// ---------------------------------------------------------------------------
__global__ __launch_bounds__(256) void postproc(
    const float* __restrict__ x, const float* __restrict__ ve,
    const float* __restrict__ cosb, const float* __restrict__ sinb,
    const float* __restrict__ Wgate) {
    const int bt = blockIdx.x;
    const int b = bt / T_, t = bt % T_;
    const int tid = threadIdx.x;
    const int lane = tid & 31, w = tid >> 5;
    __shared__ float s_gate[NKV_];

    if (w < NKV_) {
        float p = x[(size_t)bt * C_ + lane] * Wgate[lane * NKV_ + w];
#pragma unroll
        for (int o = 16; o; o >>= 1) p += __shfl_xor_sync(0xffffffffu, p, o);
        if (lane == 0) s_gate[w] = 2.0f / (1.0f + expf(-p));
    }
    __syncthreads();

    const float c = cosb[t * (HD_ / 2) + lane];
    const float s = sinb[t * (HD_ / 2) + lane];
    const float* qkvrow = g_qkv + (size_t)bt * NQKV_;
    for (int row = w; row < NH_ + NKV_; row += 8) {
        const float* src;
        __nv_bfloat16 *dhi, *dlo;
        if (row < NH_) {
            src = qkvrow + row * HD_;
            size_t base = ((size_t)(b * NH_ + row) * T_ + t) * HD_;
            dhi = g_qs_hi + base;
            dlo = g_qs_lo + base;
        } else {
            int kh = row - NH_;
            src = qkvrow + 1024 + kh * HD_;
            size_t base = ((size_t)(b * NKV_ + kh) * T_ + t) * HD_;
            dhi = g_ks_hi + base;
            dlo = g_ks_lo + base;
        }
        float x1 = src[lane], x2 = src[lane + 32];
        float o1 = x1 * c + x2 * s;
        float o2 = -x1 * s + x2 * c;
        float sq = o1 * o1 + o2 * o2;
#pragma unroll
        for (int o = 16; o; o >>= 1) sq += __shfl_xor_sync(0xffffffffu, sq, o);
        float scale = rsqrtf(sq * (1.0f / HD_) + 1.1920929e-7f);
        float v1 = o1 * scale, v2 = o2 * scale;
        __nv_bfloat16 h1 = __float2bfloat16(v1);
        __nv_bfloat16 h2 = __float2bfloat16(v2);
        dhi[lane] = h1;
        dhi[lane + 32] = h2;
        dlo[lane] = __float2bfloat16(v1 - __bfloat162float(h1));
        dlo[lane + 32] = __float2bfloat16(v2 - __bfloat162float(h2));
    }

    {
        int h = tid >> 6, d = tid & 63;
        float val = qkvrow[1280 + tid] +
                    s_gate[h] * ve[(size_t)bt * (NKV_ * HD_) + tid];
        size_t o = ((size_t)(b * NKV_ + h) * HD_ + d) * T_ + t;  // transposed
        __nv_bfloat16 hh = __float2bfloat16(val);
        g_vts_hi[o] = hh;
        g_vts_lo[o] = __float2bfloat16(val - __bfloat162float(hh));
    }
}

// ---------------------------------------------------------------------------
// tcgen05 sliding-window flash attention, static-max softmax, deep pipeline,
// P STORED IN TMEM (PV runs TS-mode, A-in-TMEM) -> smem ~101KB, 2 CTAs/SM.
// TMEM (256 cols/CTA so two CTAs co-alloc): S0=0-63, S1=64-127, PV=128-191,
// Phi=192-223, Plo=224-255 (bf16x2, single-buffered; guarded by PV wait).
// mbar0 = S commits (waited at iter top); mbar1 = PV commits (waited before
// the P TMEM overwrite / V buffer reuse).
// grid = (T/128, NH, B), 256 threads, 2 CTAs/SM.
// ---------------------------------------------------------------------------
#define AOFF_RED 0         // redsum[256] f32 (1KB)
#define AOFF_Q   2048      // Qhi 16K | Qlo 16K                 (end 34816)
#define AOFF_K   34816     // buf s: {Khi 8K | Klo 8K} x2       (end 67584)
#define AOFF_V   67584     // buf s: {Vhi 8K | Vlo 8K} x2       (end 100352)
#define KBUF(s)  (AOFF_K + (s) * 16384)
#define VBUF(s)  (AOFF_V + (s) * 16384)
#define ATT_SMEM 103424    // 1024 hdr + align slack + 100352

#define TM_S(s)  ((s) * 64)
#define TM_PV    128
#define TM_PHI   192
#define TM_PLO   224

__global__ __launch_bounds__(256, 2) void attn_tc(const int* __restrict__ winp) {
#if TC_OK
    extern __shared__ char smem[];
    const uint32_t sb = smem_u32(smem);
    const uint32_t ab = (sb + 1024 + 1023) & 0xFFFFFC00u;
    char* abp = smem + (ab - sb);

    int win = winp[0];
    if (win <= 0 || win > T_) win = 1024;
    const int qt = blockIdx.x, h = blockIdx.y, b = blockIdx.z;
    const int kvh = h >> 2;
    const int q0 = qt * 128;
    const int tid = threadIdx.x, w = tid >> 5, lane = tid & 31;
    const int sp = w & 3;              // TMEM subpartition (HW: warp%4)
    const int hf = w >> 2;             // key half (0 or 1)
    const int kbase = hf * 32;
    const int r = sp * 32 + lane;      // q row within tile
    const int qg = q0 + r;             // global q index
    const uint32_t wo = (uint32_t)sp << 21;   // TMEM subpartition offset

    float* redsum = (float*)(abp + AOFF_RED);

    if (w == 0) { TC_ALLOC(sb, 256); TC_RELINQ(); }
    if (tid == 0) { MBAR_INIT(sb + 8, 1); MBAR_INIT(sb + 16, 1); }
    __syncthreads();
    uint32_t tmem;
    asm volatile("ld.shared.b32 %0, [%1];" : "=r"(tmem) : "r"(sb));

    const __nv_bfloat16* qh  = g_qs_hi  + ((size_t)(b * NH_ + h) * T_ + q0) * HD_;
    const __nv_bfloat16* qlo = g_qs_lo  + ((size_t)(b * NH_ + h) * T_ + q0) * HD_;
    const __nv_bfloat16* kh  = g_ks_hi  + ((size_t)(b * NKV_ + kvh) * T_) * HD_;
    const __nv_bfloat16* kl  = g_ks_lo  + ((size_t)(b * NKV_ + kvh) * T_) * HD_;
    const __nv_bfloat16* vth = g_vts_hi + ((size_t)(b * NKV_ + kvh) * HD_) * T_;
    const __nv_bfloat16* vtl = g_vts_lo + ((size_t)(b * NKV_ + kvh) * HD_) * T_;

    int j0s = q0 - win;
    if (j0s < 0) j0s = 0;
    const int jt0 = j0s >> 6;
    const int jt1 = (q0 + 127) >> 6;   // always >= jt0 + 1

    // per-thread K/V load coordinates: 2 x 16B per component per thread
    const int krr0 = tid >> 3, kc8 = (tid & 7) * 8;          // rows 0..31
    const uint32_t koff0 = SW128((uint32_t)(krr0 * 128 + kc8 * 2));
    const uint32_t koff1 = SW128((uint32_t)((krr0 + 32) * 128 + kc8 * 2));

#define LOAD_K(jt, s)                                                         \
    do {                                                                      \
        const int j0_ = (jt) * 64;                                            \
        uint32_t kb_ = ab + KBUF(s);                                          \
        CP_ASYNC16(kb_ + koff0,        kh + (size_t)(j0_ + krr0) * 64 + kc8); \
        CP_ASYNC16(kb_ + koff1,        kh + (size_t)(j0_ + krr0 + 32) * 64 + kc8); \
        CP_ASYNC16(kb_ + 8192 + koff0, kl + (size_t)(j0_ + krr0) * 64 + kc8); \
        CP_ASYNC16(kb_ + 8192 + koff1, kl + (size_t)(j0_ + krr0 + 32) * 64 + kc8); \
    } while (0)

#define LOAD_V(jt, s)                                                         \
    do {                                                                      \
        const int j0_ = (jt) * 64;                                            \
        uint32_t vb_ = ab + VBUF(s);                                          \
        CP_ASYNC16(vb_ + koff0,        vth + (size_t)krr0 * T_ + j0_ + kc8);  \
        CP_ASYNC16(vb_ + koff1,        vth + (size_t)(krr0 + 32) * T_ + j0_ + kc8); \
        CP_ASYNC16(vb_ + 8192 + koff0, vtl + (size_t)krr0 * T_ + j0_ + kc8);  \
        CP_ASYNC16(vb_ + 8192 + koff1, vtl + (size_t)(krr0 + 32) * T_ + j0_ + kc8); \
    } while (0)

#define ISSUE_S(kbuf_s, tm_s)                                                 \
    do {                                                                      \
        uint64_t dKh = smem_desc_sw128(ab + KBUF(kbuf_s));                    \
        uint64_t dKl = smem_desc_sw128(ab + KBUF(kbuf_s) + 8192);             \
        uint32_t sdst = tmem + TM_S(tm_s);                                    \
        _Pragma("unroll")                                                     \
        for (int kk = 0; kk < 4; kk++)                                        \
            mma_f16_ss(sdst, dQh + kk * 2, dKh + kk * 2, ATT_IDESC, kk > 0);  \
        _Pragma("unroll")                                                     \
        for (int kk = 0; kk < 4; kk++)                                        \
            mma_f16_ss(sdst, dQh + kk * 2, dKl + kk * 2, ATT_IDESC, 1);       \
        _Pragma("unroll")                                                     \
        for (int kk = 0; kk < 4; kk++)                                        \
            mma_f16_ss(sdst, dQl + kk * 2, dKh + kk * 2, ATT_IDESC, 1);       \
    } while (0)

    // ---- prologue ----
#pragma unroll
    for (int v = 0; v < 4; v++) {
        int idx = tid + v * 256;
        int rr = idx >> 3, c8 = idx & 7;
        uint32_t off = SW128((uint32_t)(rr * 128 + c8 * 16));
        *(uint4*)(abp + AOFF_Q + off)         = *(const uint4*)(qh  + rr * 64 + c8 * 8);
        *(uint4*)(abp + AOFF_Q + 16384 + off) = *(const uint4*)(qlo + rr * 64 + c8 * 8);
    }
    LOAD_K(jt0, jt0 & 1);
    LOAD_V(jt0, jt0 & 1);
    CP_COMMIT();
    LOAD_K(jt0 + 1, (jt0 + 1) & 1);    // jt0+1 <= jt1 always
    CP_COMMIT();
    CP_WAIT0();
    __syncthreads();
    const uint64_t dQh = smem_desc_sw128(ab + AOFF_Q);
    const uint64_t dQl = smem_desc_sw128(ab + AOFF_Q + 16384);
    if (w == 0) {
        FENCE_ASYNC();
        if (elect_one()) {
            ISSUE_S(jt0 & 1, jt0 & 1);
            TC_COMMIT(sb + 8);
        }
    }

    float l_loc = 0.f;
    int ps = 0, ppv = 0;
    const float C1 = 0.18033688f;      // 0.125 * log2(e)
    const float C0 = -11.541560f;      // -8 * log2(e)

    for (int jt = jt0; jt <= jt1; jt++) {
        const int sbuf = jt & 1;
        const int j0 = jt * 64;
        // 1. S(jt) done
        mbar_wait(sb + 8, ps & 1); ps++;
        // 2. own K(jt+1) cp.async copies retired (oldest group)
        CP_WAIT1();
        // 3. everyone's K(jt+1) visible; all prior LDTM/STTM done
        __syncthreads();
        TC_FENCE_AFTER();
        // 4. issue S(jt+1) NOW (runs behind PV(jt-1) while we do softmax)
        if (jt < jt1 && w == 0) {
            FENCE_ASYNC();
            if (elect_one()) {
                ISSUE_S(sbuf ^ 1, sbuf ^ 1);
                TC_COMMIT(sb + 8);
            }
        }
        // 5. prefetch K(jt+2) into kbuf[sbuf] (reader S(jt) done)
        {
            int kidx = jt + 2 <= jt1 ? jt + 2 : jt1;
            LOAD_K(kidx, sbuf);
            CP_COMMIT();
        }
        // 6. softmax(jt): p = exp2(s*C1 + C0), masked -> 0
        uint32_t sr[32];
        LDTM_X32(sr, tmem + wo + TM_S(sbuf) + kbase);
        TC_WAIT_LD();
        float p[32];
#pragma unroll
        for (int i = 0; i < 32; i++) {
            int jg = j0 + kbase + i;
            bool ok = (jg <= qg) && (jg >= qg - win);
            float e = ex2_approx(fmaf(__uint_as_float(sr[i]), C1, C0));
            p[i] = ok ? e : 0.f;
            l_loc += p[i];
        }
        // 7. PV(jt-1) done -> P TMEM and V(jt-1) buffer free
        if (jt > jt0) { mbar_wait(sb + 16, ppv & 1); ppv++; TC_FENCE_AFTER(); }
        // 8. store P(jt) into TMEM (warp-local: rows=subpartition, 16 cols)
        {
            uint32_t ph[16], pl[16];
#pragma unroll
            for (int i = 0; i < 16; i++) {
                float pa = p[2 * i], pb = p[2 * i + 1];
                __nv_bfloat162 hh = __floats2bfloat162_rn(pa, pb);
                float la = pa - __bfloat162float(hh.x);
                float lb = pb - __bfloat162float(hh.y);
                __nv_bfloat162 ll = __floats2bfloat162_rn(la, lb);
                ph[i] = b2u(hh);
                pl[i] = b2u(ll);
            }
            STTM_X16(tmem + wo + TM_PHI + hf * 16, ph);
            STTM_X16(tmem + wo + TM_PLO + hf * 16, pl);
            TC_WAIT_ST();
            TC_FENCE_BEFORE();
        }
        // 9. own V(jt) copies retired (oldest group now), prefetch V(jt+1)
        CP_WAIT1();
        {
            int vidx = jt + 1 <= jt1 ? jt + 1 : jt1;
            LOAD_V(vidx, sbuf ^ 1);
            CP_COMMIT();
        }
        // 10. P(jt) TMEM + everyone's V(jt) smem visible block-wide
        __syncthreads();
        // 11. issue PV(jt) in TS mode (A = P in TMEM), accumulate
        if (w == 0) {
            TC_FENCE_AFTER();
            FENCE_ASYNC();
            if (elect_one()) {
                uint64_t dVh = smem_desc_sw128(ab + VBUF(sbuf));
                uint64_t dVl = smem_desc_sw128(ab + VBUF(sbuf) + 8192);
#pragma unroll
                for (int kk = 0; kk < 4; kk++)
                    mma_f16_ts(tmem + TM_PV, tmem + TM_PHI + kk * 8,
                               dVh + kk * 2, ATT_IDESC, (jt > jt0) || (kk > 0));
#pragma unroll
                for (int kk = 0; kk < 4; kk++)
                    mma_f16_ts(tmem + TM_PV, tmem + TM_PHI + kk * 8,
                               dVl + kk * 2, ATT_IDESC, 1);
#pragma unroll
                for (int kk = 0; kk < 4; kk++)
                    mma_f16_ts(tmem + TM_PV, tmem + TM_PLO + kk * 8,
                               dVh + kk * 2, ATT_IDESC, 1);
                TC_COMMIT(sb + 16);
            }
        }
    }
    // drain final PV, combine l halves, write O
    mbar_wait(sb + 16, ppv & 1);
    TC_FENCE_AFTER();
    redsum[r * 2 + hf] = l_loc;
    __syncthreads();
    const float l = redsum[r * 2] + redsum[r * 2 + 1];
    uint32_t pr[32];
    LDTM_X32(pr, tmem + wo + TM_PV + kbase);
    TC_WAIT_LD();
    {
        const float inv = 1.0f / l;
        float* dst = g_y + ((size_t)(b * T_ + qg)) * C_ + h * 64 + kbase;
#pragma unroll
        for (int i = 0; i < 32; i += 4)
            *(float4*)(dst + i) = make_float4(
                __uint_as_float(pr[i]) * inv, __uint_as_float(pr[i + 1]) * inv,
                __uint_as_float(pr[i + 2]) * inv, __uint_as_float(pr[i + 3]) * inv);
    }
    __syncthreads();
    if (w == 0) TC_DEALLOC(tmem, 256);
#undef LOAD_K
#undef LOAD_V
#undef ISSUE_S

#else  // ---------------- SIMT fallback (baseline target, never run) --------
    const int qt = blockIdx.x, h = blockIdx.y, b = blockIdx.z;
    const int kvh = h >> 2;
    int win = winp[0];
    if (win <= 0 || win > T_) win = 1024;
    const int tid = threadIdx.x;
    if (tid < 128) {
        const int qg = qt * 128 + tid;
        const __nv_bfloat16* qh  = g_qs_hi + ((size_t)(b * NH_ + h) * T_ + qg) * HD_;
        const __nv_bfloat16* qlo = g_qs_lo + ((size_t)(b * NH_ + h) * T_ + qg) * HD_;
        float q[64];
        for (int d = 0; d < 64; d++)
            q[d] = __bfloat162float(qh[d]) + __bfloat162float(qlo[d]);
        const __nv_bfloat16* kh  = g_ks_hi  + ((size_t)(b * NKV_ + kvh) * T_) * HD_;
        const __nv_bfloat16* kl  = g_ks_lo  + ((size_t)(b * NKV_ + kvh) * T_) * HD_;
        const __nv_bfloat16* vth = g_vts_hi + ((size_t)(b * NKV_ + kvh) * HD_) * T_;
        const __nv_bfloat16* vtl = g_vts_lo + ((size_t)(b * NKV_ + kvh) * HD_) * T_;
        float l = 0.f, O[64];
        for (int d = 0; d < 64; d++) O[d] = 0.f;
        int js = qg - win;
        if (js < 0) js = 0;
        for (int j = js; j <= qg; j++) {
            float s = 0.f;
            for (int d = 0; d < 64; d++)
                s += q[d] * (__bfloat162float(kh[(size_t)j * 64 + d]) +
                             __bfloat162float(kl[(size_t)j * 64 + d]));
            float p = __expf(s * 0.125f - 8.0f);
            l += p;
            for (int d = 0; d < 64; d++)
                O[d] += p * (__bfloat162float(vth[(size_t)d * T_ + j]) +
                             __bfloat162float(vtl[(size_t)d * T_ + j]));
        }
        float inv = 1.0f / l;
        float* dst = g_y + ((size_t)(b * T_ + qg)) * C_ + h * 64;
        for (int d = 0; d < 64; d++) dst[d] = O[d] * inv;
    }
#endif
}

// ---------------------------------------------------------------------------
// Launch
// ---------------------------------------------------------------------------
extern "C" void kernel_launch(void* const* d_in, const int* in_sizes, int n_in,
                              void* d_out, int out_size) {
    const float* x     = (const float*)d_in[0];
    const float* ve    = (const float*)d_in[1];
    const float* cosb  = (const float*)d_in[2];
    const float* sinb  = (const float*)d_in[3];
    const float* Wq    = (const float*)d_in[4];
    const float* Wk    = (const float*)d_in[5];
    const float* Wv    = (const float*)d_in[6];
    const float* Wproj = (const float*)d_in[7];
    const float* Wgate = (const float*)d_in[8];
    const int*   win   = (const int*)d_in[9];
    float* out = (float*)d_out;

    __nv_bfloat16 *wqkv_hi, *wqkv_lo, *wproj_hi, *wproj_lo;
    float *qkv, *yb;
    cudaGetSymbolAddress((void**)&wqkv_hi, g_wqkv_hi);
    cudaGetSymbolAddress((void**)&wqkv_lo, g_wqkv_lo);
    cudaGetSymbolAddress((void**)&wproj_hi, g_wproj_hi);
    cudaGetSymbolAddress((void**)&wproj_lo, g_wproj_lo);
    cudaGetSymbolAddress((void**)&qkv, g_qkv);
    cudaGetSymbolAddress((void**)&yb, g_y);

    cudaFuncSetAttribute(gemm_split,
                         cudaFuncAttributeMaxDynamicSharedMemorySize, GEMM_SMEM);
    cudaFuncSetAttribute(attn_tc,
                         cudaFuncAttributeMaxDynamicSharedMemorySize, ATT_SMEM);

    // 1. transpose + split all weights (one launch)
    transpose_split_all<<<dim3(80, C_ / 32), dim3(32, 8)>>>(Wq, Wk, Wv, Wproj);
    // 2. fused QKV projection (A = x fp32, split in-kernel)
    gemm_split<<<dim3(NQKV_ / 128, M_ / 128), 256, GEMM_SMEM>>>(
        x, wqkv_hi, wqkv_lo, qkv, NQKV_);
    // 3. gate + RoPE + RMSNorm + bf16 split + layouts
    postproc<<<M_, 256>>>(x, ve, cosb, sinb, Wgate);
    // 4. deep-pipelined tensor-core attention (P in TMEM, 2 CTAs/SM)
    attn_tc<<<dim3(T_ / 128, NH_, B_), 256, ATT_SMEM>>>(win);
    // 5. output projection (A = y fp32, split in-kernel)
    gemm_split<<<dim3(C_ / 128, M_ / 128), 256, GEMM_SMEM>>>(
        yb, wproj_hi, wproj_lo, out, C_);
}

// round 14
// speedup vs baseline: 8.9046x; 1.3596x over previous
#include <cuda_runtime.h>
#include <cuda_bf16.h>
#include <math.h>
#include <stdint.h>

// Problem constants (fixed by the reference)
#define B_  2
#define T_  2048
#define C_  1024
#define NH_ 16
#define NKV_ 4
#define HD_ 64
#define VEC_ 32
#define M_  (B_ * T_)      // 4096 token rows
#define NQKV_ 1536         // fused q(1024) | k(256) | v(256) columns

// tcgen05 is arch-conditional: only in the sm_103a/sm_100a passes. The
// baseline compute_103 target gets SIMT fallback bodies.
#if defined(__CUDA_ARCH_FEAT_SM103_ALL) || defined(__CUDA_ARCH_FEAT_SM100_ALL) || \
    defined(__CUDA_ARCH_FEAT_SM101_ALL)
#define TC_OK 1
#else
#define TC_OK 0
#endif

// ---------------------------------------------------------------------------
// Scratch (static device globals; no runtime allocation allowed)
// ---------------------------------------------------------------------------
__device__ __align__(16) __nv_bfloat16 g_xs_hi[M_ * C_];       // x split
__device__ __align__(16) __nv_bfloat16 g_xs_lo[M_ * C_];
__device__ __align__(16) __nv_bfloat16 g_ys_hi[M_ * C_];       // attn out split
__device__ __align__(16) __nv_bfloat16 g_ys_lo[M_ * C_];
__device__ __align__(16) __nv_bfloat16 g_wqkv_hi[NQKV_ * C_];  // [N,K] transposed
__device__ __align__(16) __nv_bfloat16 g_wqkv_lo[NQKV_ * C_];
__device__ __align__(16) __nv_bfloat16 g_wproj_hi[C_ * C_];    // [N,K] transposed
__device__ __align__(16) __nv_bfloat16 g_wproj_lo[C_ * C_];
__device__ float g_qkv[M_ * NQKV_];        // fused projection output
// attention operands, bf16 hi/lo split
__device__ __align__(16) __nv_bfloat16 g_qs_hi[M_ * NH_ * HD_];   // [B,NH,T,HD]
__device__ __align__(16) __nv_bfloat16 g_qs_lo[M_ * NH_ * HD_];
__device__ __align__(16) __nv_bfloat16 g_ks_hi[M_ * NKV_ * HD_];  // [B,NKV,T,HD]
__device__ __align__(16) __nv_bfloat16 g_ks_lo[M_ * NKV_ * HD_];
__device__ __align__(16) __nv_bfloat16 g_vts_hi[M_ * NKV_ * HD_]; // [B,NKV,HD,T]
__device__ __align__(16) __nv_bfloat16 g_vts_lo[M_ * NKV_ * HD_];

// ---------------------------------------------------------------------------
// PTX helpers
// ---------------------------------------------------------------------------
__device__ __forceinline__ uint32_t smem_u32(const void* p) {
    uint32_t a;
    asm("{ .reg .u64 t; cvta.to.shared.u64 t, %1; cvt.u32.u64 %0, t; }"
        : "=r"(a) : "l"(p));
    return a;
}
__device__ __forceinline__ uint32_t elect_one() {
    uint32_t pred;
    asm volatile("{\n\t.reg .pred p;\n\telect.sync _|p, 0xFFFFFFFF;\n\t"
                 "selp.b32 %0, 1, 0, p;\n\t}" : "=r"(pred));
    return pred;
}
#define TC_ALLOC(sm, n)   asm volatile("tcgen05.alloc.cta_group::1.sync.aligned.shared::cta.b32 [%0], %1;" :: "r"(sm), "r"((uint32_t)(n)) : "memory")
#define TC_DEALLOC(t, n)  asm volatile("tcgen05.dealloc.cta_group::1.sync.aligned.b32 %0, %1;" :: "r"(t), "r"((uint32_t)(n)))
#define TC_RELINQ()       asm volatile("tcgen05.relinquish_alloc_permit.cta_group::1.sync.aligned;")
#define TC_COMMIT(mbar)   asm volatile("tcgen05.commit.cta_group::1.mbarrier::arrive::one.shared::cluster.b64 [%0];" :: "r"(mbar) : "memory")
#define TC_FENCE_AFTER()  asm volatile("tcgen05.fence::after_thread_sync;" ::: "memory")
#define TC_FENCE_BEFORE() asm volatile("tcgen05.fence::before_thread_sync;" ::: "memory")
#define TC_WAIT_LD()      asm volatile("tcgen05.wait::ld.sync.aligned;" ::: "memory")
#define TC_WAIT_ST()      asm volatile("tcgen05.wait::st.sync.aligned;" ::: "memory")
#define MBAR_INIT(sm, n)  asm volatile("mbarrier.init.shared.b64 [%0], %1;" :: "r"(sm), "r"((uint32_t)(n)) : "memory")
#define FENCE_ASYNC()     asm volatile("fence.proxy.async.shared::cta;" ::: "memory")
#define CP_ASYNC16(dst, src) asm volatile("cp.async.cg.shared.global [%0], [%1], 16;" :: "r"(dst), "l"(src) : "memory")
#define CP_COMMIT()       asm volatile("cp.async.commit_group;" ::: "memory")
#define CP_WAIT0()        asm volatile("cp.async.wait_group 0;" ::: "memory")
#define CP_WAIT1()        asm volatile("cp.async.wait_group 1;" ::: "memory")

__device__ __forceinline__ void mbar_wait(uint32_t mbar, uint32_t parity) {
    asm volatile(
        "{\n\t.reg .pred P;\n\t"
        "W%=:\n\t"
        "mbarrier.try_wait.parity.acquire.cta.shared::cta.b64 P, [%0], %1, 0x989680;\n\t"
        "@P bra D%=;\n\t"
        "bra W%=;\n\t"
        "D%=:\n\t}"
        :: "r"(mbar), "r"(parity) : "memory");
}
__device__ __forceinline__ float ex2_approx(float x) {
    float r;
    asm("ex2.approx.ftz.f32 %0, %1;" : "=f"(r) : "f"(x));
    return r;
}

#if TC_OK
// SS-mode bf16 MMA, cta_group::1, fp32 accum
__device__ __forceinline__ void mma_f16_ss(uint32_t d, uint64_t a, uint64_t b,
                                           uint32_t idesc, uint32_t en) {
    asm volatile(
        "{\n\t.reg .pred p;\n\t"
        "setp.ne.u32 p, %4, 0;\n\t"
        "tcgen05.mma.cta_group::1.kind::f16 [%0], %1, %2, %3, {%5, %5, %5, %5}, p;\n\t"
        "}"
        :: "r"(d), "l"(a), "l"(b), "r"(idesc), "r"(en), "r"(0u)
        : "memory");
}
// TS-mode bf16 MMA: A in TMEM, B in SMEM
__device__ __forceinline__ void mma_f16_ts(uint32_t d, uint32_t a, uint64_t b,
                                           uint32_t idesc, uint32_t en) {
    asm volatile(
        "{\n\t.reg .pred p;\n\t"
        "setp.ne.u32 p, %4, 0;\n\t"
        "tcgen05.mma.cta_group::1.kind::f16 [%0], [%1], %2, %3, {%5, %5, %5, %5}, p;\n\t"
        "}"
        :: "r"(d), "r"(a), "l"(b), "r"(idesc), "r"(en), "r"(0u)
        : "memory");
}

#define LDTM_X32(r, addr) \
    asm volatile( \
        "tcgen05.ld.sync.aligned.32x32b.x32.b32 " \
        "{%0, %1, %2, %3, %4, %5, %6, %7, " \
        " %8, %9, %10, %11, %12, %13, %14, %15, " \
        " %16, %17, %18, %19, %20, %21, %22, %23, " \
        " %24, %25, %26, %27, %28, %29, %30, %31}, [%32];" \
        : "=r"((r)[0]),  "=r"((r)[1]),  "=r"((r)[2]),  "=r"((r)[3]), \
          "=r"((r)[4]),  "=r"((r)[5]),  "=r"((r)[6]),  "=r"((r)[7]), \
          "=r"((r)[8]),  "=r"((r)[9]),  "=r"((r)[10]), "=r"((r)[11]), \
          "=r"((r)[12]), "=r"((r)[13]), "=r"((r)[14]), "=r"((r)[15]), \
          "=r"((r)[16]), "=r"((r)[17]), "=r"((r)[18]), "=r"((r)[19]), \
          "=r"((r)[20]), "=r"((r)[21]), "=r"((r)[22]), "=r"((r)[23]), \
          "=r"((r)[24]), "=r"((r)[25]), "=r"((r)[26]), "=r"((r)[27]), \
          "=r"((r)[28]), "=r"((r)[29]), "=r"((r)[30]), "=r"((r)[31]) \
        : "r"(addr))

#define STTM_X16(addr, r) \
    asm volatile( \
        "tcgen05.st.sync.aligned.32x32b.x16.b32 [%0], " \
        "{%1, %2, %3, %4, %5, %6, %7, %8, " \
        " %9, %10, %11, %12, %13, %14, %15, %16};" \
        :: "r"(addr), \
           "r"((r)[0]),  "r"((r)[1]),  "r"((r)[2]),  "r"((r)[3]), \
           "r"((r)[4]),  "r"((r)[5]),  "r"((r)[6]),  "r"((r)[7]), \
           "r"((r)[8]),  "r"((r)[9]),  "r"((r)[10]), "r"((r)[11]), \
           "r"((r)[12]), "r"((r)[13]), "r"((r)[14]), "r"((r)[15]) \
        : "memory")
#endif  // TC_OK

// 64-bit SMEM descriptor: SW128, version=1 (Blackwell), LBO=1, SBO=64
static __device__ __forceinline__ uint64_t smem_desc_sw128(uint32_t addr) {
    const uint64_t base =
        (uint64_t(2)  << 61) | (uint64_t(1) << 46) |
        (uint64_t(64) << 32) | (uint64_t(1) << 16);
    return base | ((uint64_t)(addr >> 4) & 0x3FFF);
}
#define SW128(off) ((off) ^ (((off) >> 3) & 0x70))

// idesc: dtype=F32, atype=BF16, btype=BF16 (K-major both)
#define GEMM_IDESC ((1u << 4) | (1u << 7) | (1u << 10) | ((128u / 8) << 17) | ((128u / 16) << 24))
#define ATT_IDESC  ((1u << 4) | (1u << 7) | (1u << 10) | ((64u / 8) << 17) | ((128u / 16) << 24))

__device__ __forceinline__ uint32_t b2u(__nv_bfloat162 v) {
    return *(uint32_t*)&v;
}

// ---------------------------------------------------------------------------
// fp32 -> (hi, lo) bf16 split, elementwise (for x).
// ---------------------------------------------------------------------------
__global__ __launch_bounds__(256) void split_fp32(
    const float* __restrict__ src, __nv_bfloat16* __restrict__ hi,
    __nv_bfloat16* __restrict__ lo, int n) {
    int i = blockIdx.x * 256 + threadIdx.x;
    if (i < n) {
        float v = src[i];
        __nv_bfloat16 h = __float2bfloat16(v);
        hi[i] = h;
        lo[i] = __float2bfloat16(v - __bfloat162float(h));
    }
}

// ---------------------------------------------------------------------------
// Combined weight transpose + hi/lo split.
// ---------------------------------------------------------------------------
__global__ __launch_bounds__(256) void transpose_split_all(
    const float* __restrict__ Wq, const float* __restrict__ Wk,
    const float* __restrict__ Wv, const float* __restrict__ Wp) {
    __shared__ float t[32][33];
    const int ct = blockIdx.x;
    const float* W;
    __nv_bfloat16 *hi, *lo;
    int Ncols, nb;
    if (ct < 32)      { W = Wq; hi = g_wqkv_hi;                     lo = g_wqkv_lo;                     Ncols = 1024; nb = ct * 32; }
    else if (ct < 40) { W = Wk; hi = g_wqkv_hi + (size_t)1024 * C_; lo = g_wqkv_lo + (size_t)1024 * C_; Ncols = 256;  nb = (ct - 32) * 32; }
    else if (ct < 48) { W = Wv; hi = g_wqkv_hi + (size_t)1280 * C_; lo = g_wqkv_lo + (size_t)1280 * C_; Ncols = 256;  nb = (ct - 40) * 32; }
    else              { W = Wp; hi = g_wproj_hi;                    lo = g_wproj_lo;                    Ncols = 1024; nb = (ct - 48) * 32; }
    const int kb = blockIdx.y * 32;
    const int tx = threadIdx.x, ty = threadIdx.y;
#pragma unroll
    for (int j = 0; j < 32; j += 8)
        t[ty + j][tx] = W[(size_t)(kb + ty + j) * Ncols + nb + tx];
    __syncthreads();
#pragma unroll
    for (int j = 0; j < 32; j += 8) {
        float v = t[tx][ty + j];
        __nv_bfloat16 h = __float2bfloat16(v);
        size_t o = (size_t)(nb + ty + j) * C_ + kb + tx;
        hi[o] = h;
        lo[o] = __float2bfloat16(v - __bfloat162float(h));
    }
}

// ---------------------------------------------------------------------------
// Split-bf16 GEMM: C[M,N] = (Ahi+Alo)[M,K] . (Bhi+Blo)[N,K]^T, 3-term.
// ALL operands pre-split bf16; loads via cp.async (no register staging, no
// conversion in the mainloop). 128x128 tile, K-chunk 64, 2-stage pipeline:
// per iter: wait MMA(i-1) -> cp.async group(i+1) -> wait_group(i) -> sync ->
// issue MMA(i). MMA-paced (~850 cyc/chunk).
// grid = (N/128, M/128), 256 threads.
// ---------------------------------------------------------------------------
#define KCHUNK   64
#define NCHUNKS  (C_ / KCHUNK)           // 16
#define BUFSZ    16384                   // 128 rows x 128 bytes
#define STAGESZ  (4 * BUFSZ)             // Ahi | Alo | Bhi | Blo
#define GEMM_SMEM (2048 + 2 * STAGESZ)

__global__ __launch_bounds__(256) void gemm_split(
    const __nv_bfloat16* __restrict__ Ahi, const __nv_bfloat16* __restrict__ Alo,
    const __nv_bfloat16* __restrict__ Bhi, const __nv_bfloat16* __restrict__ Blo,
    float* __restrict__ C, int N) {
#if TC_OK
    extern __shared__ char smem[];
    const uint32_t sb = smem_u32(smem);
    const uint32_t ab = (sb + 1024 + 1023) & 0xFFFFFC00u;
    const int tid = threadIdx.x;
    const int wid = tid >> 5;
    const int lane = tid & 31;
    const int bm = blockIdx.y * 128;
    const int bn = blockIdx.x * 128;
    const int K = C_;

    if (wid == 0) TC_ALLOC(sb, 128);
    if (tid == 0) { MBAR_INIT(sb + 8, 1); MBAR_INIT(sb + 16, 1); }
    __syncthreads();
    uint32_t tmem;
    asm volatile("ld.shared.b32 %0, [%1];" : "=r"(tmem) : "r"(sb));

    // per-thread line coordinates: 4 lines per buffer (idx = tid + v*256)
#define LOAD_CHUNK(kc, s)                                                     \
    do {                                                                      \
        const int k0 = (kc) * KCHUNK;                                         \
        uint32_t st = ab + (s) * STAGESZ;                                     \
        _Pragma("unroll")                                                     \
        for (int v = 0; v < 4; v++) {                                         \
            int idx = tid + v * 256;                                          \
            int r = idx >> 3, c8 = idx & 7;                                   \
            uint32_t off = SW128((uint32_t)(r * 128 + c8 * 16));              \
            size_t ga = (size_t)(bm + r) * K + k0 + c8 * 8;                   \
            size_t gb = (size_t)(bn + r) * K + k0 + c8 * 8;                   \
            CP_ASYNC16(st + off,              Ahi + ga);                      \
            CP_ASYNC16(st + BUFSZ + off,      Alo + ga);                      \
            CP_ASYNC16(st + 2 * BUFSZ + off,  Bhi + gb);                      \
            CP_ASYNC16(st + 3 * BUFSZ + off,  Blo + gb);                      \
        }                                                                     \
        CP_COMMIT();                                                          \
    } while (0)

    LOAD_CHUNK(0, 0);
    int p0 = 0, p1 = 0;

    for (int i = 0; i < NCHUNKS; i++) {
        const int s = i & 1;
        if (i + 1 < NCHUNKS) {
            const int s2 = (i + 1) & 1;
            if (i >= 1) {   // MMA(i-1) done -> stage s2 (chunk i-1) reusable
                if (s2 == 0) { mbar_wait(sb + 8,  p0 & 1); p0++; }
                else         { mbar_wait(sb + 16, p1 & 1); p1++; }
            }
            LOAD_CHUNK(i + 1, s2);
            CP_WAIT1();     // retire group i (chunk i data resident)
        } else {
            CP_WAIT0();     // last chunk
        }
        __syncthreads();    // all threads' chunk-i copies visible
        if (wid == 0) {
            FENCE_ASYNC();
            if (elect_one()) {
                uint32_t base = ab + s * STAGESZ;
                uint64_t dah = smem_desc_sw128(base);
                uint64_t dal = smem_desc_sw128(base + BUFSZ);
                uint64_t dbh = smem_desc_sw128(base + 2 * BUFSZ);
                uint64_t dbl = smem_desc_sw128(base + 3 * BUFSZ);
#pragma unroll
                for (int kk = 0; kk < 4; kk++)
                    mma_f16_ss(tmem, dah + kk * 2, dbh + kk * 2, GEMM_IDESC,
                               (i > 0) || (kk > 0));
#pragma unroll
                for (int kk = 0; kk < 4; kk++)
                    mma_f16_ss(tmem, dah + kk * 2, dbl + kk * 2, GEMM_IDESC, 1);
#pragma unroll
                for (int kk = 0; kk < 4; kk++)
                    mma_f16_ss(tmem, dal + kk * 2, dbh + kk * 2, GEMM_IDESC, 1);
                TC_COMMIT(sb + 8 + s * 8);
            }
        }
    }
    {
        const int sl = (NCHUNKS - 1) & 1;
        if (sl == 0) mbar_wait(sb + 8, p0 & 1);
        else         mbar_wait(sb + 16, p1 & 1);
    }
    TC_FENCE_AFTER();

    {
        const int sp = wid & 3;
        const int colbase = (wid >> 2) * 64;
        const uint32_t wo = (uint32_t)sp << 21;
        uint32_t d0[32], d1[32];
        LDTM_X32(d0, tmem + wo + colbase);
        LDTM_X32(d1, tmem + wo + colbase + 32);
        TC_WAIT_LD();
        const int row = bm + sp * 32 + lane;
        float* dst = C + (size_t)row * N + bn + colbase;
#pragma unroll
        for (int c = 0; c < 32; c += 4) {
            *(float4*)(dst + c) = make_float4(
                __uint_as_float(d0[c]), __uint_as_float(d0[c + 1]),
                __uint_as_float(d0[c + 2]), __uint_as_float(d0[c + 3]));
            *(float4*)(dst + 32 + c) = make_float4(
                __uint_as_float(d1[c]), __uint_as_float(d1[c + 1]),
                __uint_as_float(d1[c + 2]), __uint_as_float(d1[c + 3]));
        }
    }
    __syncthreads();
    if (wid == 0) TC_DEALLOC(tmem, 128);
#undef LOAD_CHUNK

#else  // SIMT fallback
    __shared__ float As[8][128];
    __shared__ float Bs[8][128];
    const int tid = threadIdx.x;
    const int bm = blockIdx.y * 128;
    const int bn = blockIdx.x * 128;
    const int K = C_;
    const int ldRow = tid >> 1;
    const int ldK   = (tid & 1) * 4;
    const int ri = (tid >> 4) * 4;
    const int ci = (tid & 15) * 4;

    float acc[8][8];
#pragma unroll
    for (int i = 0; i < 8; i++)
#pragma unroll
        for (int j = 0; j < 8; j++) acc[i][j] = 0.f;

    for (int k0 = 0; k0 < K; k0 += 8) {
#pragma unroll
        for (int c = 0; c < 4; c++) {
            size_t ga = (size_t)(bm + ldRow) * K + k0 + ldK + c;
            size_t gb = (size_t)(bn + ldRow) * K + k0 + ldK + c;
            As[ldK + c][ldRow] = __bfloat162float(Ahi[ga]) + __bfloat162float(Alo[ga]);
            Bs[ldK + c][ldRow] = __bfloat162float(Bhi[gb]) + __bfloat162float(Blo[gb]);
        }
        __syncthreads();
#pragma unroll
        for (int kk = 0; kk < 8; kk++) {
            float ar[8], br[8];
#pragma unroll
            for (int i = 0; i < 4; i++) {
                ar[i] = As[kk][ri + i];
                ar[i + 4] = As[kk][ri + 64 + i];
                br[i] = Bs[kk][ci + i];
                br[i + 4] = Bs[kk][ci + 64 + i];
            }
#pragma unroll
            for (int i = 0; i < 8; i++)
#pragma unroll
                for (int j = 0; j < 8; j++) acc[i][j] += ar[i] * br[j];
        }
        __syncthreads();
    }
#pragma unroll
    for (int ib = 0; ib < 2; ib++)
#pragma unroll
        for (int i = 0; i < 4; i++) {
            int row = bm + ib * 64 + ri + i;
#pragma unroll
            for (int jb = 0; jb < 2; jb++)
#pragma unroll
                for (int j = 0; j < 4; j++)
                    C[(size_t)row * N + bn + jb * 64 + ci + j] =
                        acc[ib * 4 + i][jb * 4 + j];
        }
#endif
}

// ---------------------------------------------------------------------------
// Per-token post-process (unchanged).
// ---------------------------------------------------------------------------
__global__ __launch_bounds__(256) void postproc(
    const float* __restrict__ x, const float* __restrict__ ve,
    const float* __restrict__ cosb, const float* __restrict__ sinb,
    const float* __restrict__ Wgate) {
    const int bt = blockIdx.x;
    const int b = bt / T_, t = bt % T_;
    const int tid = threadIdx.x;
    const int lane = tid & 31, w = tid >> 5;
    __shared__ float s_gate[NKV_];

    if (w < NKV_) {
        float p = x[(size_t)bt * C_ + lane] * Wgate[lane * NKV_ + w];
#pragma unroll
        for (int o = 16; o; o >>= 1) p += __shfl_xor_sync(0xffffffffu, p, o);
        if (lane == 0) s_gate[w] = 2.0f / (1.0f + expf(-p));
    }
    __syncthreads();

    const float c = cosb[t * (HD_ / 2) + lane];
    const float s = sinb[t * (HD_ / 2) + lane];
    const float* qkvrow = g_qkv + (size_t)bt * NQKV_;
    for (int row = w; row < NH_ + NKV_; row += 8) {
        const float* src;
        __nv_bfloat16 *dhi, *dlo;
        if (row < NH_) {
            src = qkvrow + row * HD_;
            size_t base = ((size_t)(b * NH_ + row) * T_ + t) * HD_;
            dhi = g_qs_hi + base;
            dlo = g_qs_lo + base;
        } else {
            int kh = row - NH_;
            src = qkvrow + 1024 + kh * HD_;
            size_t base = ((size_t)(b * NKV_ + kh) * T_ + t) * HD_;
            dhi = g_ks_hi + base;
            dlo = g_ks_lo + base;
        }
        float x1 = src[lane], x2 = src[lane + 32];
        float o1 = x1 * c + x2 * s;
        float o2 = -x1 * s + x2 * c;
        float sq = o1 * o1 + o2 * o2;
#pragma unroll
        for (int o = 16; o; o >>= 1) sq += __shfl_xor_sync(0xffffffffu, sq, o);
        float scale = rsqrtf(sq * (1.0f / HD_) + 1.1920929e-7f);
        float v1 = o1 * scale, v2 = o2 * scale;
        __nv_bfloat16 h1 = __float2bfloat16(v1);
        __nv_bfloat16 h2 = __float2bfloat16(v2);
        dhi[lane] = h1;
        dhi[lane + 32] = h2;
        dlo[lane] = __float2bfloat16(v1 - __bfloat162float(h1));
        dlo[lane + 32] = __float2bfloat16(v2 - __bfloat162float(h2));
    }

    {
        int h = tid >> 6, d = tid & 63;
        float val = qkvrow[1280 + tid] +
                    s_gate[h] * ve[(size_t)bt * (NKV_ * HD_) + tid];
        size_t o = ((size_t)(b * NKV_ + h) * HD_ + d) * T_ + t;  // transposed
        __nv_bfloat16 hh = __float2bfloat16(val);
        g_vts_hi[o] = hh;
        g_vts_lo[o] = __float2bfloat16(val - __bfloat162float(hh));
    }
}

// ---------------------------------------------------------------------------
// tcgen05 sliding-window flash attention (unchanged from round 13 except the
// epilogue now writes ys hi/lo bf16 directly).
// ---------------------------------------------------------------------------
#define AOFF_RED 0         // redsum[256] f32 (1KB)
#define AOFF_Q   2048      // Qhi 16K | Qlo 16K                 (end 34816)
#define AOFF_K   34816     // buf s: {Khi 8K | Klo 8K} x2       (end 67584)
#define AOFF_V   67584     // buf s: {Vhi 8K | Vlo 8K} x2       (end 100352)
#define KBUF(s)  (AOFF_K + (s) * 16384)
#define VBUF(s)  (AOFF_V + (s) * 16384)
#define ATT_SMEM 103424    // 1024 hdr + align slack + 100352

#define TM_S(s)  ((s) * 64)
#define TM_PV    128
#define TM_PHI   192
#define TM_PLO   224

__global__ __launch_bounds__(256, 2) void attn_tc(const int* __restrict__ winp) {
#if TC_OK
    extern __shared__ char smem[];
    const uint32_t sb = smem_u32(smem);
    const uint32_t ab = (sb + 1024 + 1023) & 0xFFFFFC00u;
    char* abp = smem + (ab - sb);

    int win = winp[0];
    if (win <= 0 || win > T_) win = 1024;
    const int qt = blockIdx.x, h = blockIdx.y, b = blockIdx.z;
    const int kvh = h >> 2;
    const int q0 = qt * 128;
    const int tid = threadIdx.x, w = tid >> 5, lane = tid & 31;
    const int sp = w & 3;              // TMEM subpartition
    const int hf = w >> 2;             // key half (0 or 1)
    const int kbase = hf * 32;
    const int r = sp * 32 + lane;      // q row within tile
    const int qg = q0 + r;             // global q index
    const uint32_t wo = (uint32_t)sp << 21;

    float* redsum = (float*)(abp + AOFF_RED);

    if (w == 0) { TC_ALLOC(sb, 256); TC_RELINQ(); }
    if (tid == 0) { MBAR_INIT(sb + 8, 1); MBAR_INIT(sb + 16, 1); }
    __syncthreads();
    uint32_t tmem;
    asm volatile("ld.shared.b32 %0, [%1];" : "=r"(tmem) : "r"(sb));

    const __nv_bfloat16* qh  = g_qs_hi  + ((size_t)(b * NH_ + h) * T_ + q0) * HD_;
    const __nv_bfloat16* qlo = g_qs_lo  + ((size_t)(b * NH_ + h) * T_ + q0) * HD_;
    const __nv_bfloat16* kh  = g_ks_hi  + ((size_t)(b * NKV_ + kvh) * T_) * HD_;
    const __nv_bfloat16* kl  = g_ks_lo  + ((size_t)(b * NKV_ + kvh) * T_) * HD_;
    const __nv_bfloat16* vth = g_vts_hi + ((size_t)(b * NKV_ + kvh) * HD_) * T_;
    const __nv_bfloat16* vtl = g_vts_lo + ((size_t)(b * NKV_ + kvh) * HD_) * T_;

    int j0s = q0 - win;
    if (j0s < 0) j0s = 0;
    const int jt0 = j0s >> 6;
    const int jt1 = (q0 + 127) >> 6;   // always >= jt0 + 1

    const int krr0 = tid >> 3, kc8 = (tid & 7) * 8;
    const uint32_t koff0 = SW128((uint32_t)(krr0 * 128 + kc8 * 2));
    const uint32_t koff1 = SW128((uint32_t)((krr0 + 32) * 128 + kc8 * 2));

#define LOAD_K(jt, s)                                                         \
    do {                                                                      \
        const int j0_ = (jt) * 64;                                            \
        uint32_t kb_ = ab + KBUF(s);                                          \
        CP_ASYNC16(kb_ + koff0,        kh + (size_t)(j0_ + krr0) * 64 + kc8); \
        CP_ASYNC16(kb_ + koff1,        kh + (size_t)(j0_ + krr0 + 32) * 64 + kc8); \
        CP_ASYNC16(kb_ + 8192 + koff0, kl + (size_t)(j0_ + krr0) * 64 + kc8); \
        CP_ASYNC16(kb_ + 8192 + koff1, kl + (size_t)(j0_ + krr0 + 32) * 64 + kc8); \
    } while (0)

#define LOAD_V(jt, s)                                                         \
    do {                                                                      \
        const int j0_ = (jt) * 64;                                            \
        uint32_t vb_ = ab + VBUF(s);                                          \
        CP_ASYNC16(vb_ + koff0,        vth + (size_t)krr0 * T_ + j0_ + kc8);  \
        CP_ASYNC16(vb_ + koff1,        vth + (size_t)(krr0 + 32) * T_ + j0_ + kc8); \
        CP_ASYNC16(vb_ + 8192 + koff0, vtl + (size_t)krr0 * T_ + j0_ + kc8);  \
        CP_ASYNC16(vb_ + 8192 + koff1, vtl + (size_t)(krr0 + 32) * T_ + j0_ + kc8); \
    } while (0)

#define ISSUE_S(kbuf_s, tm_s)                                                 \
    do {                                                                      \
        uint64_t dKh = smem_desc_sw128(ab + KBUF(kbuf_s));                    \
        uint64_t dKl = smem_desc_sw128(ab + KBUF(kbuf_s) + 8192);             \
        uint32_t sdst = tmem + TM_S(tm_s);                                    \
        _Pragma("unroll")                                                     \
        for (int kk = 0; kk < 4; kk++)                                        \
            mma_f16_ss(sdst, dQh + kk * 2, dKh + kk * 2, ATT_IDESC, kk > 0);  \
        _Pragma("unroll")                                                     \
        for (int kk = 0; kk < 4; kk++)                                        \
            mma_f16_ss(sdst, dQh + kk * 2, dKl + kk * 2, ATT_IDESC, 1);       \
        _Pragma("unroll")                                                     \
        for (int kk = 0; kk < 4; kk++)                                        \
            mma_f16_ss(sdst, dQl + kk * 2, dKh + kk * 2, ATT_IDESC, 1);       \
    } while (0)

    // ---- prologue ----
#pragma unroll
    for (int v = 0; v < 4; v++) {
        int idx = tid + v * 256;
        int rr = idx >> 3, c8 = idx & 7;
        uint32_t off = SW128((uint32_t)(rr * 128 + c8 * 16));
        *(uint4*)(abp + AOFF_Q + off)         = *(const uint4*)(qh  + rr * 64 + c8 * 8);
        *(uint4*)(abp + AOFF_Q + 16384 + off) = *(const uint4*)(qlo + rr * 64 + c8 * 8);
    }
    LOAD_K(jt0, jt0 & 1);
    LOAD_V(jt0, jt0 & 1);
    CP_COMMIT();
    LOAD_K(jt0 + 1, (jt0 + 1) & 1);
    CP_COMMIT();
    CP_WAIT0();
    __syncthreads();
    const uint64_t dQh = smem_desc_sw128(ab + AOFF_Q);
    const uint64_t dQl = smem_desc_sw128(ab + AOFF_Q + 16384);
    if (w == 0) {
        FENCE_ASYNC();
        if (elect_one()) {
            ISSUE_S(jt0 & 1, jt0 & 1);
            TC_COMMIT(sb + 8);
        }
    }

    float l_loc = 0.f;
    int ps = 0, ppv = 0;
    const float C1 = 0.18033688f;      // 0.125 * log2(e)
    const float C0 = -11.541560f;      // -8 * log2(e)

    for (int jt = jt0; jt <= jt1; jt++) {
        const int sbuf = jt & 1;
        const int j0 = jt * 64;
        mbar_wait(sb + 8, ps & 1); ps++;
        CP_WAIT1();
        __syncthreads();
        TC_FENCE_AFTER();
        if (jt < jt1 && w == 0) {
            FENCE_ASYNC();
            if (elect_one()) {
                ISSUE_S(sbuf ^ 1, sbuf ^ 1);
                TC_COMMIT(sb + 8);
            }
        }
        {
            int kidx = jt + 2 <= jt1 ? jt + 2 : jt1;
            LOAD_K(kidx, sbuf);
            CP_COMMIT();
        }
        uint32_t sr[32];
        LDTM_X32(sr, tmem + wo + TM_S(sbuf) + kbase);
        TC_WAIT_LD();
        float p[32];
#pragma unroll
        for (int i = 0; i < 32; i++) {
            int jg = j0 + kbase + i;
            bool ok = (jg <= qg) && (jg >= qg - win);
            float e = ex2_approx(fmaf(__uint_as_float(sr[i]), C1, C0));
            p[i] = ok ? e : 0.f;
            l_loc += p[i];
        }
        if (jt > jt0) { mbar_wait(sb + 16, ppv & 1); ppv++; TC_FENCE_AFTER(); }
        {
            uint32_t ph[16], pl[16];
#pragma unroll
            for (int i = 0; i < 16; i++) {
                float pa = p[2 * i], pb = p[2 * i + 1];
                __nv_bfloat162 hh = __floats2bfloat162_rn(pa, pb);
                float la = pa - __bfloat162float(hh.x);
                float lb = pb - __bfloat162float(hh.y);
                __nv_bfloat162 ll = __floats2bfloat162_rn(la, lb);
                ph[i] = b2u(hh);
                pl[i] = b2u(ll);
            }
            STTM_X16(tmem + wo + TM_PHI + hf * 16, ph);
            STTM_X16(tmem + wo + TM_PLO + hf * 16, pl);
            TC_WAIT_ST();
            TC_FENCE_BEFORE();
        }
        CP_WAIT1();
        {
            int vidx = jt + 1 <= jt1 ? jt + 1 : jt1;
            LOAD_V(vidx, sbuf ^ 1);
            CP_COMMIT();
        }
        __syncthreads();
        if (w == 0) {
            TC_FENCE_AFTER();
            FENCE_ASYNC();
            if (elect_one()) {
                uint64_t dVh = smem_desc_sw128(ab + VBUF(sbuf));
                uint64_t dVl = smem_desc_sw128(ab + VBUF(sbuf) + 8192);
#pragma unroll
                for (int kk = 0; kk < 4; kk++)
                    mma_f16_ts(tmem + TM_PV, tmem + TM_PHI + kk * 8,
                               dVh + kk * 2, ATT_IDESC, (jt > jt0) || (kk > 0));
#pragma unroll
                for (int kk = 0; kk < 4; kk++)
                    mma_f16_ts(tmem + TM_PV, tmem + TM_PHI + kk * 8,
                               dVl + kk * 2, ATT_IDESC, 1);
#pragma unroll
                for (int kk = 0; kk < 4; kk++)
                    mma_f16_ts(tmem + TM_PV, tmem + TM_PLO + kk * 8,
                               dVh + kk * 2, ATT_IDESC, 1);
                TC_COMMIT(sb + 16);
            }
        }
    }
    // drain final PV, combine l halves, write ys hi/lo (bf16 split)
    mbar_wait(sb + 16, ppv & 1);
    TC_FENCE_AFTER();
    redsum[r * 2 + hf] = l_loc;
    __syncthreads();
    const float l = redsum[r * 2] + redsum[r * 2 + 1];
    uint32_t pr[32];
    LDTM_X32(pr, tmem + wo + TM_PV + kbase);
    TC_WAIT_LD();
    {
        const float inv = 1.0f / l;
        size_t orow = ((size_t)(b * T_ + qg)) * C_ + h * 64 + kbase;
#pragma unroll
        for (int i = 0; i < 16; i++) {
            float va = __uint_as_float(pr[2 * i]) * inv;
            float vb = __uint_as_float(pr[2 * i + 1]) * inv;
            __nv_bfloat162 hh = __floats2bfloat162_rn(va, vb);
            float la = va - __bfloat162float(hh.x);
            float lb = vb - __bfloat162float(hh.y);
            __nv_bfloat162 ll = __floats2bfloat162_rn(la, lb);
            *(uint32_t*)(g_ys_hi + orow + 2 * i) = b2u(hh);
            *(uint32_t*)(g_ys_lo + orow + 2 * i) = b2u(ll);
        }
    }
    __syncthreads();
    if (w == 0) TC_DEALLOC(tmem, 256);
#undef LOAD_K
#undef LOAD_V
#undef ISSUE_S

#else  // ---------------- SIMT fallback (baseline target, never run) --------
    const int qt = blockIdx.x, h = blockIdx.y, b = blockIdx.z;
    const int kvh = h >> 2;
    int win = winp[0];
    if (win <= 0 || win > T_) win = 1024;
    const int tid = threadIdx.x;
    if (tid < 128) {
        const int qg = qt * 128 + tid;
        const __nv_bfloat16* qh  = g_qs_hi + ((size_t)(b * NH_ + h) * T_ + qg) * HD_;
        const __nv_bfloat16* qlo = g_qs_lo + ((size_t)(b * NH_ + h) * T_ + qg) * HD_;
        float q[64];
        for (int d = 0; d < 64; d++)
            q[d] = __bfloat162float(qh[d]) + __bfloat162float(qlo[d]);
        const __nv_bfloat16* kh  = g_ks_hi  + ((size_t)(b * NKV_ + kvh) * T_) * HD_;
        const __nv_bfloat16* kl  = g_ks_lo  + ((size_t)(b * NKV_ + kvh) * T_) * HD_;
        const __nv_bfloat16* vth = g_vts_hi + ((size_t)(b * NKV_ + kvh) * HD_) * T_;
        const __nv_bfloat16* vtl = g_vts_lo + ((size_t)(b * NKV_ + kvh) * HD_) * T_;
        float l = 0.f, O[64];
        for (int d = 0; d < 64; d++) O[d] = 0.f;
        int js = qg - win;
        if (js < 0) js = 0;
        for (int j = js; j <= qg; j++) {
            float s = 0.f;
            for (int d = 0; d < 64; d++)
                s += q[d] * (__bfloat162float(kh[(size_t)j * 64 + d]) +
                             __bfloat162float(kl[(size_t)j * 64 + d]));
            float p = __expf(s * 0.125f - 8.0f);
            l += p;
            for (int d = 0; d < 64; d++)
                O[d] += p * (__bfloat162float(vth[(size_t)d * T_ + j]) +
                             __bfloat162float(vtl[(size_t)d * T_ + j]));
        }
        float inv = 1.0f / l;
        size_t orow = ((size_t)(b * T_ + qg)) * C_ + h * 64;
        for (int d = 0; d < 64; d++) {
            float vO = O[d] * inv;
            __nv_bfloat16 hh = __float2bfloat16(vO);
            g_ys_hi[orow + d] = hh;
            g_ys_lo[orow + d] = __float2bfloat16(vO - __bfloat162float(hh));
        }
    }
#endif
}

// ---------------------------------------------------------------------------
// Launch
// ---------------------------------------------------------------------------
extern "C" void kernel_launch(void* const* d_in, const int* in_sizes, int n_in,
                              void* d_out, int out_size) {
    const float* x     = (const float*)d_in[0];
    const float* ve    = (const float*)d_in[1];
    const float* cosb  = (const float*)d_in[2];
    const float* sinb  = (const float*)d_in[3];
    const float* Wq    = (const float*)d_in[4];
    const float* Wk    = (const float*)d_in[5];
    const float* Wv    = (const float*)d_in[6];
    const float* Wproj = (const float*)d_in[7];
    const float* Wgate = (const float*)d_in[8];
    const int*   win   = (const int*)d_in[9];
    float* out = (float*)d_out;

    __nv_bfloat16 *xs_hi, *xs_lo, *ys_hi, *ys_lo,
                  *wqkv_hi, *wqkv_lo, *wproj_hi, *wproj_lo;
    float *qkv;
    cudaGetSymbolAddress((void**)&xs_hi, g_xs_hi);
    cudaGetSymbolAddress((void**)&xs_lo, g_xs_lo);
    cudaGetSymbolAddress((void**)&ys_hi, g_ys_hi);
    cudaGetSymbolAddress((void**)&ys_lo, g_ys_lo);
    cudaGetSymbolAddress((void**)&wqkv_hi, g_wqkv_hi);
    cudaGetSymbolAddress((void**)&wqkv_lo, g_wqkv_lo);
    cudaGetSymbolAddress((void**)&wproj_hi, g_wproj_hi);
    cudaGetSymbolAddress((void**)&wproj_lo, g_wproj_lo);
    cudaGetSymbolAddress((void**)&qkv, g_qkv);

    cudaFuncSetAttribute(gemm_split,
                         cudaFuncAttributeMaxDynamicSharedMemorySize, GEMM_SMEM);
    cudaFuncSetAttribute(attn_tc,
                         cudaFuncAttributeMaxDynamicSharedMemorySize, ATT_SMEM);

    // 1. weight prep + x split
    transpose_split_all<<<dim3(80, C_ / 32), dim3(32, 8)>>>(Wq, Wk, Wv, Wproj);
    split_fp32<<<(M_ * C_ + 255) / 256, 256>>>(x, xs_hi, xs_lo, M_ * C_);
    // 2. fused QKV projection (all-bf16 cp.async pipeline)
    gemm_split<<<dim3(NQKV_ / 128, M_ / 128), 256, GEMM_SMEM>>>(
        xs_hi, xs_lo, wqkv_hi, wqkv_lo, qkv, NQKV_);
    // 3. gate + RoPE + RMSNorm + bf16 split + layouts
    postproc<<<M_, 256>>>(x, ve, cosb, sinb, Wgate);
    // 4. deep-pipelined tensor-core attention (writes ys hi/lo directly)
    attn_tc<<<dim3(T_ / 128, NH_, B_), 256, ATT_SMEM>>>(win);
    // 5. output projection (all-bf16 cp.async pipeline)
    gemm_split<<<dim3(C_ / 128, M_ / 128), 256, GEMM_SMEM>>>(
        ys_hi, ys_lo, wproj_hi, wproj_lo, out, C_);
}

// round 15
// speedup vs baseline: 9.3430x; 1.0492x over previous
#include <cuda_runtime.h>
#include <cuda_bf16.h>
#include <math.h>
#include <stdint.h>

// Problem constants (fixed by the reference)
#define B_  2
#define T_  2048
#define C_  1024
#define NH_ 16
#define NKV_ 4
#define HD_ 64
#define VEC_ 32
#define M_  (B_ * T_)      // 4096 token rows
#define NQKV_ 1536         // fused q(1024) | k(256) | v(256) columns

// tcgen05 is arch-conditional: only in the sm_103a/sm_100a passes. The
// baseline compute_103 target gets SIMT fallback bodies.
#if defined(__CUDA_ARCH_FEAT_SM103_ALL) || defined(__CUDA_ARCH_FEAT_SM100_ALL) || \
    defined(__CUDA_ARCH_FEAT_SM101_ALL)
#define TC_OK 1
#else
#define TC_OK 0
#endif

// ---------------------------------------------------------------------------
// Scratch (static device globals; no runtime allocation allowed)
// ---------------------------------------------------------------------------
__device__ __align__(16) __nv_bfloat16 g_xs_hi[M_ * C_];       // x split
__device__ __align__(16) __nv_bfloat16 g_xs_lo[M_ * C_];
__device__ __align__(16) __nv_bfloat16 g_ys_hi[M_ * C_];       // attn out split
__device__ __align__(16) __nv_bfloat16 g_ys_lo[M_ * C_];
__device__ __align__(16) __nv_bfloat16 g_wqkv_hi[NQKV_ * C_];  // [N,K] transposed
__device__ __align__(16) __nv_bfloat16 g_wqkv_lo[NQKV_ * C_];
__device__ __align__(16) __nv_bfloat16 g_wproj_hi[C_ * C_];    // [N,K] transposed
__device__ __align__(16) __nv_bfloat16 g_wproj_lo[C_ * C_];
__device__ float g_qkv[M_ * NQKV_];        // fused projection output
// attention operands, bf16 hi/lo split
__device__ __align__(16) __nv_bfloat16 g_qs_hi[M_ * NH_ * HD_];   // [B,NH,T,HD]
__device__ __align__(16) __nv_bfloat16 g_qs_lo[M_ * NH_ * HD_];
__device__ __align__(16) __nv_bfloat16 g_ks_hi[M_ * NKV_ * HD_];  // [B,NKV,T,HD]
__device__ __align__(16) __nv_bfloat16 g_ks_lo[M_ * NKV_ * HD_];
__device__ __align__(16) __nv_bfloat16 g_vn_hi[M_ * NKV_ * HD_];  // [B,NKV,T,HD]
__device__ __align__(16) __nv_bfloat16 g_vn_lo[M_ * NKV_ * HD_];
__device__ __align__(16) __nv_bfloat16 g_vts_hi[M_ * NKV_ * HD_]; // [B,NKV,HD,T]
__device__ __align__(16) __nv_bfloat16 g_vts_lo[M_ * NKV_ * HD_];

// ---------------------------------------------------------------------------
// PTX helpers
// ---------------------------------------------------------------------------
__device__ __forceinline__ uint32_t smem_u32(const void* p) {
    uint32_t a;
    asm("{ .reg .u64 t; cvta.to.shared.u64 t, %1; cvt.u32.u64 %0, t; }"
        : "=r"(a) : "l"(p));
    return a;
}
__device__ __forceinline__ uint32_t elect_one() {
    uint32_t pred;
    asm volatile("{\n\t.reg .pred p;\n\telect.sync _|p, 0xFFFFFFFF;\n\t"
                 "selp.b32 %0, 1, 0, p;\n\t}" : "=r"(pred));
    return pred;
}
#define TC_ALLOC(sm, n)   asm volatile("tcgen05.alloc.cta_group::1.sync.aligned.shared::cta.b32 [%0], %1;" :: "r"(sm), "r"((uint32_t)(n)) : "memory")
#define TC_DEALLOC(t, n)  asm volatile("tcgen05.dealloc.cta_group::1.sync.aligned.b32 %0, %1;" :: "r"(t), "r"((uint32_t)(n)))
#define TC_RELINQ()       asm volatile("tcgen05.relinquish_alloc_permit.cta_group::1.sync.aligned;")
#define TC_COMMIT(mbar)   asm volatile("tcgen05.commit.cta_group::1.mbarrier::arrive::one.shared::cluster.b64 [%0];" :: "r"(mbar) : "memory")
#define TC_FENCE_AFTER()  asm volatile("tcgen05.fence::after_thread_sync;" ::: "memory")
#define TC_FENCE_BEFORE() asm volatile("tcgen05.fence::before_thread_sync;" ::: "memory")
#define TC_WAIT_LD()      asm volatile("tcgen05.wait::ld.sync.aligned;" ::: "memory")
#define TC_WAIT_ST()      asm volatile("tcgen05.wait::st.sync.aligned;" ::: "memory")
#define MBAR_INIT(sm, n)  asm volatile("mbarrier.init.shared.b64 [%0], %1;" :: "r"(sm), "r"((uint32_t)(n)) : "memory")
#define FENCE_ASYNC()     asm volatile("fence.proxy.async.shared::cta;" ::: "memory")
#define CP_ASYNC16(dst, src) asm volatile("cp.async.cg.shared.global [%0], [%1], 16;" :: "r"(dst), "l"(src) : "memory")
#define CP_COMMIT()       asm volatile("cp.async.commit_group;" ::: "memory")
#define CP_WAIT0()        asm volatile("cp.async.wait_group 0;" ::: "memory")
#define CP_WAIT1()        asm volatile("cp.async.wait_group 1;" ::: "memory")

__device__ __forceinline__ void mbar_wait(uint32_t mbar, uint32_t parity) {
    asm volatile(
        "{\n\t.reg .pred P;\n\t"
        "W%=:\n\t"
        "mbarrier.try_wait.parity.acquire.cta.shared::cta.b64 P, [%0], %1, 0x989680;\n\t"
        "@P bra D%=;\n\t"
        "bra W%=;\n\t"
        "D%=:\n\t}"
        :: "r"(mbar), "r"(parity) : "memory");
}
__device__ __forceinline__ float ex2_approx(float x) {
    float r;
    asm("ex2.approx.ftz.f32 %0, %1;" : "=f"(r) : "f"(x));
    return r;
}

#if TC_OK
// SS-mode bf16 MMA, cta_group::1, fp32 accum
__device__ __forceinline__ void mma_f16_ss(uint32_t d, uint64_t a, uint64_t b,
                                           uint32_t idesc, uint32_t en) {
    asm volatile(
        "{\n\t.reg .pred p;\n\t"
        "setp.ne.u32 p, %4, 0;\n\t"
        "tcgen05.mma.cta_group::1.kind::f16 [%0], %1, %2, %3, {%5, %5, %5, %5}, p;\n\t"
        "}"
        :: "r"(d), "l"(a), "l"(b), "r"(idesc), "r"(en), "r"(0u)
        : "memory");
}
// TS-mode bf16 MMA: A in TMEM, B in SMEM
__device__ __forceinline__ void mma_f16_ts(uint32_t d, uint32_t a, uint64_t b,
                                           uint32_t idesc, uint32_t en) {
    asm volatile(
        "{\n\t.reg .pred p;\n\t"
        "setp.ne.u32 p, %4, 0;\n\t"
        "tcgen05.mma.cta_group::1.kind::f16 [%0], [%1], %2, %3, {%5, %5, %5, %5}, p;\n\t"
        "}"
        :: "r"(d), "r"(a), "l"(b), "r"(idesc), "r"(en), "r"(0u)
        : "memory");
}

#define LDTM_X32(r, addr) \
    asm volatile( \
        "tcgen05.ld.sync.aligned.32x32b.x32.b32 " \
        "{%0, %1, %2, %3, %4, %5, %6, %7, " \
        " %8, %9, %10, %11, %12, %13, %14, %15, " \
        " %16, %17, %18, %19, %20, %21, %22, %23, " \
        " %24, %25, %26, %27, %28, %29, %30, %31}, [%32];" \
        : "=r"((r)[0]),  "=r"((r)[1]),  "=r"((r)[2]),  "=r"((r)[3]), \
          "=r"((r)[4]),  "=r"((r)[5]),  "=r"((r)[6]),  "=r"((r)[7]), \
          "=r"((r)[8]),  "=r"((r)[9]),  "=r"((r)[10]), "=r"((r)[11]), \
          "=r"((r)[12]), "=r"((r)[13]), "=r"((r)[14]), "=r"((r)[15]), \
          "=r"((r)[16]), "=r"((r)[17]), "=r"((r)[18]), "=r"((r)[19]), \
          "=r"((r)[20]), "=r"((r)[21]), "=r"((r)[22]), "=r"((r)[23]), \
          "=r"((r)[24]), "=r"((r)[25]), "=r"((r)[26]), "=r"((r)[27]), \
          "=r"((r)[28]), "=r"((r)[29]), "=r"((r)[30]), "=r"((r)[31]) \
        : "r"(addr))

#define STTM_X16(addr, r) \
    asm volatile( \
        "tcgen05.st.sync.aligned.32x32b.x16.b32 [%0], " \
        "{%1, %2, %3, %4, %5, %6, %7, %8, " \
        " %9, %10, %11, %12, %13, %14, %15, %16};" \
        :: "r"(addr), \
           "r"((r)[0]),  "r"((r)[1]),  "r"((r)[2]),  "r"((r)[3]), \
           "r"((r)[4]),  "r"((r)[5]),  "r"((r)[6]),  "r"((r)[7]), \
           "r"((r)[8]),  "r"((r)[9]),  "r"((r)[10]), "r"((r)[11]), \
           "r"((r)[12]), "r"((r)[13]), "r"((r)[14]), "r"((r)[15]) \
        : "memory")
#endif  // TC_OK

// 64-bit SMEM descriptor: SW128, version=1 (Blackwell), LBO=1, SBO=64
static __device__ __forceinline__ uint64_t smem_desc_sw128(uint32_t addr) {
    const uint64_t base =
        (uint64_t(2)  << 61) | (uint64_t(1) << 46) |
        (uint64_t(64) << 32) | (uint64_t(1) << 16);
    return base | ((uint64_t)(addr >> 4) & 0x3FFF);
}
#define SW128(off) ((off) ^ (((off) >> 3) & 0x70))

// idesc: dtype=F32, atype=BF16, btype=BF16 (K-major both)
#define GEMM_IDESC ((1u << 4) | (1u << 7) | (1u << 10) | ((128u / 8) << 17) | ((128u / 16) << 24))
#define ATT_IDESC  ((1u << 4) | (1u << 7) | (1u << 10) | ((64u / 8) << 17) | ((128u / 16) << 24))

__device__ __forceinline__ uint32_t b2u(__nv_bfloat162 v) {
    return *(uint32_t*)&v;
}

// ---------------------------------------------------------------------------
// fp32 -> (hi, lo) bf16 split, elementwise (for x).
// ---------------------------------------------------------------------------
__global__ __launch_bounds__(256) void split_fp32(
    const float* __restrict__ src, __nv_bfloat16* __restrict__ hi,
    __nv_bfloat16* __restrict__ lo, int n) {
    int i = blockIdx.x * 256 + threadIdx.x;
    if (i < n) {
        float v = src[i];
        __nv_bfloat16 h = __float2bfloat16(v);
        hi[i] = h;
        lo[i] = __float2bfloat16(v - __bfloat162float(h));
    }
}

// ---------------------------------------------------------------------------
// Combined weight transpose + hi/lo split.
// ---------------------------------------------------------------------------
__global__ __launch_bounds__(256) void transpose_split_all(
    const float* __restrict__ Wq, const float* __restrict__ Wk,
    const float* __restrict__ Wv, const float* __restrict__ Wp) {
    __shared__ float t[32][33];
    const int ct = blockIdx.x;
    const float* W;
    __nv_bfloat16 *hi, *lo;
    int Ncols, nb;
    if (ct < 32)      { W = Wq; hi = g_wqkv_hi;                     lo = g_wqkv_lo;                     Ncols = 1024; nb = ct * 32; }
    else if (ct < 40) { W = Wk; hi = g_wqkv_hi + (size_t)1024 * C_; lo = g_wqkv_lo + (size_t)1024 * C_; Ncols = 256;  nb = (ct - 32) * 32; }
    else if (ct < 48) { W = Wv; hi = g_wqkv_hi + (size_t)1280 * C_; lo = g_wqkv_lo + (size_t)1280 * C_; Ncols = 256;  nb = (ct - 40) * 32; }
    else              { W = Wp; hi = g_wproj_hi;                    lo = g_wproj_lo;                    Ncols = 1024; nb = (ct - 48) * 32; }
    const int kb = blockIdx.y * 32;
    const int tx = threadIdx.x, ty = threadIdx.y;
#pragma unroll
    for (int j = 0; j < 32; j += 8)
        t[ty + j][tx] = W[(size_t)(kb + ty + j) * Ncols + nb + tx];
    __syncthreads();
#pragma unroll
    for (int j = 0; j < 32; j += 8) {
        float v = t[tx][ty + j];
        __nv_bfloat16 h = __float2bfloat16(v);
        size_t o = (size_t)(nb + ty + j) * C_ + kb + tx;
        hi[o] = h;
        lo[o] = __float2bfloat16(v - __bfloat162float(h));
    }
}

// ---------------------------------------------------------------------------
// V layout transpose: [T, HD] -> [HD, T] per (b, kvh), hi+lo, via smem tiles.
// grid (T/32, HD/32, B*NKV), block (32, 8). Both sides coalesced.
// ---------------------------------------------------------------------------
__global__ __launch_bounds__(256) void transpose_v() {
    __shared__ __nv_bfloat16 th[32][34], tl[32][34];  // stride 17 banks: conflict-free
    const int tb = blockIdx.x * 32;
    const int db = blockIdx.y * 32;
    const int m  = blockIdx.z;
    const int tx = threadIdx.x, ty = threadIdx.y;
    const __nv_bfloat16* sh = g_vn_hi + (size_t)m * T_ * HD_;
    const __nv_bfloat16* sl = g_vn_lo + (size_t)m * T_ * HD_;
#pragma unroll
    for (int j = 0; j < 32; j += 8) {
        th[ty + j][tx] = sh[(size_t)(tb + ty + j) * HD_ + db + tx];
        tl[ty + j][tx] = sl[(size_t)(tb + ty + j) * HD_ + db + tx];
    }
    __syncthreads();
    __nv_bfloat16* dh = g_vts_hi + (size_t)m * HD_ * T_;
    __nv_bfloat16* dl = g_vts_lo + (size_t)m * HD_ * T_;
#pragma unroll
    for (int j = 0; j < 32; j += 8) {
        dh[(size_t)(db + ty + j) * T_ + tb + tx] = th[tx][ty + j];
        dl[(size_t)(db + ty + j) * T_ + tb + tx] = tl[tx][ty + j];
    }
}

// ---------------------------------------------------------------------------
// Split-bf16 GEMM: C[M,N] = (Ahi+Alo)[M,K] . (Bhi+Blo)[N,K]^T, 3-term.
// ALL operands pre-split bf16; loads via cp.async. Unchanged from round 14.
// ---------------------------------------------------------------------------
#define KCHUNK   64
#define NCHUNKS  (C_ / KCHUNK)           // 16
#define BUFSZ    16384                   // 128 rows x 128 bytes
#define STAGESZ  (4 * BUFSZ)             // Ahi | Alo | Bhi | Blo
#define GEMM_SMEM (2048 + 2 * STAGESZ)

__global__ __launch_bounds__(256) void gemm_split(
    const __nv_bfloat16* __restrict__ Ahi, const __nv_bfloat16* __restrict__ Alo,
    const __nv_bfloat16* __restrict__ Bhi, const __nv_bfloat16* __restrict__ Blo,
    float* __restrict__ C, int N) {
#if TC_OK
    extern __shared__ char smem[];
    const uint32_t sb = smem_u32(smem);
    const uint32_t ab = (sb + 1024 + 1023) & 0xFFFFFC00u;
    const int tid = threadIdx.x;
    const int wid = tid >> 5;
    const int lane = tid & 31;
    const int bm = blockIdx.y * 128;
    const int bn = blockIdx.x * 128;
    const int K = C_;

    if (wid == 0) TC_ALLOC(sb, 128);
    if (tid == 0) { MBAR_INIT(sb + 8, 1); MBAR_INIT(sb + 16, 1); }
    __syncthreads();
    uint32_t tmem;
    asm volatile("ld.shared.b32 %0, [%1];" : "=r"(tmem) : "r"(sb));

#define LOAD_CHUNK(kc, s)                                                     \
    do {                                                                      \
        const int k0 = (kc) * KCHUNK;                                         \
        uint32_t st = ab + (s) * STAGESZ;                                     \
        _Pragma("unroll")                                                     \
        for (int v = 0; v < 4; v++) {                                         \
            int idx = tid + v * 256;                                          \
            int r = idx >> 3, c8 = idx & 7;                                   \
            uint32_t off = SW128((uint32_t)(r * 128 + c8 * 16));              \
            size_t ga = (size_t)(bm + r) * K + k0 + c8 * 8;                   \
            size_t gb = (size_t)(bn + r) * K + k0 + c8 * 8;                   \
            CP_ASYNC16(st + off,              Ahi + ga);                      \
            CP_ASYNC16(st + BUFSZ + off,      Alo + ga);                      \
            CP_ASYNC16(st + 2 * BUFSZ + off,  Bhi + gb);                      \
            CP_ASYNC16(st + 3 * BUFSZ + off,  Blo + gb);                      \
        }                                                                     \
        CP_COMMIT();                                                          \
    } while (0)

    LOAD_CHUNK(0, 0);
    int p0 = 0, p1 = 0;

    for (int i = 0; i < NCHUNKS; i++) {
        const int s = i & 1;
        if (i + 1 < NCHUNKS) {
            const int s2 = (i + 1) & 1;
            if (i >= 1) {
                if (s2 == 0) { mbar_wait(sb + 8,  p0 & 1); p0++; }
                else         { mbar_wait(sb + 16, p1 & 1); p1++; }
            }
            LOAD_CHUNK(i + 1, s2);
            CP_WAIT1();
        } else {
            CP_WAIT0();
        }
        __syncthreads();
        if (wid == 0) {
            FENCE_ASYNC();
            if (elect_one()) {
                uint32_t base = ab + s * STAGESZ;
                uint64_t dah = smem_desc_sw128(base);
                uint64_t dal = smem_desc_sw128(base + BUFSZ);
                uint64_t dbh = smem_desc_sw128(base + 2 * BUFSZ);
                uint64_t dbl = smem_desc_sw128(base + 3 * BUFSZ);
#pragma unroll
                for (int kk = 0; kk < 4; kk++)
                    mma_f16_ss(tmem, dah + kk * 2, dbh + kk * 2, GEMM_IDESC,
                               (i > 0) || (kk > 0));
#pragma unroll
                for (int kk = 0; kk < 4; kk++)
                    mma_f16_ss(tmem, dah + kk * 2, dbl + kk * 2, GEMM_IDESC, 1);
#pragma unroll
                for (int kk = 0; kk < 4; kk++)
                    mma_f16_ss(tmem, dal + kk * 2, dbh + kk * 2, GEMM_IDESC, 1);
                TC_COMMIT(sb + 8 + s * 8);
            }
        }
    }
    {
        const int sl = (NCHUNKS - 1) & 1;
        if (sl == 0) mbar_wait(sb + 8, p0 & 1);
        else         mbar_wait(sb + 16, p1 & 1);
    }
    TC_FENCE_AFTER();

    {
        const int sp = wid & 3;
        const int colbase = (wid >> 2) * 64;
        const uint32_t wo = (uint32_t)sp << 21;
        uint32_t d0[32], d1[32];
        LDTM_X32(d0, tmem + wo + colbase);
        LDTM_X32(d1, tmem + wo + colbase + 32);
        TC_WAIT_LD();
        const int row = bm + sp * 32 + lane;
        float* dst = C + (size_t)row * N + bn + colbase;
#pragma unroll
        for (int c = 0; c < 32; c += 4) {
            *(float4*)(dst + c) = make_float4(
                __uint_as_float(d0[c]), __uint_as_float(d0[c + 1]),
                __uint_as_float(d0[c + 2]), __uint_as_float(d0[c + 3]));
            *(float4*)(dst + 32 + c) = make_float4(
                __uint_as_float(d1[c]), __uint_as_float(d1[c + 1]),
                __uint_as_float(d1[c + 2]), __uint_as_float(d1[c + 3]));
        }
    }
    __syncthreads();
    if (wid == 0) TC_DEALLOC(tmem, 128);
#undef LOAD_CHUNK

#else  // SIMT fallback
    __shared__ float As[8][128];
    __shared__ float Bs[8][128];
    const int tid = threadIdx.x;
    const int bm = blockIdx.y * 128;
    const int bn = blockIdx.x * 128;
    const int K = C_;
    const int ldRow = tid >> 1;
    const int ldK   = (tid & 1) * 4;
    const int ri = (tid >> 4) * 4;
    const int ci = (tid & 15) * 4;

    float acc[8][8];
#pragma unroll
    for (int i = 0; i < 8; i++)
#pragma unroll
        for (int j = 0; j < 8; j++) acc[i][j] = 0.f;

    for (int k0 = 0; k0 < K; k0 += 8) {
#pragma unroll
        for (int c = 0; c < 4; c++) {
            size_t ga = (size_t)(bm + ldRow) * K + k0 + ldK + c;
            size_t gb = (size_t)(bn + ldRow) * K + k0 + ldK + c;
            As[ldK + c][ldRow] = __bfloat162float(Ahi[ga]) + __bfloat162float(Alo[ga]);
            Bs[ldK + c][ldRow] = __bfloat162float(Bhi[gb]) + __bfloat162float(Blo[gb]);
        }
        __syncthreads();
#pragma unroll
        for (int kk = 0; kk < 8; kk++) {
            float ar[8], br[8];
#pragma unroll
            for (int i = 0; i < 4; i++) {
                ar[i] = As[kk][ri + i];
                ar[i + 4] = As[kk][ri + 64 + i];
                br[i] = Bs[kk][ci + i];
                br[i + 4] = Bs[kk][ci + 64 + i];
            }
#pragma unroll
            for (int i = 0; i < 8; i++)
#pragma unroll
                for (int j = 0; j < 8; j++) acc[i][j] += ar[i] * br[j];
        }
        __syncthreads();
    }
#pragma unroll
    for (int ib = 0; ib < 2; ib++)
#pragma unroll
        for (int i = 0; i < 4; i++) {
            int row = bm + ib * 64 + ri + i;
#pragma unroll
            for (int jb = 0; jb < 2; jb++)
#pragma unroll
                for (int j = 0; j < 4; j++)
                    C[(size_t)row * N + bn + jb * 64 + ci + j] =
                        acc[ib * 4 + i][jb * 4 + j];
        }
#endif
}

// ---------------------------------------------------------------------------
// Per-token post-process: gate, v += gate*ve, RoPE + RMSNorm on q/k.
// V is written UNTRANSPOSED [B,NKV,T,HD] (coalesced); transpose_v fixes
// layout afterwards.
// ---------------------------------------------------------------------------
__global__ __launch_bounds__(256) void postproc(
    const float* __restrict__ x, const float* __restrict__ ve,
    const float* __restrict__ cosb, const float* __restrict__ sinb,
    const float* __restrict__ Wgate) {
    const int bt = blockIdx.x;
    const int b = bt / T_, t = bt % T_;
    const int tid = threadIdx.x;
    const int lane = tid & 31, w = tid >> 5;
    __shared__ float s_gate[NKV_];

    if (w < NKV_) {
        float p = x[(size_t)bt * C_ + lane] * Wgate[lane * NKV_ + w];
#pragma unroll
        for (int o = 16; o; o >>= 1) p += __shfl_xor_sync(0xffffffffu, p, o);
        if (lane == 0) s_gate[w] = 2.0f / (1.0f + expf(-p));
    }
    __syncthreads();

    const float c = cosb[t * (HD_ / 2) + lane];
    const float s = sinb[t * (HD_ / 2) + lane];
    const float* qkvrow = g_qkv + (size_t)bt * NQKV_;
    for (int row = w; row < NH_ + NKV_; row += 8) {
        const float* src;
        __nv_bfloat16 *dhi, *dlo;
        if (row < NH_) {
            src = qkvrow + row * HD_;
            size_t base = ((size_t)(b * NH_ + row) * T_ + t) * HD_;
            dhi = g_qs_hi + base;
            dlo = g_qs_lo + base;
        } else {
            int kh = row - NH_;
            src = qkvrow + 1024 + kh * HD_;
            size_t base = ((size_t)(b * NKV_ + kh) * T_ + t) * HD_;
            dhi = g_ks_hi + base;
            dlo = g_ks_lo + base;
        }
        float x1 = src[lane], x2 = src[lane + 32];
        float o1 = x1 * c + x2 * s;
        float o2 = -x1 * s + x2 * c;
        float sq = o1 * o1 + o2 * o2;
#pragma unroll
        for (int o = 16; o; o >>= 1) sq += __shfl_xor_sync(0xffffffffu, sq, o);
        float scale = rsqrtf(sq * (1.0f / HD_) + 1.1920929e-7f);
        float v1 = o1 * scale, v2 = o2 * scale;
        __nv_bfloat16 h1 = __float2bfloat16(v1);
        __nv_bfloat16 h2 = __float2bfloat16(v2);
        dhi[lane] = h1;
        dhi[lane + 32] = h2;
        dlo[lane] = __float2bfloat16(v1 - __bfloat162float(h1));
        dlo[lane + 32] = __float2bfloat16(v2 - __bfloat162float(h2));
    }

    {
        int h = tid >> 6, d = tid & 63;
        float val = qkvrow[1280 + tid] +
                    s_gate[h] * ve[(size_t)bt * (NKV_ * HD_) + tid];
        size_t o = ((size_t)(b * NKV_ + h) * T_ + t) * HD_ + d;  // coalesced
        __nv_bfloat16 hh = __float2bfloat16(val);
        g_vn_hi[o] = hh;
        g_vn_lo[o] = __float2bfloat16(val - __bfloat162float(hh));
    }
}

// ---------------------------------------------------------------------------
// tcgen05 sliding-window flash attention (unchanged from round 14).
// ---------------------------------------------------------------------------
#define AOFF_RED 0         // redsum[256] f32 (1KB)
#define AOFF_Q   2048      // Qhi 16K | Qlo 16K                 (end 34816)
#define AOFF_K   34816     // buf s: {Khi 8K | Klo 8K} x2       (end 67584)
#define AOFF_V   67584     // buf s: {Vhi 8K | Vlo 8K} x2       (end 100352)
#define KBUF(s)  (AOFF_K + (s) * 16384)
#define VBUF(s)  (AOFF_V + (s) * 16384)
#define ATT_SMEM 103424    // 1024 hdr + align slack + 100352

#define TM_S(s)  ((s) * 64)
#define TM_PV    128
#define TM_PHI   192
#define TM_PLO   224

__global__ __launch_bounds__(256, 2) void attn_tc(const int* __restrict__ winp) {
#if TC_OK
    extern __shared__ char smem[];
    const uint32_t sb = smem_u32(smem);
    const uint32_t ab = (sb + 1024 + 1023) & 0xFFFFFC00u;
    char* abp = smem + (ab - sb);

    int win = winp[0];
    if (win <= 0 || win > T_) win = 1024;
    const int qt = blockIdx.x, h = blockIdx.y, b = blockIdx.z;
    const int kvh = h >> 2;
    const int q0 = qt * 128;
    const int tid = threadIdx.x, w = tid >> 5, lane = tid & 31;
    const int sp = w & 3;              // TMEM subpartition
    const int hf = w >> 2;             // key half (0 or 1)
    const int kbase = hf * 32;
    const int r = sp * 32 + lane;      // q row within tile
    const int qg = q0 + r;             // global q index
    const uint32_t wo = (uint32_t)sp << 21;

    float* redsum = (float*)(abp + AOFF_RED);

    if (w == 0) { TC_ALLOC(sb, 256); TC_RELINQ(); }
    if (tid == 0) { MBAR_INIT(sb + 8, 1); MBAR_INIT(sb + 16, 1); }
    __syncthreads();
    uint32_t tmem;
    asm volatile("ld.shared.b32 %0, [%1];" : "=r"(tmem) : "r"(sb));

    const __nv_bfloat16* qh  = g_qs_hi  + ((size_t)(b * NH_ + h) * T_ + q0) * HD_;
    const __nv_bfloat16* qlo = g_qs_lo  + ((size_t)(b * NH_ + h) * T_ + q0) * HD_;
    const __nv_bfloat16* kh  = g_ks_hi  + ((size_t)(b * NKV_ + kvh) * T_) * HD_;
    const __nv_bfloat16* kl  = g_ks_lo  + ((size_t)(b * NKV_ + kvh) * T_) * HD_;
    const __nv_bfloat16* vth = g_vts_hi + ((size_t)(b * NKV_ + kvh) * HD_) * T_;
    const __nv_bfloat16* vtl = g_vts_lo + ((size_t)(b * NKV_ + kvh) * HD_) * T_;

    int j0s = q0 - win;
    if (j0s < 0) j0s = 0;
    const int jt0 = j0s >> 6;
    const int jt1 = (q0 + 127) >> 6;   // always >= jt0 + 1

    const int krr0 = tid >> 3, kc8 = (tid & 7) * 8;
    const uint32_t koff0 = SW128((uint32_t)(krr0 * 128 + kc8 * 2));
    const uint32_t koff1 = SW128((uint32_t)((krr0 + 32) * 128 + kc8 * 2));

#define LOAD_K(jt, s)                                                         \
    do {                                                                      \
        const int j0_ = (jt) * 64;                                            \
        uint32_t kb_ = ab + KBUF(s);                                          \
        CP_ASYNC16(kb_ + koff0,        kh + (size_t)(j0_ + krr0) * 64 + kc8); \
        CP_ASYNC16(kb_ + koff1,        kh + (size_t)(j0_ + krr0 + 32) * 64 + kc8); \
        CP_ASYNC16(kb_ + 8192 + koff0, kl + (size_t)(j0_ + krr0) * 64 + kc8); \
        CP_ASYNC16(kb_ + 8192 + koff1, kl + (size_t)(j0_ + krr0 + 32) * 64 + kc8); \
    } while (0)

#define LOAD_V(jt, s)                                                         \
    do {                                                                      \
        const int j0_ = (jt) * 64;                                            \
        uint32_t vb_ = ab + VBUF(s);                                          \
        CP_ASYNC16(vb_ + koff0,        vth + (size_t)krr0 * T_ + j0_ + kc8);  \
        CP_ASYNC16(vb_ + koff1,        vth + (size_t)(krr0 + 32) * T_ + j0_ + kc8); \
        CP_ASYNC16(vb_ + 8192 + koff0, vtl + (size_t)krr0 * T_ + j0_ + kc8);  \
        CP_ASYNC16(vb_ + 8192 + koff1, vtl + (size_t)(krr0 + 32) * T_ + j0_ + kc8); \
    } while (0)

#define ISSUE_S(kbuf_s, tm_s)                                                 \
    do {                                                                      \
        uint64_t dKh = smem_desc_sw128(ab + KBUF(kbuf_s));                    \
        uint64_t dKl = smem_desc_sw128(ab + KBUF(kbuf_s) + 8192);             \
        uint32_t sdst = tmem + TM_S(tm_s);                                    \
        _Pragma("unroll")                                                     \
        for (int kk = 0; kk < 4; kk++)                                        \
            mma_f16_ss(sdst, dQh + kk * 2, dKh + kk * 2, ATT_IDESC, kk > 0);  \
        _Pragma("unroll")                                                     \
        for (int kk = 0; kk < 4; kk++)                                        \
            mma_f16_ss(sdst, dQh + kk * 2, dKl + kk * 2, ATT_IDESC, 1);       \
        _Pragma("unroll")                                                     \
        for (int kk = 0; kk < 4; kk++)                                        \
            mma_f16_ss(sdst, dQl + kk * 2, dKh + kk * 2, ATT_IDESC, 1);       \
    } while (0)

    // ---- prologue ----
#pragma unroll
    for (int v = 0; v < 4; v++) {
        int idx = tid + v * 256;
        int rr = idx >> 3, c8 = idx & 7;
        uint32_t off = SW128((uint32_t)(rr * 128 + c8 * 16));
        *(uint4*)(abp + AOFF_Q + off)         = *(const uint4*)(qh  + rr * 64 + c8 * 8);
        *(uint4*)(abp + AOFF_Q + 16384 + off) = *(const uint4*)(qlo + rr * 64 + c8 * 8);
    }
    LOAD_K(jt0, jt0 & 1);
    LOAD_V(jt0, jt0 & 1);
    CP_COMMIT();
    LOAD_K(jt0 + 1, (jt0 + 1) & 1);
    CP_COMMIT();
    CP_WAIT0();
    __syncthreads();
    const uint64_t dQh = smem_desc_sw128(ab + AOFF_Q);
    const uint64_t dQl = smem_desc_sw128(ab + AOFF_Q + 16384);
    if (w == 0) {
        FENCE_ASYNC();
        if (elect_one()) {
            ISSUE_S(jt0 & 1, jt0 & 1);
            TC_COMMIT(sb + 8);
        }
    }

    float l_loc = 0.f;
    int ps = 0, ppv = 0;
    const float C1 = 0.18033688f;      // 0.125 * log2(e)
    const float C0 = -11.541560f;      // -8 * log2(e)

    for (int jt = jt0; jt <= jt1; jt++) {
        const int sbuf = jt & 1;
        const int j0 = jt * 64;
        mbar_wait(sb + 8, ps & 1); ps++;
        CP_WAIT1();
        __syncthreads();
        TC_FENCE_AFTER();
        if (jt < jt1 && w == 0) {
            FENCE_ASYNC();
            if (elect_one()) {
                ISSUE_S(sbuf ^ 1, sbuf ^ 1);
                TC_COMMIT(sb + 8);
            }
        }
        {
            int kidx = jt + 2 <= jt1 ? jt + 2 : jt1;
            LOAD_K(kidx, sbuf);
            CP_COMMIT();
        }
        uint32_t sr[32];
        LDTM_X32(sr, tmem + wo + TM_S(sbuf) + kbase);
        TC_WAIT_LD();
        float p[32];
#pragma unroll
        for (int i = 0; i < 32; i++) {
            int jg = j0 + kbase + i;
            bool ok = (jg <= qg) && (jg >= qg - win);
            float e = ex2_approx(fmaf(__uint_as_float(sr[i]), C1, C0));
            p[i] = ok ? e : 0.f;
            l_loc += p[i];
        }
        if (jt > jt0) { mbar_wait(sb + 16, ppv & 1); ppv++; TC_FENCE_AFTER(); }
        {
            uint32_t ph[16], pl[16];
#pragma unroll
            for (int i = 0; i < 16; i++) {
                float pa = p[2 * i], pb = p[2 * i + 1];
                __nv_bfloat162 hh = __floats2bfloat162_rn(pa, pb);
                float la = pa - __bfloat162float(hh.x);
                float lb = pb - __bfloat162float(hh.y);
                __nv_bfloat162 ll = __floats2bfloat162_rn(la, lb);
                ph[i] = b2u(hh);
                pl[i] = b2u(ll);
            }
            STTM_X16(tmem + wo + TM_PHI + hf * 16, ph);
            STTM_X16(tmem + wo + TM_PLO + hf * 16, pl);
            TC_WAIT_ST();
            TC_FENCE_BEFORE();
        }
        CP_WAIT1();
        {
            int vidx = jt + 1 <= jt1 ? jt + 1 : jt1;
            LOAD_V(vidx, sbuf ^ 1);
            CP_COMMIT();
        }
        __syncthreads();
        if (w == 0) {
            TC_FENCE_AFTER();
            FENCE_ASYNC();
            if (elect_one()) {
                uint64_t dVh = smem_desc_sw128(ab + VBUF(sbuf));
                uint64_t dVl = smem_desc_sw128(ab + VBUF(sbuf) + 8192);
#pragma unroll
                for (int kk = 0; kk < 4; kk++)
                    mma_f16_ts(tmem + TM_PV, tmem + TM_PHI + kk * 8,
                               dVh + kk * 2, ATT_IDESC, (jt > jt0) || (kk > 0));
#pragma unroll
                for (int kk = 0; kk < 4; kk++)
                    mma_f16_ts(tmem + TM_PV, tmem + TM_PHI + kk * 8,
                               dVl + kk * 2, ATT_IDESC, 1);
#pragma unroll
                for (int kk = 0; kk < 4; kk++)
                    mma_f16_ts(tmem + TM_PV, tmem + TM_PLO + kk * 8,
                               dVh + kk * 2, ATT_IDESC, 1);
                TC_COMMIT(sb + 16);
            }
        }
    }
    // drain final PV, combine l halves, write ys hi/lo (bf16 split)
    mbar_wait(sb + 16, ppv & 1);
    TC_FENCE_AFTER();
    redsum[r * 2 + hf] = l_loc;
    __syncthreads();
    const float l = redsum[r * 2] + redsum[r * 2 + 1];
    uint32_t pr[32];
    LDTM_X32(pr, tmem + wo + TM_PV + kbase);
    TC_WAIT_LD();
    {
        const float inv = 1.0f / l;
        size_t orow = ((size_t)(b * T_ + qg)) * C_ + h * 64 + kbase;
#pragma unroll
        for (int i = 0; i < 16; i++) {
            float va = __uint_as_float(pr[2 * i]) * inv;
            float vb = __uint_as_float(pr[2 * i + 1]) * inv;
            __nv_bfloat162 hh = __floats2bfloat162_rn(va, vb);
            float la = va - __bfloat162float(hh.x);
            float lb = vb - __bfloat162float(hh.y);
            __nv_bfloat162 ll = __floats2bfloat162_rn(la, lb);
            *(uint32_t*)(g_ys_hi + orow + 2 * i) = b2u(hh);
            *(uint32_t*)(g_ys_lo + orow + 2 * i) = b2u(ll);
        }
    }
    __syncthreads();
    if (w == 0) TC_DEALLOC(tmem, 256);
#undef LOAD_K
#undef LOAD_V
#undef ISSUE_S

#else  // ---------------- SIMT fallback (baseline target, never run) --------
    const int qt = blockIdx.x, h = blockIdx.y, b = blockIdx.z;
    const int kvh = h >> 2;
    int win = winp[0];
    if (win <= 0 || win > T_) win = 1024;
    const int tid = threadIdx.x;
    if (tid < 128) {
        const int qg = qt * 128 + tid;
        const __nv_bfloat16* qh  = g_qs_hi + ((size_t)(b * NH_ + h) * T_ + qg) * HD_;
        const __nv_bfloat16* qlo = g_qs_lo + ((size_t)(b * NH_ + h) * T_ + qg) * HD_;
        float q[64];
        for (int d = 0; d < 64; d++)
            q[d] = __bfloat162float(qh[d]) + __bfloat162float(qlo[d]);
        const __nv_bfloat16* kh  = g_ks_hi  + ((size_t)(b * NKV_ + kvh) * T_) * HD_;
        const __nv_bfloat16* kl  = g_ks_lo  + ((size_t)(b * NKV_ + kvh) * T_) * HD_;
        const __nv_bfloat16* vth = g_vts_hi + ((size_t)(b * NKV_ + kvh) * HD_) * T_;
        const __nv_bfloat16* vtl = g_vts_lo + ((size_t)(b * NKV_ + kvh) * HD_) * T_;
        float l = 0.f, O[64];
        for (int d = 0; d < 64; d++) O[d] = 0.f;
        int js = qg - win;
        if (js < 0) js = 0;
        for (int j = js; j <= qg; j++) {
            float s = 0.f;
            for (int d = 0; d < 64; d++)
                s += q[d] * (__bfloat162float(kh[(size_t)j * 64 + d]) +
                             __bfloat162float(kl[(size_t)j * 64 + d]));
            float p = __expf(s * 0.125f - 8.0f);
            l += p;
            for (int d = 0; d < 64; d++)
                O[d] += p * (__bfloat162float(vth[(size_t)d * T_ + j]) +
                             __bfloat162float(vtl[(size_t)d * T_ + j]));
        }
        float inv = 1.0f / l;
        size_t orow = ((size_t)(b * T_ + qg)) * C_ + h * 64;
        for (int d = 0; d < 64; d++) {
            float vO = O[d] * inv;
            __nv_bfloat16 hh = __float2bfloat16(vO);
            g_ys_hi[orow + d] = hh;
            g_ys_lo[orow + d] = __float2bfloat16(vO - __bfloat162float(hh));
        }
    }
#endif
}

// ---------------------------------------------------------------------------
// Launch
// ---------------------------------------------------------------------------
extern "C" void kernel_launch(void* const* d_in, const int* in_sizes, int n_in,
                              void* d_out, int out_size) {
    const float* x     = (const float*)d_in[0];
    const float* ve    = (const float*)d_in[1];
    const float* cosb  = (const float*)d_in[2];
    const float* sinb  = (const float*)d_in[3];
    const float* Wq    = (const float*)d_in[4];
    const float* Wk    = (const float*)d_in[5];
    const float* Wv    = (const float*)d_in[6];
    const float* Wproj = (const float*)d_in[7];
    const float* Wgate = (const float*)d_in[8];
    const int*   win   = (const int*)d_in[9];
    float* out = (float*)d_out;

    __nv_bfloat16 *xs_hi, *xs_lo, *ys_hi, *ys_lo,
                  *wqkv_hi, *wqkv_lo, *wproj_hi, *wproj_lo;
    float *qkv;
    cudaGetSymbolAddress((void**)&xs_hi, g_xs_hi);
    cudaGetSymbolAddress((void**)&xs_lo, g_xs_lo);
    cudaGetSymbolAddress((void**)&ys_hi, g_ys_hi);
    cudaGetSymbolAddress((void**)&ys_lo, g_ys_lo);
    cudaGetSymbolAddress((void**)&wqkv_hi, g_wqkv_hi);
    cudaGetSymbolAddress((void**)&wqkv_lo, g_wqkv_lo);
    cudaGetSymbolAddress((void**)&wproj_hi, g_wproj_hi);
    cudaGetSymbolAddress((void**)&wproj_lo, g_wproj_lo);
    cudaGetSymbolAddress((void**)&qkv, g_qkv);

    cudaFuncSetAttribute(gemm_split,
                         cudaFuncAttributeMaxDynamicSharedMemorySize, GEMM_SMEM);
    cudaFuncSetAttribute(attn_tc,
                         cudaFuncAttributeMaxDynamicSharedMemorySize, ATT_SMEM);

    // 1. weight prep + x split
    transpose_split_all<<<dim3(80, C_ / 32), dim3(32, 8)>>>(Wq, Wk, Wv, Wproj);
    split_fp32<<<(M_ * C_ + 255) / 256, 256>>>(x, xs_hi, xs_lo, M_ * C_);
    // 2. fused QKV projection (all-bf16 cp.async pipeline)
    gemm_split<<<dim3(NQKV_ / 128, M_ / 128), 256, GEMM_SMEM>>>(
        xs_hi, xs_lo, wqkv_hi, wqkv_lo, qkv, NQKV_);
    // 3. gate + RoPE + RMSNorm + bf16 split (V untransposed, coalesced)
    postproc<<<M_, 256>>>(x, ve, cosb, sinb, Wgate);
    // 3b. V layout transpose via smem tiles (both sides coalesced)
    transpose_v<<<dim3(T_ / 32, HD_ / 32, B_ * NKV_), dim3(32, 8)>>>();
    // 4. deep-pipelined tensor-core attention (writes ys hi/lo directly)
    attn_tc<<<dim3(T_ / 128, NH_, B_), 256, ATT_SMEM>>>(win);
    // 5. output projection (all-bf16 cp.async pipeline)
    gemm_split<<<dim3(C_ / 128, M_ / 128), 256, GEMM_SMEM>>>(
        ys_hi, ys_lo, wproj_hi, wproj_lo, out, C_);
}